// round 1
// baseline (speedup 1.0000x reference)
#include <cuda_runtime.h>
#include <math.h>

// Problem constants
#define BATCH 2
#define SEQ   4096
#define DMODEL 512
#define NH    8
#define HD    64
// derived
#define M_ROWS (BATCH*SEQ)          // 8192
#define QKV_ELEMS (BATCH*NH*SEQ*HD) // 4,194,304

// Scratch (device globals; no allocation allowed)
__device__ float g_q[QKV_ELEMS];       // [b][h][s][d]
__device__ float g_k[QKV_ELEMS];       // [b][h][s][d]
__device__ float g_v[QKV_ELEMS];       // [b][h][s][d]
__device__ float g_attnout[QKV_ELEMS]; // [b][s][h*HD+v]  (row-major [8192,512])

// ---------------------------------------------------------------------------
// GEMM: Y = X[M,512] @ W[512,512] + bias, tiles 64x64, BK=32, 256 thr, 4x4 micro
// mode 0: permuted store into [b][h][s][d] layout; mode 1: row-major [M,512]
// ---------------------------------------------------------------------------
__global__ __launch_bounds__(256) void gemm_kernel(
    const float* __restrict__ X, const float* __restrict__ W,
    const float* __restrict__ bias, float* __restrict__ Y, int mode)
{
    __shared__ float As[64][36];  // [m][k], pad->row stride 36 (16B aligned)
    __shared__ float Bs[32][68];  // [k][n], pad 68

    const int tid = threadIdx.x;
    const int tx = tid & 15, ty = tid >> 4;
    const int m0 = blockIdx.x * 64, n0 = blockIdx.y * 64;

    float acc[4][4] = {};

    for (int kt = 0; kt < 512; kt += 32) {
        // load A tile 64x32
        #pragma unroll
        for (int i = 0; i < 2; i++) {
            int idx = tid + i * 256;
            int m = idx >> 3, k8 = idx & 7;
            float4 v = *(const float4*)&X[(size_t)(m0 + m) * 512 + kt + k8 * 4];
            *(float4*)&As[m][k8 * 4] = v;
        }
        // load B tile 32x64
        #pragma unroll
        for (int i = 0; i < 2; i++) {
            int idx = tid + i * 256;
            int k = idx >> 4, n16 = idx & 15;
            float4 v = *(const float4*)&W[(size_t)(kt + k) * 512 + n0 + n16 * 4];
            *(float4*)&Bs[k][n16 * 4] = v;
        }
        __syncthreads();
        #pragma unroll
        for (int k = 0; k < 32; k++) {
            float a[4];
            #pragma unroll
            for (int ii = 0; ii < 4; ii++) a[ii] = As[ty * 4 + ii][k];
            float4 b = *(const float4*)&Bs[k][tx * 4];
            #pragma unroll
            for (int ii = 0; ii < 4; ii++) {
                acc[ii][0] += a[ii] * b.x;
                acc[ii][1] += a[ii] * b.y;
                acc[ii][2] += a[ii] * b.z;
                acc[ii][3] += a[ii] * b.w;
            }
        }
        __syncthreads();
    }

    float4 bi = *(const float4*)&bias[n0 + tx * 4];
    #pragma unroll
    for (int ii = 0; ii < 4; ii++) {
        int mg = m0 + ty * 4 + ii;
        float4 v;
        v.x = acc[ii][0] + bi.x; v.y = acc[ii][1] + bi.y;
        v.z = acc[ii][2] + bi.z; v.w = acc[ii][3] + bi.w;
        if (mode == 0) {
            int b = mg >> 12;            // /SEQ
            int s = mg & (SEQ - 1);
            int h = n0 >> 6;             // whole 64-tile is one head
            *(float4*)&Y[(((size_t)(b * NH + h) * SEQ) + s) * HD + tx * 4] = v;
        } else {
            *(float4*)&Y[(size_t)mg * 512 + n0 + tx * 4] = v;
        }
    }
}

// ---------------------------------------------------------------------------
// Fused attention, flash-style: per (b,h,i-tile of 64 queries), loop all 64
// j-tiles: S = QK^T/8, write raw tile always; for causal tiles do online
// softmax + O += P@V.  256 threads, 4x4 microtiles.
// ---------------------------------------------------------------------------
#define ATTN_SMEM_FLOATS (4*64*68 + 3*64)
#define ATTN_SMEM_BYTES  (ATTN_SMEM_FLOATS * 4)

__global__ __launch_bounds__(256) void attn_kernel(float* __restrict__ rawOut)
{
    extern __shared__ float sm[];
    float* Qs  = sm;               // [64][68]  natural [i][d]
    float* KsT = Qs  + 64 * 68;    // [64][68]  transposed [d][j]
    float* Vs  = KsT + 64 * 68;    // [64][68]  natural [j][v]
    float* Sb  = Vs  + 64 * 68;    // [64][68]  S then P, [i][j]
    float* mrow = Sb + 64 * 68;    // [64]
    float* lrow = mrow + 64;       // [64]
    float* srow = lrow + 64;       // [64]

    const int it = blockIdx.x, h = blockIdx.y, b = blockIdx.z;
    const int tid = threadIdx.x;
    const int tx = tid & 15, ty = tid >> 4;

    const float* Qbase = g_q + ((size_t)(b * NH + h) * SEQ + it * 64) * HD;
    const float* Kb = g_k + (size_t)(b * NH + h) * SEQ * HD;
    const float* Vb = g_v + (size_t)(b * NH + h) * SEQ * HD;
    const size_t rawBase = ((size_t)(h * BATCH + b) * SEQ + (size_t)it * 64) * SEQ;

    // load Q tile
    #pragma unroll
    for (int i = 0; i < 4; i++) {
        int idx = tid + i * 256;
        int r = idx >> 4, c = (idx & 15) * 4;
        float4 v = *(const float4*)&Qbase[r * 64 + c];
        *(float4*)&Qs[r * 68 + c] = v;
    }
    if (tid < 64) { mrow[tid] = -INFINITY; lrow[tid] = 0.f; }

    float O[4][4] = {};
    __syncthreads();

    for (int jt = 0; jt < 64; jt++) {
        const bool causal = (jt <= it);
        // load K (transposed) and V (natural, only if needed)
        #pragma unroll
        for (int i = 0; i < 4; i++) {
            int idx = tid + i * 256;
            int r = idx >> 4, c16 = idx & 15;
            float4 kv = *(const float4*)&Kb[(size_t)(jt * 64 + r) * 64 + c16 * 4];
            KsT[(c16 * 4 + 0) * 68 + r] = kv.x;
            KsT[(c16 * 4 + 1) * 68 + r] = kv.y;
            KsT[(c16 * 4 + 2) * 68 + r] = kv.z;
            KsT[(c16 * 4 + 3) * 68 + r] = kv.w;
            if (causal) {
                float4 vv = *(const float4*)&Vb[(size_t)(jt * 64 + r) * 64 + c16 * 4];
                *(float4*)&Vs[r * 68 + c16 * 4] = vv;
            }
        }
        __syncthreads();

        // S = Q @ K^T
        float acc[4][4] = {};
        #pragma unroll 16
        for (int d = 0; d < 64; d++) {
            float a[4];
            #pragma unroll
            for (int ii = 0; ii < 4; ii++) a[ii] = Qs[(ty * 4 + ii) * 68 + d];
            float4 bf = *(const float4*)&KsT[d * 68 + tx * 4];
            #pragma unroll
            for (int ii = 0; ii < 4; ii++) {
                acc[ii][0] += a[ii] * bf.x;
                acc[ii][1] += a[ii] * bf.y;
                acc[ii][2] += a[ii] * bf.z;
                acc[ii][3] += a[ii] * bf.w;
            }
        }
        // scale, write raw (pre-mask!), stage into smem for softmax
        #pragma unroll
        for (int ii = 0; ii < 4; ii++) {
            float4 v;
            v.x = acc[ii][0] * 0.125f; v.y = acc[ii][1] * 0.125f;
            v.z = acc[ii][2] * 0.125f; v.w = acc[ii][3] * 0.125f;
            *(float4*)&rawOut[rawBase + (size_t)(ty * 4 + ii) * SEQ + jt * 64 + tx * 4] = v;
            if (causal) *(float4*)&Sb[(ty * 4 + ii) * 68 + tx * 4] = v;
        }

        if (causal) {
            __syncthreads();
            if (tid < 64) {
                const int r = tid;
                const int nvalid = (jt < it) ? 64 : (r + 1);
                float mt = -INFINITY;
                for (int j = 0; j < nvalid; j++) mt = fmaxf(mt, Sb[r * 68 + j]);
                const float mo = mrow[r];
                const float mn = fmaxf(mo, mt);
                const float scl = __expf(mo - mn);
                float sum = 0.f;
                for (int j = 0; j < 64; j++) {
                    float p = (j < nvalid) ? __expf(Sb[r * 68 + j] - mn) : 0.f;
                    Sb[r * 68 + j] = p;
                    sum += p;
                }
                lrow[r] = lrow[r] * scl + sum;
                mrow[r] = mn;
                srow[r] = scl;
            }
            __syncthreads();
            float sc[4];
            #pragma unroll
            for (int ii = 0; ii < 4; ii++) sc[ii] = srow[ty * 4 + ii];
            #pragma unroll
            for (int ii = 0; ii < 4; ii++)
                #pragma unroll
                for (int jj = 0; jj < 4; jj++) O[ii][jj] *= sc[ii];
            // O += P @ V
            #pragma unroll 16
            for (int j = 0; j < 64; j++) {
                float a[4];
                #pragma unroll
                for (int ii = 0; ii < 4; ii++) a[ii] = Sb[(ty * 4 + ii) * 68 + j];
                float4 bf = *(const float4*)&Vs[j * 68 + tx * 4];
                #pragma unroll
                for (int ii = 0; ii < 4; ii++) {
                    O[ii][0] += a[ii] * bf.x;
                    O[ii][1] += a[ii] * bf.y;
                    O[ii][2] += a[ii] * bf.z;
                    O[ii][3] += a[ii] * bf.w;
                }
            }
        }
        __syncthreads();
    }

    // normalize and write attention output in [b][s][h*HD+v] layout
    #pragma unroll
    for (int ii = 0; ii < 4; ii++) {
        int r = ty * 4 + ii;
        int ig = it * 64 + r;
        float inv = 1.f / lrow[r];
        float4 v;
        v.x = O[ii][0] * inv; v.y = O[ii][1] * inv;
        v.z = O[ii][2] * inv; v.w = O[ii][3] * inv;
        *(float4*)&g_attnout[((size_t)(b * SEQ + ig) * NH + h) * HD + tx * 4] = v;
    }
}

// ---------------------------------------------------------------------------
// Launch
// inputs: x, Wq, bq, Wk, bk, Wv, bv, Wo, bo
// out: [self_attention (2*4096*512)] ++ [raw (16*4096*4096)]
// ---------------------------------------------------------------------------
extern "C" void kernel_launch(void* const* d_in, const int* in_sizes, int n_in,
                              void* d_out, int out_size)
{
    (void)in_sizes; (void)n_in; (void)out_size;
    const float* x  = (const float*)d_in[0];
    const float* Wq = (const float*)d_in[1];
    const float* bq = (const float*)d_in[2];
    const float* Wk = (const float*)d_in[3];
    const float* bk = (const float*)d_in[4];
    const float* Wv = (const float*)d_in[5];
    const float* bv = (const float*)d_in[6];
    const float* Wo = (const float*)d_in[7];
    const float* bo = (const float*)d_in[8];

    float* out = (float*)d_out;
    float* rawOut = out + (size_t)BATCH * SEQ * DMODEL;

    void *pq, *pk, *pv, *pa;
    cudaGetSymbolAddress(&pq, g_q);
    cudaGetSymbolAddress(&pk, g_k);
    cudaGetSymbolAddress(&pv, g_v);
    cudaGetSymbolAddress(&pa, g_attnout);

    dim3 gg(M_ROWS / 64, 512 / 64, 1);
    dim3 tt(256);
    gemm_kernel<<<gg, tt>>>(x, Wq, bq, (float*)pq, 0);
    gemm_kernel<<<gg, tt>>>(x, Wk, bk, (float*)pk, 0);
    gemm_kernel<<<gg, tt>>>(x, Wv, bv, (float*)pv, 0);

    cudaFuncSetAttribute(attn_kernel, cudaFuncAttributeMaxDynamicSharedMemorySize,
                         ATTN_SMEM_BYTES);
    attn_kernel<<<dim3(SEQ / 64, NH, BATCH), tt, ATTN_SMEM_BYTES>>>(rawOut);

    gemm_kernel<<<gg, tt>>>((const float*)pa, Wo, bo, out, 1);
}

// round 5
// speedup vs baseline: 2.0130x; 2.0130x over previous
#include <cuda_runtime.h>
#include <cuda_bf16.h>
#include <math.h>
#include <stdint.h>

// Problem constants
#define BATCH 2
#define SEQ   4096
#define DMODEL 512
#define NH    8
#define HD    64
#define M_ROWS (BATCH*SEQ)          // 8192
#define QKV_ELEMS (BATCH*NH*SEQ*HD) // 4,194,304

// Scratch (device globals; no allocation allowed)
__device__ float g_q[QKV_ELEMS];       // [b][h][s][d]
__device__ float g_k[QKV_ELEMS];       // [b][h][s][d]
__device__ float g_v[QKV_ELEMS];       // [b][h][s][d]
__device__ float g_attnout[QKV_ELEMS]; // [b][s][h*HD+v]  (row-major [8192,512])

// ===========================================================================
// Helpers: mma.sync (bf16, sm_80+ ISA -> works on plain sm_103 target),
// ldmatrix, packing
// ===========================================================================
__device__ __forceinline__ uint32_t smem_u32(const void* p) {
    uint32_t a;
    asm("{ .reg .u64 t; cvta.to.shared.u64 t, %1; cvt.u32.u64 %0, t; }"
        : "=r"(a) : "l"(p));
    return a;
}

__device__ __forceinline__ void mma_bf16(float4& d, const uint32_t* a,
                                         uint32_t b0, uint32_t b1) {
    asm volatile(
        "mma.sync.aligned.m16n8k16.row.col.f32.bf16.bf16.f32 "
        "{%0,%1,%2,%3}, {%4,%5,%6,%7}, {%8,%9}, {%0,%1,%2,%3};"
        : "+f"(d.x), "+f"(d.y), "+f"(d.z), "+f"(d.w)
        : "r"(a[0]), "r"(a[1]), "r"(a[2]), "r"(a[3]), "r"(b0), "r"(b1));
}

#define LDSM4(R0,R1,R2,R3,A) \
    asm volatile("ldmatrix.sync.aligned.m8n8.x4.shared.b16 {%0,%1,%2,%3}, [%4];" \
                 : "=r"(R0),"=r"(R1),"=r"(R2),"=r"(R3) : "r"(A))
#define LDSM4T(R0,R1,R2,R3,A) \
    asm volatile("ldmatrix.sync.aligned.m8n8.x4.trans.shared.b16 {%0,%1,%2,%3}, [%4];" \
                 : "=r"(R0),"=r"(R1),"=r"(R2),"=r"(R3) : "r"(A))

// pack two f32 -> bf16x2 (lo = first/lower-index element)
__device__ __forceinline__ uint32_t pack_bf16(float lo, float hi) {
    uint32_t d;
    asm("cvt.rn.bf16x2.f32 %0, %1, %2;" : "=r"(d) : "f"(hi), "f"(lo));
    return d;
}
__device__ __forceinline__ float bf_res(float x) {
    __nv_bfloat16 h = __float2bfloat16(x);
    return x - __bfloat162float(h);
}

// swizzled byte offset inside a [rows][64] bf16 tile with 128B row pitch:
// 16B segment index XORed with (row & 7) -> conflict-free ldmatrix
__device__ __forceinline__ uint32_t swz(int r, int c) {
    return (uint32_t)(r * 128 + ((((c >> 3) ^ r) & 7) << 4) + (c & 7) * 2);
}

// ===========================================================================
// SIMT GEMM for projections (proven in R1)
// ===========================================================================
__global__ __launch_bounds__(256) void gemm_kernel(
    const float* __restrict__ X, const float* __restrict__ W,
    const float* __restrict__ bias, float* __restrict__ Y, int mode)
{
    __shared__ float As[64][36];
    __shared__ float Bs[32][68];

    const int tid = threadIdx.x;
    const int tx = tid & 15, ty = tid >> 4;
    const int m0 = blockIdx.x * 64, n0 = blockIdx.y * 64;

    float acc[4][4] = {};

    for (int kt = 0; kt < 512; kt += 32) {
        #pragma unroll
        for (int i = 0; i < 2; i++) {
            int idx = tid + i * 256;
            int m = idx >> 3, k8 = idx & 7;
            float4 v = *(const float4*)&X[(size_t)(m0 + m) * 512 + kt + k8 * 4];
            *(float4*)&As[m][k8 * 4] = v;
        }
        #pragma unroll
        for (int i = 0; i < 2; i++) {
            int idx = tid + i * 256;
            int k = idx >> 4, n16 = idx & 15;
            float4 v = *(const float4*)&W[(size_t)(kt + k) * 512 + n0 + n16 * 4];
            *(float4*)&Bs[k][n16 * 4] = v;
        }
        __syncthreads();
        #pragma unroll
        for (int k = 0; k < 32; k++) {
            float a[4];
            #pragma unroll
            for (int ii = 0; ii < 4; ii++) a[ii] = As[ty * 4 + ii][k];
            float4 b = *(const float4*)&Bs[k][tx * 4];
            #pragma unroll
            for (int ii = 0; ii < 4; ii++) {
                acc[ii][0] += a[ii] * b.x;
                acc[ii][1] += a[ii] * b.y;
                acc[ii][2] += a[ii] * b.z;
                acc[ii][3] += a[ii] * b.w;
            }
        }
        __syncthreads();
    }

    float4 bi = *(const float4*)&bias[n0 + tx * 4];
    #pragma unroll
    for (int ii = 0; ii < 4; ii++) {
        int mg = m0 + ty * 4 + ii;
        float4 v;
        v.x = acc[ii][0] + bi.x; v.y = acc[ii][1] + bi.y;
        v.z = acc[ii][2] + bi.z; v.w = acc[ii][3] + bi.w;
        if (mode == 0) {
            int b = mg >> 12;
            int s = mg & (SEQ - 1);
            int h = n0 >> 6;
            *(float4*)&Y[(((size_t)(b * NH + h) * SEQ) + s) * HD + tx * 4] = v;
        } else {
            *(float4*)&Y[(size_t)mg * 512 + n0 + tx * 4] = v;
        }
    }
}

// ===========================================================================
// mma.sync attention. CTA = (b, h, 128-row q strip), 8 warps, warp = 16 rows.
// Single pass over 64 j-tiles of 64: S (bf16x3 MMA) -> raw STG -> online
// softmax in registers -> O += P@V (bf16x3, ldmatrix.trans B frags).
// ===========================================================================
#define BR 128
#define BC 64

// smem byte offsets ([rows][64] bf16 tiles, 128B pitch, swizzled)
#define SQH 0
#define SQL 16384
#define SKH 32768
#define SKL 40960
#define SVH 49152
#define SVL 57344
#define SM_ATTN 65536

__global__ __launch_bounds__(256, 1) void attn_mma(float* __restrict__ rawOut)
{
    extern __shared__ char smem[];
    const uint32_t sb = smem_u32(smem);
    const int tid = threadIdx.x, w = tid >> 5, L = tid & 31;
    const int t2 = L & 3;
    const int i0 = blockIdx.x * BR, h = blockIdx.y, b = blockIdx.z;

    const float* Qp = g_q + ((size_t)(b * NH + h) * SEQ + i0) * HD;
    const float* Kb = g_k + (size_t)(b * NH + h) * SEQ * HD;
    const float* Vb = g_v + (size_t)(b * NH + h) * SEQ * HD;

    // ---- fill Q smem (scaled by 1/8, split hi/lo) ----
    for (int i = tid; i < 2048; i += 256) {
        int r = i >> 4, c = (i & 15) * 4;
        float4 v = *(const float4*)&Qp[(size_t)r * HD + c];
        v.x *= 0.125f; v.y *= 0.125f; v.z *= 0.125f; v.w *= 0.125f;
        uint32_t off = swz(r, c);
        *(uint2*)(smem + SQH + off) = make_uint2(pack_bf16(v.x, v.y), pack_bf16(v.z, v.w));
        *(uint2*)(smem + SQL + off) = make_uint2(pack_bf16(bf_res(v.x), bf_res(v.y)),
                                                 pack_bf16(bf_res(v.z), bf_res(v.w)));
    }

    const int i_row0 = i0 + w * 16 + (L >> 2);   // row g
    const int i_row1 = i_row0 + 8;               // row g+8
    const int iwmax = i0 + w * 16 + 15;
    const size_t raw0 = ((size_t)(h * BATCH + b) * SEQ + i_row0) * SEQ;
    const size_t raw1 = raw0 + 8ull * SEQ;
    const int lastCausal = 2 * blockIdx.x + 1;   // jt <= this may need V/softmax

    float4 O[8];
    #pragma unroll
    for (int nt = 0; nt < 8; nt++) O[nt] = make_float4(0.f, 0.f, 0.f, 0.f);
    float m0 = -INFINITY, m1 = -INFINITY, l0 = 0.f, l1 = 0.f;

    // prefetch registers for K/V fp32 tiles (64x64 each)
    float4 kreg[4], vreg[4];
    {
        #pragma unroll
        for (int q = 0; q < 4; q++) {
            int i = tid + q * 256;
            int r = i >> 4, c = (i & 15) * 4;
            kreg[q] = *(const float4*)&Kb[(size_t)r * HD + c];
            vreg[q] = *(const float4*)&Vb[(size_t)r * HD + c];
        }
    }

    for (int jt = 0; jt < 64; jt++) {
        const bool tileCausal = (jt <= lastCausal);
        __syncthreads();   // previous tile's readers done
        // store prefetched K (and V if needed), split hi/lo
        #pragma unroll
        for (int q = 0; q < 4; q++) {
            int i = tid + q * 256;
            int r = i >> 4, c = (i & 15) * 4;
            uint32_t off = swz(r, c);
            float4 kv = kreg[q];
            *(uint2*)(smem + SKH + off) = make_uint2(pack_bf16(kv.x, kv.y), pack_bf16(kv.z, kv.w));
            *(uint2*)(smem + SKL + off) = make_uint2(pack_bf16(bf_res(kv.x), bf_res(kv.y)),
                                                     pack_bf16(bf_res(kv.z), bf_res(kv.w)));
            if (tileCausal) {
                float4 vv = vreg[q];
                *(uint2*)(smem + SVH + off) = make_uint2(pack_bf16(vv.x, vv.y), pack_bf16(vv.z, vv.w));
                *(uint2*)(smem + SVL + off) = make_uint2(pack_bf16(bf_res(vv.x), bf_res(vv.y)),
                                                         pack_bf16(bf_res(vv.z), bf_res(vv.w)));
            }
        }
        __syncthreads();
        // prefetch next tile
        if (jt < 63) {
            const float* Kt = Kb + (size_t)(jt + 1) * BC * HD;
            const float* Vt = Vb + (size_t)(jt + 1) * BC * HD;
            const bool nextCausal = (jt + 1 <= lastCausal);
            #pragma unroll
            for (int q = 0; q < 4; q++) {
                int i = tid + q * 256;
                int r = i >> 4, c = (i & 15) * 4;
                kreg[q] = *(const float4*)&Kt[(size_t)r * HD + c];
                if (nextCausal) vreg[q] = *(const float4*)&Vt[(size_t)r * HD + c];
            }
        }

        // ---- S = Q @ K^T (bf16x3) ----
        float4 acc[8];
        #pragma unroll
        for (int nt = 0; nt < 8; nt++) acc[nt] = make_float4(0.f, 0.f, 0.f, 0.f);

        #pragma unroll
        for (int kt = 0; kt < 4; kt++) {
            // Q A-frags: row = w*16 + (L&7) + 8*((L>>3)&1), col = kt*16 + 8*((L>>4)&1)
            int qr = w * 16 + (L & 7) + 8 * ((L >> 3) & 1);
            int qc = kt * 16 + 8 * ((L >> 4) & 1);
            uint32_t qh[4], ql[4];
            LDSM4(qh[0], qh[1], qh[2], qh[3], sb + SQH + swz(qr, qc));
            LDSM4(ql[0], ql[1], ql[2], ql[3], sb + SQL + swz(qr, qc));
            // K B-frags: row = 16p + (L&7) + 8*((L>>4)&1), col = kt*16 + 8*((L>>3)&1)
            int krr = (L & 7) + 8 * ((L >> 4) & 1);
            int kcc = kt * 16 + 8 * ((L >> 3) & 1);
            #pragma unroll
            for (int p = 0; p < 4; p++) {
                uint32_t bh0, bh1, bh2, bh3, bl0, bl1, bl2, bl3;
                LDSM4(bh0, bh1, bh2, bh3, sb + SKH + swz(16 * p + krr, kcc));
                LDSM4(bl0, bl1, bl2, bl3, sb + SKL + swz(16 * p + krr, kcc));
                mma_bf16(acc[2 * p],     qh, bh0, bh1);
                mma_bf16(acc[2 * p + 1], qh, bh2, bh3);
                mma_bf16(acc[2 * p],     ql, bh0, bh1);
                mma_bf16(acc[2 * p + 1], ql, bh2, bh3);
                mma_bf16(acc[2 * p],     qh, bl0, bl1);
                mma_bf16(acc[2 * p + 1], qh, bl2, bl3);
            }
        }

        // ---- raw scores (pre-mask) ----
        #pragma unroll
        for (int nt = 0; nt < 8; nt++) {
            int j = jt * 64 + nt * 8 + t2 * 2;
            *(float2*)&rawOut[raw0 + j] = make_float2(acc[nt].x, acc[nt].y);
            *(float2*)&rawOut[raw1 + j] = make_float2(acc[nt].z, acc[nt].w);
        }

        // ---- softmax + PV on causal tiles (warp-uniform condition) ----
        if (jt * 64 <= iwmax) {
            const bool full = (jt * 64 + 63 <= i0 + w * 16);
            float mt0 = -INFINITY, mt1 = -INFINITY;
            #pragma unroll
            for (int nt = 0; nt < 8; nt++) {
                int j = jt * 64 + nt * 8 + t2 * 2;
                float ax = (full || j     <= i_row0) ? acc[nt].x : -INFINITY;
                float ay = (full || j + 1 <= i_row0) ? acc[nt].y : -INFINITY;
                float az = (full || j     <= i_row1) ? acc[nt].z : -INFINITY;
                float aw = (full || j + 1 <= i_row1) ? acc[nt].w : -INFINITY;
                mt0 = fmaxf(mt0, fmaxf(ax, ay));
                mt1 = fmaxf(mt1, fmaxf(az, aw));
            }
            mt0 = fmaxf(mt0, __shfl_xor_sync(0xffffffffu, mt0, 1));
            mt0 = fmaxf(mt0, __shfl_xor_sync(0xffffffffu, mt0, 2));
            mt1 = fmaxf(mt1, __shfl_xor_sync(0xffffffffu, mt1, 1));
            mt1 = fmaxf(mt1, __shfl_xor_sync(0xffffffffu, mt1, 2));

            float mn0 = fmaxf(m0, mt0), mn1 = fmaxf(m1, mt1);
            float sc0 = __expf(m0 - mn0), sc1 = __expf(m1 - mn1);

            float s0 = 0.f, s1 = 0.f;
            uint32_t ph[16], pl[16];
            #pragma unroll
            for (int nt = 0; nt < 8; nt++) {
                int j = jt * 64 + nt * 8 + t2 * 2;
                float px = (full || j     <= i_row0) ? __expf(acc[nt].x - mn0) : 0.f;
                float py = (full || j + 1 <= i_row0) ? __expf(acc[nt].y - mn0) : 0.f;
                float pz = (full || j     <= i_row1) ? __expf(acc[nt].z - mn1) : 0.f;
                float pw = (full || j + 1 <= i_row1) ? __expf(acc[nt].w - mn1) : 0.f;
                s0 += px + py; s1 += pz + pw;
                ph[2 * nt]     = pack_bf16(px, py);
                ph[2 * nt + 1] = pack_bf16(pz, pw);
                pl[2 * nt]     = pack_bf16(bf_res(px), bf_res(py));
                pl[2 * nt + 1] = pack_bf16(bf_res(pz), bf_res(pw));
            }
            s0 += __shfl_xor_sync(0xffffffffu, s0, 1);
            s0 += __shfl_xor_sync(0xffffffffu, s0, 2);
            s1 += __shfl_xor_sync(0xffffffffu, s1, 1);
            s1 += __shfl_xor_sync(0xffffffffu, s1, 2);
            l0 = l0 * sc0 + s0;  l1 = l1 * sc1 + s1;
            m0 = mn0;  m1 = mn1;

            #pragma unroll
            for (int nt = 0; nt < 8; nt++) {
                O[nt].x *= sc0; O[nt].y *= sc0;
                O[nt].z *= sc1; O[nt].w *= sc1;
            }

            // O += P @ V
            int vrr = (L & 7) + 8 * ((L >> 3) & 1);
            int vcb = 8 * ((L >> 4) & 1);
            #pragma unroll
            for (int ktj = 0; ktj < 4; ktj++) {
                const uint32_t* ah = &ph[4 * ktj];
                const uint32_t* al = &pl[4 * ktj];
                #pragma unroll
                for (int vp = 0; vp < 4; vp++) {
                    uint32_t bh0, bh1, bh2, bh3, bl0, bl1, bl2, bl3;
                    LDSM4T(bh0, bh1, bh2, bh3,
                           sb + SVH + swz(ktj * 16 + vrr, vp * 16 + vcb));
                    LDSM4T(bl0, bl1, bl2, bl3,
                           sb + SVL + swz(ktj * 16 + vrr, vp * 16 + vcb));
                    mma_bf16(O[2 * vp],     ah, bh0, bh1);
                    mma_bf16(O[2 * vp + 1], ah, bh2, bh3);
                    mma_bf16(O[2 * vp],     al, bh0, bh1);
                    mma_bf16(O[2 * vp + 1], al, bh2, bh3);
                    mma_bf16(O[2 * vp],     ah, bl0, bl1);
                    mma_bf16(O[2 * vp + 1], ah, bl2, bl3);
                }
            }
        }
    }

    // ---- epilogue ----
    const float inv0 = 1.f / l0, inv1 = 1.f / l1;
    float* o0 = &g_attnout[((size_t)(b * SEQ + i_row0) * NH + h) * HD];
    float* o1 = &g_attnout[((size_t)(b * SEQ + i_row1) * NH + h) * HD];
    #pragma unroll
    for (int nt = 0; nt < 8; nt++) {
        int v = nt * 8 + t2 * 2;
        *(float2*)&o0[v] = make_float2(O[nt].x * inv0, O[nt].y * inv0);
        *(float2*)&o1[v] = make_float2(O[nt].z * inv1, O[nt].w * inv1);
    }
}

// ===========================================================================
// Launch
// ===========================================================================
extern "C" void kernel_launch(void* const* d_in, const int* in_sizes, int n_in,
                              void* d_out, int out_size)
{
    (void)in_sizes; (void)n_in; (void)out_size;
    const float* x  = (const float*)d_in[0];
    const float* Wq = (const float*)d_in[1];
    const float* bq = (const float*)d_in[2];
    const float* Wk = (const float*)d_in[3];
    const float* bk = (const float*)d_in[4];
    const float* Wv = (const float*)d_in[5];
    const float* bv = (const float*)d_in[6];
    const float* Wo = (const float*)d_in[7];
    const float* bo = (const float*)d_in[8];

    float* out = (float*)d_out;
    float* rawOut = out + (size_t)BATCH * SEQ * DMODEL;

    void *pq, *pk, *pv, *pa;
    cudaGetSymbolAddress(&pq, g_q);
    cudaGetSymbolAddress(&pk, g_k);
    cudaGetSymbolAddress(&pv, g_v);
    cudaGetSymbolAddress(&pa, g_attnout);

    dim3 gg(M_ROWS / 64, 512 / 64, 1);
    dim3 tt(256);
    gemm_kernel<<<gg, tt>>>(x, Wq, bq, (float*)pq, 0);
    gemm_kernel<<<gg, tt>>>(x, Wk, bk, (float*)pk, 0);
    gemm_kernel<<<gg, tt>>>(x, Wv, bv, (float*)pv, 0);

    cudaFuncSetAttribute(attn_mma, cudaFuncAttributeMaxDynamicSharedMemorySize,
                         SM_ATTN);
    attn_mma<<<dim3(SEQ / BR, NH, BATCH), 256, SM_ATTN>>>(rawOut);

    gemm_kernel<<<gg, tt>>>((const float*)pa, Wo, bo, out, 1);
}

// round 6
// speedup vs baseline: 2.7438x; 1.3630x over previous
#include <cuda_runtime.h>
#include <cuda_bf16.h>
#include <math.h>
#include <stdint.h>

// Problem constants
#define BATCH 2
#define SEQ   4096
#define DMODEL 512
#define NH    8
#define HD    64
#define M_ROWS (BATCH*SEQ)          // 8192
#define QKV_ELEMS (BATCH*NH*SEQ*HD) // 4,194,304 (== M_ROWS*DMODEL)
#define WELEMS (DMODEL*DMODEL)      // 262,144

// Scratch (device globals; no allocation allowed)
__device__ __nv_bfloat16 g_qkvh[3 * QKV_ELEMS]; // mat-major: Q,K,V [b][h][s][d]
__device__ __nv_bfloat16 g_qkvl[3 * QKV_ELEMS];
__device__ __nv_bfloat16 g_xh[QKV_ELEMS];       // x split  [8192][512]
__device__ __nv_bfloat16 g_xl[QKV_ELEMS];
__device__ __nv_bfloat16 g_wh[4 * WELEMS];      // Wq,Wk,Wv,Wo split [k][n]
__device__ __nv_bfloat16 g_wl[4 * WELEMS];
__device__ __nv_bfloat16 g_ah[QKV_ELEMS];       // attn out split [8192][512]
__device__ __nv_bfloat16 g_al[QKV_ELEMS];

// ===========================================================================
// Helpers
// ===========================================================================
__device__ __forceinline__ uint32_t smem_u32(const void* p) {
    uint32_t a;
    asm("{ .reg .u64 t; cvta.to.shared.u64 t, %1; cvt.u32.u64 %0, t; }"
        : "=r"(a) : "l"(p));
    return a;
}

__device__ __forceinline__ void mma_bf16(float4& d, const uint32_t* a,
                                         uint32_t b0, uint32_t b1) {
    asm volatile(
        "mma.sync.aligned.m16n8k16.row.col.f32.bf16.bf16.f32 "
        "{%0,%1,%2,%3}, {%4,%5,%6,%7}, {%8,%9}, {%0,%1,%2,%3};"
        : "+f"(d.x), "+f"(d.y), "+f"(d.z), "+f"(d.w)
        : "r"(a[0]), "r"(a[1]), "r"(a[2]), "r"(a[3]), "r"(b0), "r"(b1));
}

#define LDSM4(R0,R1,R2,R3,A) \
    asm volatile("ldmatrix.sync.aligned.m8n8.x4.shared.b16 {%0,%1,%2,%3}, [%4];" \
                 : "=r"(R0),"=r"(R1),"=r"(R2),"=r"(R3) : "r"(A))
#define LDSM4T(R0,R1,R2,R3,A) \
    asm volatile("ldmatrix.sync.aligned.m8n8.x4.trans.shared.b16 {%0,%1,%2,%3}, [%4];" \
                 : "=r"(R0),"=r"(R1),"=r"(R2),"=r"(R3) : "r"(A))

// pack two f32 -> bf16x2 (low half = first arg)
__device__ __forceinline__ uint32_t pack_bf16(float lo, float hi) {
    uint32_t d;
    asm("cvt.rn.bf16x2.f32 %0, %1, %2;" : "=r"(d) : "f"(hi), "f"(lo));
    return d;
}
__device__ __forceinline__ float bf_res(float x) {
    __nv_bfloat16 h = __float2bfloat16(x);
    return x - __bfloat162float(h);
}

// swizzled byte offset, [rows][64] bf16 tile, 128B pitch
__device__ __forceinline__ uint32_t swz(int r, int c) {
    return (uint32_t)(r * 128 + ((((c >> 3) ^ r) & 7) << 4) + (c & 7) * 2);
}
// swizzled byte offset, [rows][128] bf16 tile, 256B pitch (XOR low 3 seg bits)
__device__ __forceinline__ uint32_t swz256(int r, int c) {
    uint32_t seg = (uint32_t)(c >> 3);
    seg = (seg & 8u) | ((seg ^ (uint32_t)(r & 7)) & 7u);
    return (uint32_t)(r * 256) + seg * 16 + (uint32_t)((c & 7) * 2);
}

// ===========================================================================
// split: fp32 -> bf16 hi/lo
// ===========================================================================
__global__ void split_kernel(const float* __restrict__ s,
                             __nv_bfloat16* __restrict__ dh,
                             __nv_bfloat16* __restrict__ dl, int n4)
{
    int i = blockIdx.x * blockDim.x + threadIdx.x;
    if (i >= n4) return;
    float4 v = ((const float4*)s)[i];
    ((uint2*)dh)[i] = make_uint2(pack_bf16(v.x, v.y), pack_bf16(v.z, v.w));
    ((uint2*)dl)[i] = make_uint2(pack_bf16(bf_res(v.x), bf_res(v.y)),
                                 pack_bf16(bf_res(v.z), bf_res(v.w)));
}

// ===========================================================================
// bf16x3 tensor GEMM: C[8192 x 512] = A * W + bias
// A: bf16 hi/lo [8192][512]; W: bf16 hi/lo [512][512] (k-major)
// mode 0: per-mat (blockIdx.z) permuted split-bf16 store into g_qkvh/l
// mode 1: fp32 row-major store
// ===========================================================================
#define GA_H 0
#define GA_L 16384
#define GB_H 32768
#define GB_L 49152
#define GSM  65536

__global__ __launch_bounds__(256) void gemm_bf16(
    const __nv_bfloat16* __restrict__ Ah, const __nv_bfloat16* __restrict__ Al,
    const __nv_bfloat16* __restrict__ Wh, const __nv_bfloat16* __restrict__ Wl,
    const float* __restrict__ bias0, const float* __restrict__ bias1,
    const float* __restrict__ bias2,
    __nv_bfloat16* __restrict__ Oh, __nv_bfloat16* __restrict__ Ol,
    float* __restrict__ Ofp, int mode)
{
    extern __shared__ char smem[];
    const uint32_t sb = smem_u32(smem);
    const int tid = threadIdx.x, w = tid >> 5, L = tid & 31;
    const int t2 = L & 3;
    const int bm = blockIdx.x, bn = blockIdx.y, mat = blockIdx.z;
    const float* bias = (mat == 0) ? bias0 : (mat == 1) ? bias1 : bias2;
    const __nv_bfloat16* Whm = Wh + (size_t)mat * WELEMS;
    const __nv_bfloat16* Wlm = Wl + (size_t)mat * WELEMS;

    const int wm = (w >> 2) * 64, wn = (w & 3) * 32;
    float4 acc[4][4] = {};

    for (int k0 = 0; k0 < 512; k0 += 64) {
        __syncthreads();
        // A tile 128x64 (hi+lo)
        #pragma unroll
        for (int q = 0; q < 4; q++) {
            int i = tid + q * 256;
            int r = i >> 3, c = (i & 7) * 8;
            uint32_t off = swz(r, c);
            *(uint4*)(smem + GA_H + off) =
                *(const uint4*)&Ah[(size_t)(bm * 128 + r) * 512 + k0 + c];
            *(uint4*)(smem + GA_L + off) =
                *(const uint4*)&Al[(size_t)(bm * 128 + r) * 512 + k0 + c];
        }
        // B tile 64x128 (hi+lo), [k][n]
        #pragma unroll
        for (int q = 0; q < 4; q++) {
            int i = tid + q * 256;
            int r = i >> 4, c = (i & 15) * 8;
            uint32_t off = swz256(r, c);
            *(uint4*)(smem + GB_H + off) =
                *(const uint4*)&Whm[(size_t)(k0 + r) * 512 + bn * 128 + c];
            *(uint4*)(smem + GB_L + off) =
                *(const uint4*)&Wlm[(size_t)(k0 + r) * 512 + bn * 128 + c];
        }
        __syncthreads();

        #pragma unroll
        for (int kt = 0; kt < 4; kt++) {
            uint32_t ah[4][4], al[4][4], bh[2][4], bl[2][4];
            int ar = (L & 7) + 8 * ((L >> 3) & 1);
            int ac = kt * 16 + 8 * ((L >> 4) & 1);
            #pragma unroll
            for (int mi = 0; mi < 4; mi++) {
                LDSM4(ah[mi][0], ah[mi][1], ah[mi][2], ah[mi][3],
                      sb + GA_H + swz(wm + mi * 16 + ar, ac));
                LDSM4(al[mi][0], al[mi][1], al[mi][2], al[mi][3],
                      sb + GA_L + swz(wm + mi * 16 + ar, ac));
            }
            int br = kt * 16 + (L & 7) + 8 * ((L >> 3) & 1);
            int bc = 8 * ((L >> 4) & 1);
            #pragma unroll
            for (int nj = 0; nj < 2; nj++) {
                LDSM4T(bh[nj][0], bh[nj][1], bh[nj][2], bh[nj][3],
                       sb + GB_H + swz256(br, wn + nj * 16 + bc));
                LDSM4T(bl[nj][0], bl[nj][1], bl[nj][2], bl[nj][3],
                       sb + GB_L + swz256(br, wn + nj * 16 + bc));
            }
            // term-major: hh, lh, hl (acc reuse spacing = 16)
            #pragma unroll
            for (int mi = 0; mi < 4; mi++)
                #pragma unroll
                for (int nj = 0; nj < 2; nj++) {
                    mma_bf16(acc[mi][2 * nj],     ah[mi], bh[nj][0], bh[nj][1]);
                    mma_bf16(acc[mi][2 * nj + 1], ah[mi], bh[nj][2], bh[nj][3]);
                }
            #pragma unroll
            for (int mi = 0; mi < 4; mi++)
                #pragma unroll
                for (int nj = 0; nj < 2; nj++) {
                    mma_bf16(acc[mi][2 * nj],     al[mi], bh[nj][0], bh[nj][1]);
                    mma_bf16(acc[mi][2 * nj + 1], al[mi], bh[nj][2], bh[nj][3]);
                }
            #pragma unroll
            for (int mi = 0; mi < 4; mi++)
                #pragma unroll
                for (int nj = 0; nj < 2; nj++) {
                    mma_bf16(acc[mi][2 * nj],     ah[mi], bl[nj][0], bl[nj][1]);
                    mma_bf16(acc[mi][2 * nj + 1], ah[mi], bl[nj][2], bl[nj][3]);
                }
        }
    }

    // epilogue
    const float scl = (mode == 0 && mat == 0) ? 0.125f : 1.f;
    #pragma unroll
    for (int mi = 0; mi < 4; mi++) {
        #pragma unroll
        for (int nq = 0; nq < 4; nq++) {
            int r0 = bm * 128 + wm + mi * 16 + (L >> 2);
            int r1 = r0 + 8;
            int n = bn * 128 + wn + nq * 8 + t2 * 2;
            float bx = bias[n], by = bias[n + 1];
            float4 c = acc[mi][nq];
            float cx = (c.x + bx) * scl, cy = (c.y + by) * scl;
            float cz = (c.z + bx) * scl, cw = (c.w + by) * scl;
            if (mode == 0) {
                int hh = n >> 6, d = n & 63;
                int b0 = r0 >> 12, s0 = r0 & (SEQ - 1);
                int b1 = r1 >> 12, s1 = r1 & (SEQ - 1);
                size_t i0 = (size_t)mat * QKV_ELEMS +
                            (((size_t)(b0 * NH + hh)) * SEQ + s0) * HD + d;
                size_t i1 = (size_t)mat * QKV_ELEMS +
                            (((size_t)(b1 * NH + hh)) * SEQ + s1) * HD + d;
                *(uint32_t*)&Oh[i0] = pack_bf16(cx, cy);
                *(uint32_t*)&Ol[i0] = pack_bf16(bf_res(cx), bf_res(cy));
                *(uint32_t*)&Oh[i1] = pack_bf16(cz, cw);
                *(uint32_t*)&Ol[i1] = pack_bf16(bf_res(cz), bf_res(cw));
            } else {
                *(float2*)&Ofp[(size_t)r0 * 512 + n] = make_float2(cx, cy);
                *(float2*)&Ofp[(size_t)r1 * 512 + n] = make_float2(cz, cw);
            }
        }
    }
}

// ===========================================================================
// mma.sync attention; inputs are pre-split bf16 (Q pre-scaled by 1/8).
// CTA = (b, h, 128-row q strip), 8 warps x 16 rows, 64 j-tiles of 64.
// ===========================================================================
#define BR 128
#define BC 64

#define SQH 0
#define SQL 16384
#define SKH 32768
#define SKL 40960
#define SVH 49152
#define SVL 57344
#define SM_ATTN 65536

__global__ __launch_bounds__(256, 1) void attn_mma(float* __restrict__ rawOut)
{
    extern __shared__ char smem[];
    const uint32_t sb = smem_u32(smem);
    const int tid = threadIdx.x, w = tid >> 5, L = tid & 31;
    const int t2 = L & 3;
    const int it = (int)(gridDim.x - 1 - blockIdx.x);   // heavy blocks first
    const int i0 = it * BR, h = blockIdx.y, b = blockIdx.z;

    const size_t headOff = (size_t)(b * NH + h) * SEQ * HD;
    const __nv_bfloat16* Qh = g_qkvh + headOff + (size_t)i0 * HD;
    const __nv_bfloat16* Ql = g_qkvl + headOff + (size_t)i0 * HD;
    const __nv_bfloat16* Kh = g_qkvh + QKV_ELEMS + headOff;
    const __nv_bfloat16* Kl = g_qkvl + QKV_ELEMS + headOff;
    const __nv_bfloat16* Vh = g_qkvh + 2 * QKV_ELEMS + headOff;
    const __nv_bfloat16* Vl = g_qkvl + 2 * QKV_ELEMS + headOff;

    // ---- fill Q smem (pure copy) ----
    for (int i = tid; i < 1024; i += 256) {
        int r = i >> 3, c = (i & 7) * 8;
        uint32_t off = swz(r, c);
        *(uint4*)(smem + SQH + off) = *(const uint4*)&Qh[(size_t)r * HD + c];
        *(uint4*)(smem + SQL + off) = *(const uint4*)&Ql[(size_t)r * HD + c];
    }

    const int i_row0 = i0 + w * 16 + (L >> 2);
    const int i_row1 = i_row0 + 8;
    const int iwmax = i0 + w * 16 + 15;
    const size_t raw0 = ((size_t)(h * BATCH + b) * SEQ + i_row0) * SEQ;
    const size_t raw1 = raw0 + 8ull * SEQ;
    const int lastCausal = 2 * it + 1;

    float4 O[8];
    #pragma unroll
    for (int nt = 0; nt < 8; nt++) O[nt] = make_float4(0.f, 0.f, 0.f, 0.f);
    float m0 = -INFINITY, m1 = -INFINITY, l0 = 0.f, l1 = 0.f;

    uint4 kh2[2], kl2[2], vh2[2], vl2[2];
    #pragma unroll
    for (int q = 0; q < 2; q++) {
        int i = tid + q * 256;
        int r = i >> 3, c = (i & 7) * 8;
        kh2[q] = *(const uint4*)&Kh[(size_t)r * HD + c];
        kl2[q] = *(const uint4*)&Kl[(size_t)r * HD + c];
        vh2[q] = *(const uint4*)&Vh[(size_t)r * HD + c];
        vl2[q] = *(const uint4*)&Vl[(size_t)r * HD + c];
    }

    for (int jt = 0; jt < 64; jt++) {
        const bool tileCausal = (jt <= lastCausal);
        __syncthreads();
        #pragma unroll
        for (int q = 0; q < 2; q++) {
            int i = tid + q * 256;
            int r = i >> 3, c = (i & 7) * 8;
            uint32_t off = swz(r, c);
            *(uint4*)(smem + SKH + off) = kh2[q];
            *(uint4*)(smem + SKL + off) = kl2[q];
            if (tileCausal) {
                *(uint4*)(smem + SVH + off) = vh2[q];
                *(uint4*)(smem + SVL + off) = vl2[q];
            }
        }
        __syncthreads();
        if (jt < 63) {
            const __nv_bfloat16* Kht = Kh + (size_t)(jt + 1) * BC * HD;
            const __nv_bfloat16* Klt = Kl + (size_t)(jt + 1) * BC * HD;
            const __nv_bfloat16* Vht = Vh + (size_t)(jt + 1) * BC * HD;
            const __nv_bfloat16* Vlt = Vl + (size_t)(jt + 1) * BC * HD;
            const bool nextCausal = (jt + 1 <= lastCausal);
            #pragma unroll
            for (int q = 0; q < 2; q++) {
                int i = tid + q * 256;
                int r = i >> 3, c = (i & 7) * 8;
                kh2[q] = *(const uint4*)&Kht[(size_t)r * HD + c];
                kl2[q] = *(const uint4*)&Klt[(size_t)r * HD + c];
                if (nextCausal) {
                    vh2[q] = *(const uint4*)&Vht[(size_t)r * HD + c];
                    vl2[q] = *(const uint4*)&Vlt[(size_t)r * HD + c];
                }
            }
        }

        // ---- S = Q @ K^T (bf16x3, term-major ILP) ----
        float4 acc[8];
        #pragma unroll
        for (int nt = 0; nt < 8; nt++) acc[nt] = make_float4(0.f, 0.f, 0.f, 0.f);

        #pragma unroll
        for (int kt = 0; kt < 4; kt++) {
            int qr = w * 16 + (L & 7) + 8 * ((L >> 3) & 1);
            int qc = kt * 16 + 8 * ((L >> 4) & 1);
            uint32_t qh[4], ql[4];
            LDSM4(qh[0], qh[1], qh[2], qh[3], sb + SQH + swz(qr, qc));
            LDSM4(ql[0], ql[1], ql[2], ql[3], sb + SQL + swz(qr, qc));
            int krr = (L & 7) + 8 * ((L >> 4) & 1);
            int kcc = kt * 16 + 8 * ((L >> 3) & 1);
            uint32_t bh[4][4], bl[4][4];
            #pragma unroll
            for (int p = 0; p < 4; p++) {
                LDSM4(bh[p][0], bh[p][1], bh[p][2], bh[p][3],
                      sb + SKH + swz(16 * p + krr, kcc));
                LDSM4(bl[p][0], bl[p][1], bl[p][2], bl[p][3],
                      sb + SKL + swz(16 * p + krr, kcc));
            }
            #pragma unroll
            for (int p = 0; p < 4; p++) {
                mma_bf16(acc[2 * p],     qh, bh[p][0], bh[p][1]);
                mma_bf16(acc[2 * p + 1], qh, bh[p][2], bh[p][3]);
            }
            #pragma unroll
            for (int p = 0; p < 4; p++) {
                mma_bf16(acc[2 * p],     ql, bh[p][0], bh[p][1]);
                mma_bf16(acc[2 * p + 1], ql, bh[p][2], bh[p][3]);
            }
            #pragma unroll
            for (int p = 0; p < 4; p++) {
                mma_bf16(acc[2 * p],     qh, bl[p][0], bl[p][1]);
                mma_bf16(acc[2 * p + 1], qh, bl[p][2], bl[p][3]);
            }
        }

        // ---- raw scores (pre-mask) ----
        #pragma unroll
        for (int nt = 0; nt < 8; nt++) {
            int j = jt * 64 + nt * 8 + t2 * 2;
            *(float2*)&rawOut[raw0 + j] = make_float2(acc[nt].x, acc[nt].y);
            *(float2*)&rawOut[raw1 + j] = make_float2(acc[nt].z, acc[nt].w);
        }

        // ---- softmax + PV (warp-uniform) ----
        if (jt * 64 <= iwmax) {
            const bool full = (jt * 64 + 63 <= i0 + w * 16);
            float mt0 = -INFINITY, mt1 = -INFINITY;
            #pragma unroll
            for (int nt = 0; nt < 8; nt++) {
                int j = jt * 64 + nt * 8 + t2 * 2;
                float ax = (full || j     <= i_row0) ? acc[nt].x : -INFINITY;
                float ay = (full || j + 1 <= i_row0) ? acc[nt].y : -INFINITY;
                float az = (full || j     <= i_row1) ? acc[nt].z : -INFINITY;
                float aw = (full || j + 1 <= i_row1) ? acc[nt].w : -INFINITY;
                mt0 = fmaxf(mt0, fmaxf(ax, ay));
                mt1 = fmaxf(mt1, fmaxf(az, aw));
            }
            mt0 = fmaxf(mt0, __shfl_xor_sync(0xffffffffu, mt0, 1));
            mt0 = fmaxf(mt0, __shfl_xor_sync(0xffffffffu, mt0, 2));
            mt1 = fmaxf(mt1, __shfl_xor_sync(0xffffffffu, mt1, 1));
            mt1 = fmaxf(mt1, __shfl_xor_sync(0xffffffffu, mt1, 2));

            float mn0 = fmaxf(m0, mt0), mn1 = fmaxf(m1, mt1);
            float sc0 = __expf(m0 - mn0), sc1 = __expf(m1 - mn1);

            float s0 = 0.f, s1 = 0.f;
            uint32_t ph[16], pl[16];
            #pragma unroll
            for (int nt = 0; nt < 8; nt++) {
                int j = jt * 64 + nt * 8 + t2 * 2;
                float px = (full || j     <= i_row0) ? __expf(acc[nt].x - mn0) : 0.f;
                float py = (full || j + 1 <= i_row0) ? __expf(acc[nt].y - mn0) : 0.f;
                float pz = (full || j     <= i_row1) ? __expf(acc[nt].z - mn1) : 0.f;
                float pw = (full || j + 1 <= i_row1) ? __expf(acc[nt].w - mn1) : 0.f;
                s0 += px + py; s1 += pz + pw;
                ph[2 * nt]     = pack_bf16(px, py);
                ph[2 * nt + 1] = pack_bf16(pz, pw);
                pl[2 * nt]     = pack_bf16(bf_res(px), bf_res(py));
                pl[2 * nt + 1] = pack_bf16(bf_res(pz), bf_res(pw));
            }
            s0 += __shfl_xor_sync(0xffffffffu, s0, 1);
            s0 += __shfl_xor_sync(0xffffffffu, s0, 2);
            s1 += __shfl_xor_sync(0xffffffffu, s1, 1);
            s1 += __shfl_xor_sync(0xffffffffu, s1, 2);
            l0 = l0 * sc0 + s0;  l1 = l1 * sc1 + s1;
            m0 = mn0;  m1 = mn1;

            #pragma unroll
            for (int nt = 0; nt < 8; nt++) {
                O[nt].x *= sc0; O[nt].y *= sc0;
                O[nt].z *= sc1; O[nt].w *= sc1;
            }

            // O += P @ V, term-major
            int vrr = (L & 7) + 8 * ((L >> 3) & 1);
            int vcb = 8 * ((L >> 4) & 1);
            #pragma unroll
            for (int ktj = 0; ktj < 4; ktj++) {
                const uint32_t* ahh = &ph[4 * ktj];
                const uint32_t* all = &pl[4 * ktj];
                uint32_t bh[4][4], bl[4][4];
                #pragma unroll
                for (int vp = 0; vp < 4; vp++) {
                    LDSM4T(bh[vp][0], bh[vp][1], bh[vp][2], bh[vp][3],
                           sb + SVH + swz(ktj * 16 + vrr, vp * 16 + vcb));
                    LDSM4T(bl[vp][0], bl[vp][1], bl[vp][2], bl[vp][3],
                           sb + SVL + swz(ktj * 16 + vrr, vp * 16 + vcb));
                }
                #pragma unroll
                for (int vp = 0; vp < 4; vp++) {
                    mma_bf16(O[2 * vp],     ahh, bh[vp][0], bh[vp][1]);
                    mma_bf16(O[2 * vp + 1], ahh, bh[vp][2], bh[vp][3]);
                }
                #pragma unroll
                for (int vp = 0; vp < 4; vp++) {
                    mma_bf16(O[2 * vp],     all, bh[vp][0], bh[vp][1]);
                    mma_bf16(O[2 * vp + 1], all, bh[vp][2], bh[vp][3]);
                }
                #pragma unroll
                for (int vp = 0; vp < 4; vp++) {
                    mma_bf16(O[2 * vp],     ahh, bl[vp][0], bl[vp][1]);
                    mma_bf16(O[2 * vp + 1], ahh, bl[vp][2], bl[vp][3]);
                }
            }
        }
    }

    // ---- epilogue: normalize, split-store to g_ah/g_al ----
    const float inv0 = 1.f / l0, inv1 = 1.f / l1;
    __nv_bfloat16* aoh0 = g_ah + ((size_t)(b * SEQ + i_row0) * DMODEL + h * HD);
    __nv_bfloat16* aol0 = g_al + ((size_t)(b * SEQ + i_row0) * DMODEL + h * HD);
    __nv_bfloat16* aoh1 = g_ah + ((size_t)(b * SEQ + i_row1) * DMODEL + h * HD);
    __nv_bfloat16* aol1 = g_al + ((size_t)(b * SEQ + i_row1) * DMODEL + h * HD);
    #pragma unroll
    for (int nt = 0; nt < 8; nt++) {
        int v = nt * 8 + t2 * 2;
        float x0 = O[nt].x * inv0, y0 = O[nt].y * inv0;
        float x1 = O[nt].z * inv1, y1 = O[nt].w * inv1;
        *(uint32_t*)&aoh0[v] = pack_bf16(x0, y0);
        *(uint32_t*)&aol0[v] = pack_bf16(bf_res(x0), bf_res(y0));
        *(uint32_t*)&aoh1[v] = pack_bf16(x1, y1);
        *(uint32_t*)&aol1[v] = pack_bf16(bf_res(x1), bf_res(y1));
    }
}

// ===========================================================================
// Launch
// ===========================================================================
extern "C" void kernel_launch(void* const* d_in, const int* in_sizes, int n_in,
                              void* d_out, int out_size)
{
    (void)in_sizes; (void)n_in; (void)out_size;
    const float* x  = (const float*)d_in[0];
    const float* Wq = (const float*)d_in[1];
    const float* bq = (const float*)d_in[2];
    const float* Wk = (const float*)d_in[3];
    const float* bk = (const float*)d_in[4];
    const float* Wv = (const float*)d_in[5];
    const float* bv = (const float*)d_in[6];
    const float* Wo = (const float*)d_in[7];
    const float* bo = (const float*)d_in[8];

    float* out = (float*)d_out;
    float* rawOut = out + (size_t)BATCH * SEQ * DMODEL;

    void *qkvh, *qkvl, *xh, *xl, *wh, *wl, *ah, *al;
    cudaGetSymbolAddress(&qkvh, g_qkvh);
    cudaGetSymbolAddress(&qkvl, g_qkvl);
    cudaGetSymbolAddress(&xh, g_xh);
    cudaGetSymbolAddress(&xl, g_xl);
    cudaGetSymbolAddress(&wh, g_wh);
    cudaGetSymbolAddress(&wl, g_wl);
    cudaGetSymbolAddress(&ah, g_ah);
    cudaGetSymbolAddress(&al, g_al);

    __nv_bfloat16* whp = (__nv_bfloat16*)wh;
    __nv_bfloat16* wlp = (__nv_bfloat16*)wl;

    // splits
    int n4x = QKV_ELEMS / 4;
    split_kernel<<<n4x / 256, 256>>>(x, (__nv_bfloat16*)xh, (__nv_bfloat16*)xl, n4x);
    int n4w = WELEMS / 4;
    split_kernel<<<n4w / 256, 256>>>(Wq, whp,              wlp,              n4w);
    split_kernel<<<n4w / 256, 256>>>(Wk, whp + WELEMS,     wlp + WELEMS,     n4w);
    split_kernel<<<n4w / 256, 256>>>(Wv, whp + 2 * WELEMS, wlp + 2 * WELEMS, n4w);
    split_kernel<<<n4w / 256, 256>>>(Wo, whp + 3 * WELEMS, wlp + 3 * WELEMS, n4w);

    cudaFuncSetAttribute(gemm_bf16, cudaFuncAttributeMaxDynamicSharedMemorySize, GSM);
    cudaFuncSetAttribute(attn_mma, cudaFuncAttributeMaxDynamicSharedMemorySize, SM_ATTN);

    // QKV projections (fused over grid.z)
    gemm_bf16<<<dim3(M_ROWS / 128, 4, 3), 256, GSM>>>(
        (const __nv_bfloat16*)xh, (const __nv_bfloat16*)xl, whp, wlp,
        bq, bk, bv,
        (__nv_bfloat16*)qkvh, (__nv_bfloat16*)qkvl, nullptr, 0);

    // attention (raw scores + softmax + PV)
    attn_mma<<<dim3(SEQ / BR, NH, BATCH), 256, SM_ATTN>>>(rawOut);

    // output projection
    gemm_bf16<<<dim3(M_ROWS / 128, 4, 1), 256, GSM>>>(
        (const __nv_bfloat16*)ah, (const __nv_bfloat16*)al,
        whp + 3 * WELEMS, wlp + 3 * WELEMS,
        bo, bo, bo, nullptr, nullptr, out, 1);
}

// round 7
// speedup vs baseline: 2.8374x; 1.0341x over previous
#include <cuda_runtime.h>
#include <cuda_bf16.h>
#include <math.h>
#include <stdint.h>

// Problem constants
#define BATCH 2
#define SEQ   4096
#define DMODEL 512
#define NH    8
#define HD    64
#define M_ROWS (BATCH*SEQ)          // 8192
#define QKV_ELEMS (BATCH*NH*SEQ*HD) // 4,194,304 (== M_ROWS*DMODEL)
#define WELEMS (DMODEL*DMODEL)      // 262,144

// Scratch (device globals; no allocation allowed)
__device__ __nv_bfloat16 g_qkvh[3 * QKV_ELEMS]; // mat-major: Q,K,V [b][h][s][d]
__device__ __nv_bfloat16 g_qkvl[3 * QKV_ELEMS];
__device__ __nv_bfloat16 g_xh[QKV_ELEMS];       // x split  [8192][512]
__device__ __nv_bfloat16 g_xl[QKV_ELEMS];
__device__ __nv_bfloat16 g_wh[4 * WELEMS];      // Wq,Wk,Wv,Wo split [k][n]
__device__ __nv_bfloat16 g_wl[4 * WELEMS];
__device__ __nv_bfloat16 g_ah[QKV_ELEMS];       // attn out split [8192][512]
__device__ __nv_bfloat16 g_al[QKV_ELEMS];

// ===========================================================================
// Helpers
// ===========================================================================
__device__ __forceinline__ uint32_t smem_u32(const void* p) {
    uint32_t a;
    asm("{ .reg .u64 t; cvta.to.shared.u64 t, %1; cvt.u32.u64 %0, t; }"
        : "=r"(a) : "l"(p));
    return a;
}

__device__ __forceinline__ void mma_bf16(float4& d, const uint32_t* a,
                                         uint32_t b0, uint32_t b1) {
    asm volatile(
        "mma.sync.aligned.m16n8k16.row.col.f32.bf16.bf16.f32 "
        "{%0,%1,%2,%3}, {%4,%5,%6,%7}, {%8,%9}, {%0,%1,%2,%3};"
        : "+f"(d.x), "+f"(d.y), "+f"(d.z), "+f"(d.w)
        : "r"(a[0]), "r"(a[1]), "r"(a[2]), "r"(a[3]), "r"(b0), "r"(b1));
}

#define LDSM4(R0,R1,R2,R3,A) \
    asm volatile("ldmatrix.sync.aligned.m8n8.x4.shared.b16 {%0,%1,%2,%3}, [%4];" \
                 : "=r"(R0),"=r"(R1),"=r"(R2),"=r"(R3) : "r"(A))
#define LDSM4T(R0,R1,R2,R3,A) \
    asm volatile("ldmatrix.sync.aligned.m8n8.x4.trans.shared.b16 {%0,%1,%2,%3}, [%4];" \
                 : "=r"(R0),"=r"(R1),"=r"(R2),"=r"(R3) : "r"(A))

// pack two f32 -> bf16x2 (low half = first arg)
__device__ __forceinline__ uint32_t pack_bf16(float lo, float hi) {
    uint32_t d;
    asm("cvt.rn.bf16x2.f32 %0, %1, %2;" : "=r"(d) : "f"(hi), "f"(lo));
    return d;
}
__device__ __forceinline__ float bf_res(float x) {
    __nv_bfloat16 h = __float2bfloat16(x);
    return x - __bfloat162float(h);
}

// swizzled byte offset, [rows][64] bf16 tile, 128B pitch
__device__ __forceinline__ uint32_t swz(int r, int c) {
    return (uint32_t)(r * 128 + ((((c >> 3) ^ r) & 7) << 4) + (c & 7) * 2);
}
// swizzled byte offset, [rows][128] bf16 tile, 256B pitch (XOR low 3 seg bits)
__device__ __forceinline__ uint32_t swz256(int r, int c) {
    uint32_t seg = (uint32_t)(c >> 3);
    seg = (seg & 8u) | ((seg ^ (uint32_t)(r & 7)) & 7u);
    return (uint32_t)(r * 256) + seg * 16 + (uint32_t)((c & 7) * 2);
}

// ===========================================================================
// split: fp32 -> bf16 hi/lo
// ===========================================================================
__global__ void split_kernel(const float* __restrict__ s,
                             __nv_bfloat16* __restrict__ dh,
                             __nv_bfloat16* __restrict__ dl, int n4)
{
    int i = blockIdx.x * blockDim.x + threadIdx.x;
    if (i >= n4) return;
    float4 v = ((const float4*)s)[i];
    ((uint2*)dh)[i] = make_uint2(pack_bf16(v.x, v.y), pack_bf16(v.z, v.w));
    ((uint2*)dl)[i] = make_uint2(pack_bf16(bf_res(v.x), bf_res(v.y)),
                                 pack_bf16(bf_res(v.z), bf_res(v.w)));
}

// ===========================================================================
// bf16x3 tensor GEMM: C[8192 x 512] = A * W + bias (unchanged from R6)
// ===========================================================================
#define GA_H 0
#define GA_L 16384
#define GB_H 32768
#define GB_L 49152
#define GSM  65536

__global__ __launch_bounds__(256) void gemm_bf16(
    const __nv_bfloat16* __restrict__ Ah, const __nv_bfloat16* __restrict__ Al,
    const __nv_bfloat16* __restrict__ Wh, const __nv_bfloat16* __restrict__ Wl,
    const float* __restrict__ bias0, const float* __restrict__ bias1,
    const float* __restrict__ bias2,
    __nv_bfloat16* __restrict__ Oh, __nv_bfloat16* __restrict__ Ol,
    float* __restrict__ Ofp, int mode)
{
    extern __shared__ char smem[];
    const uint32_t sb = smem_u32(smem);
    const int tid = threadIdx.x, w = tid >> 5, L = tid & 31;
    const int t2 = L & 3;
    const int bm = blockIdx.x, bn = blockIdx.y, mat = blockIdx.z;
    const float* bias = (mat == 0) ? bias0 : (mat == 1) ? bias1 : bias2;
    const __nv_bfloat16* Whm = Wh + (size_t)mat * WELEMS;
    const __nv_bfloat16* Wlm = Wl + (size_t)mat * WELEMS;

    const int wm = (w >> 2) * 64, wn = (w & 3) * 32;
    float4 acc[4][4] = {};

    for (int k0 = 0; k0 < 512; k0 += 64) {
        __syncthreads();
        #pragma unroll
        for (int q = 0; q < 4; q++) {
            int i = tid + q * 256;
            int r = i >> 3, c = (i & 7) * 8;
            uint32_t off = swz(r, c);
            *(uint4*)(smem + GA_H + off) =
                *(const uint4*)&Ah[(size_t)(bm * 128 + r) * 512 + k0 + c];
            *(uint4*)(smem + GA_L + off) =
                *(const uint4*)&Al[(size_t)(bm * 128 + r) * 512 + k0 + c];
        }
        #pragma unroll
        for (int q = 0; q < 4; q++) {
            int i = tid + q * 256;
            int r = i >> 4, c = (i & 15) * 8;
            uint32_t off = swz256(r, c);
            *(uint4*)(smem + GB_H + off) =
                *(const uint4*)&Whm[(size_t)(k0 + r) * 512 + bn * 128 + c];
            *(uint4*)(smem + GB_L + off) =
                *(const uint4*)&Wlm[(size_t)(k0 + r) * 512 + bn * 128 + c];
        }
        __syncthreads();

        #pragma unroll
        for (int kt = 0; kt < 4; kt++) {
            uint32_t ah[4][4], al[4][4], bh[2][4], bl[2][4];
            int ar = (L & 7) + 8 * ((L >> 3) & 1);
            int ac = kt * 16 + 8 * ((L >> 4) & 1);
            #pragma unroll
            for (int mi = 0; mi < 4; mi++) {
                LDSM4(ah[mi][0], ah[mi][1], ah[mi][2], ah[mi][3],
                      sb + GA_H + swz(wm + mi * 16 + ar, ac));
                LDSM4(al[mi][0], al[mi][1], al[mi][2], al[mi][3],
                      sb + GA_L + swz(wm + mi * 16 + ar, ac));
            }
            int br = kt * 16 + (L & 7) + 8 * ((L >> 3) & 1);
            int bc = 8 * ((L >> 4) & 1);
            #pragma unroll
            for (int nj = 0; nj < 2; nj++) {
                LDSM4T(bh[nj][0], bh[nj][1], bh[nj][2], bh[nj][3],
                       sb + GB_H + swz256(br, wn + nj * 16 + bc));
                LDSM4T(bl[nj][0], bl[nj][1], bl[nj][2], bl[nj][3],
                       sb + GB_L + swz256(br, wn + nj * 16 + bc));
            }
            #pragma unroll
            for (int mi = 0; mi < 4; mi++)
                #pragma unroll
                for (int nj = 0; nj < 2; nj++) {
                    mma_bf16(acc[mi][2 * nj],     ah[mi], bh[nj][0], bh[nj][1]);
                    mma_bf16(acc[mi][2 * nj + 1], ah[mi], bh[nj][2], bh[nj][3]);
                }
            #pragma unroll
            for (int mi = 0; mi < 4; mi++)
                #pragma unroll
                for (int nj = 0; nj < 2; nj++) {
                    mma_bf16(acc[mi][2 * nj],     al[mi], bh[nj][0], bh[nj][1]);
                    mma_bf16(acc[mi][2 * nj + 1], al[mi], bh[nj][2], bh[nj][3]);
                }
            #pragma unroll
            for (int mi = 0; mi < 4; mi++)
                #pragma unroll
                for (int nj = 0; nj < 2; nj++) {
                    mma_bf16(acc[mi][2 * nj],     ah[mi], bl[nj][0], bl[nj][1]);
                    mma_bf16(acc[mi][2 * nj + 1], ah[mi], bl[nj][2], bl[nj][3]);
                }
        }
    }

    const float scl = (mode == 0 && mat == 0) ? 0.125f : 1.f;
    #pragma unroll
    for (int mi = 0; mi < 4; mi++) {
        #pragma unroll
        for (int nq = 0; nq < 4; nq++) {
            int r0 = bm * 128 + wm + mi * 16 + (L >> 2);
            int r1 = r0 + 8;
            int n = bn * 128 + wn + nq * 8 + t2 * 2;
            float bx = bias[n], by = bias[n + 1];
            float4 c = acc[mi][nq];
            float cx = (c.x + bx) * scl, cy = (c.y + by) * scl;
            float cz = (c.z + bx) * scl, cw = (c.w + by) * scl;
            if (mode == 0) {
                int hh = n >> 6, d = n & 63;
                int b0 = r0 >> 12, s0 = r0 & (SEQ - 1);
                int b1 = r1 >> 12, s1 = r1 & (SEQ - 1);
                size_t i0 = (size_t)mat * QKV_ELEMS +
                            (((size_t)(b0 * NH + hh)) * SEQ + s0) * HD + d;
                size_t i1 = (size_t)mat * QKV_ELEMS +
                            (((size_t)(b1 * NH + hh)) * SEQ + s1) * HD + d;
                *(uint32_t*)&Oh[i0] = pack_bf16(cx, cy);
                *(uint32_t*)&Ol[i0] = pack_bf16(bf_res(cx), bf_res(cy));
                *(uint32_t*)&Oh[i1] = pack_bf16(cz, cw);
                *(uint32_t*)&Ol[i1] = pack_bf16(bf_res(cz), bf_res(cw));
            } else {
                *(float2*)&Ofp[(size_t)r0 * 512 + n] = make_float2(cx, cy);
                *(float2*)&Ofp[(size_t)r1 * 512 + n] = make_float2(cz, cw);
            }
        }
    }
}

// ===========================================================================
// mma.sync attention; pre-split bf16 inputs (Q pre-scaled by 1/8).
// R7: Q fragments resident in registers; K/V double-buffered smem, one
// __syncthreads per j-tile.
// ===========================================================================
#define BR 128
#define BC 64

// per-buffer layout (each buffer 32KB): KH 0, KL 8K, VH 16K, VL 24K
#define BUF_SZ 32768
#define BKH 0
#define BKL 8192
#define BVH 16384
#define BVL 24576
#define SM_ATTN 65536

__global__ __launch_bounds__(256, 1) void attn_mma(float* __restrict__ rawOut)
{
    extern __shared__ char smem[];
    const uint32_t sb = smem_u32(smem);
    const int tid = threadIdx.x, w = tid >> 5, L = tid & 31;
    const int t2 = L & 3;
    const int it = (int)(gridDim.x - 1 - blockIdx.x);   // heavy blocks first
    const int i0 = it * BR, h = blockIdx.y, b = blockIdx.z;

    const size_t headOff = (size_t)(b * NH + h) * SEQ * HD;
    const __nv_bfloat16* Qh = g_qkvh + headOff + (size_t)i0 * HD;
    const __nv_bfloat16* Ql = g_qkvl + headOff + (size_t)i0 * HD;
    const __nv_bfloat16* Kh = g_qkvh + QKV_ELEMS + headOff;
    const __nv_bfloat16* Kl = g_qkvl + QKV_ELEMS + headOff;
    const __nv_bfloat16* Vh = g_qkvh + 2 * QKV_ELEMS + headOff;
    const __nv_bfloat16* Vl = g_qkvl + 2 * QKV_ELEMS + headOff;

    // ---- stage Q through smem (buffer area), preload fragments to regs ----
    for (int i = tid; i < 1024; i += 256) {
        int r = i >> 3, c = (i & 7) * 8;
        uint32_t off = swz(r, c);
        *(uint4*)(smem + off)         = *(const uint4*)&Qh[(size_t)r * HD + c];
        *(uint4*)(smem + 16384 + off) = *(const uint4*)&Ql[(size_t)r * HD + c];
    }
    __syncthreads();
    uint32_t qfh[4][4], qfl[4][4];
    {
        int qr = w * 16 + (L & 7) + 8 * ((L >> 3) & 1);
        #pragma unroll
        for (int kt = 0; kt < 4; kt++) {
            int qc = kt * 16 + 8 * ((L >> 4) & 1);
            LDSM4(qfh[kt][0], qfh[kt][1], qfh[kt][2], qfh[kt][3], sb + swz(qr, qc));
            LDSM4(qfl[kt][0], qfl[kt][1], qfl[kt][2], qfl[kt][3], sb + 16384 + swz(qr, qc));
        }
    }
    __syncthreads();   // Q regs captured; buffers may be overwritten

    const int i_row0 = i0 + w * 16 + (L >> 2);
    const int i_row1 = i_row0 + 8;
    const int iwmax = i0 + w * 16 + 15;
    const size_t raw0 = ((size_t)(h * BATCH + b) * SEQ + i_row0) * SEQ;
    const size_t raw1 = raw0 + 8ull * SEQ;
    const int lastCausal = 2 * it + 1;

    float4 O[8];
    #pragma unroll
    for (int nt = 0; nt < 8; nt++) O[nt] = make_float4(0.f, 0.f, 0.f, 0.f);
    float m0 = -INFINITY, m1 = -INFINITY, l0 = 0.f, l1 = 0.f;

    // gmem prefetch registers (tile jt=0)
    const int pr = tid >> 3, pc = (tid & 7) * 8;       // row 0..31 per q-slice
    uint4 kh2[2], kl2[2], vh2[2], vl2[2];
    #pragma unroll
    for (int q = 0; q < 2; q++) {
        int r = pr + q * 32;
        kh2[q] = *(const uint4*)&Kh[(size_t)r * HD + pc];
        kl2[q] = *(const uint4*)&Kl[(size_t)r * HD + pc];
        vh2[q] = *(const uint4*)&Vh[(size_t)r * HD + pc];
        vl2[q] = *(const uint4*)&Vl[(size_t)r * HD + pc];
    }

    for (int jt = 0; jt < 64; jt++) {
        const bool tileCausal = (jt <= lastCausal);
        const uint32_t bo = (uint32_t)(jt & 1) * BUF_SZ;
        // store prefetched tile into this buffer
        #pragma unroll
        for (int q = 0; q < 2; q++) {
            int r = pr + q * 32;
            uint32_t off = bo + swz(r, pc);
            *(uint4*)(smem + BKH + off) = kh2[q];
            *(uint4*)(smem + BKL + off) = kl2[q];
            if (tileCausal) {
                *(uint4*)(smem + BVH + off) = vh2[q];
                *(uint4*)(smem + BVL + off) = vl2[q];
            }
        }
        __syncthreads();
        // prefetch next tile (targets other buffer next iteration)
        if (jt < 63) {
            const size_t tOff = (size_t)(jt + 1) * BC * HD;
            const bool nextCausal = (jt + 1 <= lastCausal);
            #pragma unroll
            for (int q = 0; q < 2; q++) {
                int r = pr + q * 32;
                kh2[q] = *(const uint4*)&Kh[tOff + (size_t)r * HD + pc];
                kl2[q] = *(const uint4*)&Kl[tOff + (size_t)r * HD + pc];
                if (nextCausal) {
                    vh2[q] = *(const uint4*)&Vh[tOff + (size_t)r * HD + pc];
                    vl2[q] = *(const uint4*)&Vl[tOff + (size_t)r * HD + pc];
                }
            }
        }

        // ---- S = Q @ K^T (Q regs resident, bf16x3 term-major) ----
        float4 acc[8];
        #pragma unroll
        for (int nt = 0; nt < 8; nt++) acc[nt] = make_float4(0.f, 0.f, 0.f, 0.f);

        #pragma unroll
        for (int kt = 0; kt < 4; kt++) {
            int krr = (L & 7) + 8 * ((L >> 4) & 1);
            int kcc = kt * 16 + 8 * ((L >> 3) & 1);
            uint32_t bh[4][4], bl[4][4];
            #pragma unroll
            for (int p = 0; p < 4; p++) {
                LDSM4(bh[p][0], bh[p][1], bh[p][2], bh[p][3],
                      sb + bo + BKH + swz(16 * p + krr, kcc));
                LDSM4(bl[p][0], bl[p][1], bl[p][2], bl[p][3],
                      sb + bo + BKL + swz(16 * p + krr, kcc));
            }
            #pragma unroll
            for (int p = 0; p < 4; p++) {
                mma_bf16(acc[2 * p],     qfh[kt], bh[p][0], bh[p][1]);
                mma_bf16(acc[2 * p + 1], qfh[kt], bh[p][2], bh[p][3]);
            }
            #pragma unroll
            for (int p = 0; p < 4; p++) {
                mma_bf16(acc[2 * p],     qfl[kt], bh[p][0], bh[p][1]);
                mma_bf16(acc[2 * p + 1], qfl[kt], bh[p][2], bh[p][3]);
            }
            #pragma unroll
            for (int p = 0; p < 4; p++) {
                mma_bf16(acc[2 * p],     qfh[kt], bl[p][0], bl[p][1]);
                mma_bf16(acc[2 * p + 1], qfh[kt], bl[p][2], bl[p][3]);
            }
        }

        // ---- raw scores (pre-mask) ----
        #pragma unroll
        for (int nt = 0; nt < 8; nt++) {
            int j = jt * 64 + nt * 8 + t2 * 2;
            *(float2*)&rawOut[raw0 + j] = make_float2(acc[nt].x, acc[nt].y);
            *(float2*)&rawOut[raw1 + j] = make_float2(acc[nt].z, acc[nt].w);
        }

        // ---- softmax + PV (warp-uniform) ----
        if (jt * 64 <= iwmax) {
            const bool full = (jt * 64 + 63 <= i0 + w * 16);
            float mt0 = -INFINITY, mt1 = -INFINITY;
            #pragma unroll
            for (int nt = 0; nt < 8; nt++) {
                int j = jt * 64 + nt * 8 + t2 * 2;
                float ax = (full || j     <= i_row0) ? acc[nt].x : -INFINITY;
                float ay = (full || j + 1 <= i_row0) ? acc[nt].y : -INFINITY;
                float az = (full || j     <= i_row1) ? acc[nt].z : -INFINITY;
                float aw = (full || j + 1 <= i_row1) ? acc[nt].w : -INFINITY;
                mt0 = fmaxf(mt0, fmaxf(ax, ay));
                mt1 = fmaxf(mt1, fmaxf(az, aw));
            }
            mt0 = fmaxf(mt0, __shfl_xor_sync(0xffffffffu, mt0, 1));
            mt0 = fmaxf(mt0, __shfl_xor_sync(0xffffffffu, mt0, 2));
            mt1 = fmaxf(mt1, __shfl_xor_sync(0xffffffffu, mt1, 1));
            mt1 = fmaxf(mt1, __shfl_xor_sync(0xffffffffu, mt1, 2));

            float mn0 = fmaxf(m0, mt0), mn1 = fmaxf(m1, mt1);
            float sc0 = __expf(m0 - mn0), sc1 = __expf(m1 - mn1);

            float s0 = 0.f, s1 = 0.f;
            uint32_t ph[16], pl[16];
            #pragma unroll
            for (int nt = 0; nt < 8; nt++) {
                int j = jt * 64 + nt * 8 + t2 * 2;
                float px = (full || j     <= i_row0) ? __expf(acc[nt].x - mn0) : 0.f;
                float py = (full || j + 1 <= i_row0) ? __expf(acc[nt].y - mn0) : 0.f;
                float pz = (full || j     <= i_row1) ? __expf(acc[nt].z - mn1) : 0.f;
                float pw = (full || j + 1 <= i_row1) ? __expf(acc[nt].w - mn1) : 0.f;
                s0 += px + py; s1 += pz + pw;
                ph[2 * nt]     = pack_bf16(px, py);
                ph[2 * nt + 1] = pack_bf16(pz, pw);
                pl[2 * nt]     = pack_bf16(bf_res(px), bf_res(py));
                pl[2 * nt + 1] = pack_bf16(bf_res(pz), bf_res(pw));
            }
            s0 += __shfl_xor_sync(0xffffffffu, s0, 1);
            s0 += __shfl_xor_sync(0xffffffffu, s0, 2);
            s1 += __shfl_xor_sync(0xffffffffu, s1, 1);
            s1 += __shfl_xor_sync(0xffffffffu, s1, 2);
            l0 = l0 * sc0 + s0;  l1 = l1 * sc1 + s1;
            m0 = mn0;  m1 = mn1;

            #pragma unroll
            for (int nt = 0; nt < 8; nt++) {
                O[nt].x *= sc0; O[nt].y *= sc0;
                O[nt].z *= sc1; O[nt].w *= sc1;
            }

            // O += P @ V, term-major
            int vrr = (L & 7) + 8 * ((L >> 3) & 1);
            int vcb = 8 * ((L >> 4) & 1);
            #pragma unroll
            for (int ktj = 0; ktj < 4; ktj++) {
                const uint32_t* ahh = &ph[4 * ktj];
                const uint32_t* all = &pl[4 * ktj];
                uint32_t bh[4][4], bl[4][4];
                #pragma unroll
                for (int vp = 0; vp < 4; vp++) {
                    LDSM4T(bh[vp][0], bh[vp][1], bh[vp][2], bh[vp][3],
                           sb + bo + BVH + swz(ktj * 16 + vrr, vp * 16 + vcb));
                    LDSM4T(bl[vp][0], bl[vp][1], bl[vp][2], bl[vp][3],
                           sb + bo + BVL + swz(ktj * 16 + vrr, vp * 16 + vcb));
                }
                #pragma unroll
                for (int vp = 0; vp < 4; vp++) {
                    mma_bf16(O[2 * vp],     ahh, bh[vp][0], bh[vp][1]);
                    mma_bf16(O[2 * vp + 1], ahh, bh[vp][2], bh[vp][3]);
                }
                #pragma unroll
                for (int vp = 0; vp < 4; vp++) {
                    mma_bf16(O[2 * vp],     all, bh[vp][0], bh[vp][1]);
                    mma_bf16(O[2 * vp + 1], all, bh[vp][2], bh[vp][3]);
                }
                #pragma unroll
                for (int vp = 0; vp < 4; vp++) {
                    mma_bf16(O[2 * vp],     ahh, bl[vp][0], bl[vp][1]);
                    mma_bf16(O[2 * vp + 1], ahh, bl[vp][2], bl[vp][3]);
                }
            }
        }
    }

    // ---- epilogue: normalize, split-store to g_ah/g_al ----
    const float inv0 = 1.f / l0, inv1 = 1.f / l1;
    __nv_bfloat16* aoh0 = g_ah + ((size_t)(b * SEQ + i_row0) * DMODEL + h * HD);
    __nv_bfloat16* aol0 = g_al + ((size_t)(b * SEQ + i_row0) * DMODEL + h * HD);
    __nv_bfloat16* aoh1 = g_ah + ((size_t)(b * SEQ + i_row1) * DMODEL + h * HD);
    __nv_bfloat16* aol1 = g_al + ((size_t)(b * SEQ + i_row1) * DMODEL + h * HD);
    #pragma unroll
    for (int nt = 0; nt < 8; nt++) {
        int v = nt * 8 + t2 * 2;
        float x0 = O[nt].x * inv0, y0 = O[nt].y * inv0;
        float x1 = O[nt].z * inv1, y1 = O[nt].w * inv1;
        *(uint32_t*)&aoh0[v] = pack_bf16(x0, y0);
        *(uint32_t*)&aol0[v] = pack_bf16(bf_res(x0), bf_res(y0));
        *(uint32_t*)&aoh1[v] = pack_bf16(x1, y1);
        *(uint32_t*)&aol1[v] = pack_bf16(bf_res(x1), bf_res(y1));
    }
}

// ===========================================================================
// Launch
// ===========================================================================
extern "C" void kernel_launch(void* const* d_in, const int* in_sizes, int n_in,
                              void* d_out, int out_size)
{
    (void)in_sizes; (void)n_in; (void)out_size;
    const float* x  = (const float*)d_in[0];
    const float* Wq = (const float*)d_in[1];
    const float* bq = (const float*)d_in[2];
    const float* Wk = (const float*)d_in[3];
    const float* bk = (const float*)d_in[4];
    const float* Wv = (const float*)d_in[5];
    const float* bv = (const float*)d_in[6];
    const float* Wo = (const float*)d_in[7];
    const float* bo = (const float*)d_in[8];

    float* out = (float*)d_out;
    float* rawOut = out + (size_t)BATCH * SEQ * DMODEL;

    void *qkvh, *qkvl, *xh, *xl, *wh, *wl, *ah, *al;
    cudaGetSymbolAddress(&qkvh, g_qkvh);
    cudaGetSymbolAddress(&qkvl, g_qkvl);
    cudaGetSymbolAddress(&xh, g_xh);
    cudaGetSymbolAddress(&xl, g_xl);
    cudaGetSymbolAddress(&wh, g_wh);
    cudaGetSymbolAddress(&wl, g_wl);
    cudaGetSymbolAddress(&ah, g_ah);
    cudaGetSymbolAddress(&al, g_al);

    __nv_bfloat16* whp = (__nv_bfloat16*)wh;
    __nv_bfloat16* wlp = (__nv_bfloat16*)wl;

    // splits
    int n4x = QKV_ELEMS / 4;
    split_kernel<<<n4x / 256, 256>>>(x, (__nv_bfloat16*)xh, (__nv_bfloat16*)xl, n4x);
    int n4w = WELEMS / 4;
    split_kernel<<<n4w / 256, 256>>>(Wq, whp,              wlp,              n4w);
    split_kernel<<<n4w / 256, 256>>>(Wk, whp + WELEMS,     wlp + WELEMS,     n4w);
    split_kernel<<<n4w / 256, 256>>>(Wv, whp + 2 * WELEMS, wlp + 2 * WELEMS, n4w);
    split_kernel<<<n4w / 256, 256>>>(Wo, whp + 3 * WELEMS, wlp + 3 * WELEMS, n4w);

    cudaFuncSetAttribute(gemm_bf16, cudaFuncAttributeMaxDynamicSharedMemorySize, GSM);
    cudaFuncSetAttribute(attn_mma, cudaFuncAttributeMaxDynamicSharedMemorySize, SM_ATTN);

    // QKV projections (fused over grid.z)
    gemm_bf16<<<dim3(M_ROWS / 128, 4, 3), 256, GSM>>>(
        (const __nv_bfloat16*)xh, (const __nv_bfloat16*)xl, whp, wlp,
        bq, bk, bv,
        (__nv_bfloat16*)qkvh, (__nv_bfloat16*)qkvl, nullptr, 0);

    // attention (raw scores + softmax + PV)
    attn_mma<<<dim3(SEQ / BR, NH, BATCH), 256, SM_ATTN>>>(rawOut);

    // output projection
    gemm_bf16<<<dim3(M_ROWS / 128, 4, 1), 256, GSM>>>(
        (const __nv_bfloat16*)ah, (const __nv_bfloat16*)al,
        whp + 3 * WELEMS, wlp + 3 * WELEMS,
        bo, bo, bo, nullptr, nullptr, out, 1);
}

// round 9
// speedup vs baseline: 3.3785x; 1.1907x over previous
#include <cuda_runtime.h>
#include <cuda_bf16.h>
#include <cuda_fp16.h>
#include <math.h>
#include <stdint.h>

// Problem constants
#define BATCH 2
#define SEQ   4096
#define DMODEL 512
#define NH    8
#define HD    64
#define M_ROWS (BATCH*SEQ)          // 8192
#define QKV_ELEMS (BATCH*NH*SEQ*HD) // 4,194,304 (== M_ROWS*DMODEL)
#define WELEMS (DMODEL*DMODEL)      // 262,144

// Scratch (device globals; no allocation allowed)
// "h" buffers hold fp16 leading term; "l" buffers hold bf16:
//   for A-side tensors (x, Q, P, attnout): bf16 RESIDUAL (v - fp16(v))
//   for B-side tensors (W, K, V): bf16 of the FULL value
__device__ __half        g_qkvh[3 * QKV_ELEMS]; // mat-major: Q,K,V [b][h][s][d]
__device__ __nv_bfloat16 g_qkvl[3 * QKV_ELEMS];
__device__ __half        g_xh[QKV_ELEMS];       // x  [8192][512]
__device__ __nv_bfloat16 g_xl[QKV_ELEMS];
__device__ __half        g_wh[4 * WELEMS];      // Wq,Wk,Wv,Wo [k][n]
__device__ __nv_bfloat16 g_wl[4 * WELEMS];
__device__ __half        g_ah[QKV_ELEMS];       // attn out [8192][512]
__device__ __nv_bfloat16 g_al[QKV_ELEMS];

// ===========================================================================
// Helpers
// ===========================================================================
__device__ __forceinline__ uint32_t smem_u32(const void* p) {
    uint32_t a;
    asm("{ .reg .u64 t; cvta.to.shared.u64 t, %1; cvt.u32.u64 %0, t; }"
        : "=r"(a) : "l"(p));
    return a;
}

__device__ __forceinline__ void mma_bf16(float4& d, const uint32_t* a,
                                         uint32_t b0, uint32_t b1) {
    asm volatile(
        "mma.sync.aligned.m16n8k16.row.col.f32.bf16.bf16.f32 "
        "{%0,%1,%2,%3}, {%4,%5,%6,%7}, {%8,%9}, {%0,%1,%2,%3};"
        : "+f"(d.x), "+f"(d.y), "+f"(d.z), "+f"(d.w)
        : "r"(a[0]), "r"(a[1]), "r"(a[2]), "r"(a[3]), "r"(b0), "r"(b1));
}
__device__ __forceinline__ void mma_f16(float4& d, const uint32_t* a,
                                        uint32_t b0, uint32_t b1) {
    asm volatile(
        "mma.sync.aligned.m16n8k16.row.col.f32.f16.f16.f32 "
        "{%0,%1,%2,%3}, {%4,%5,%6,%7}, {%8,%9}, {%0,%1,%2,%3};"
        : "+f"(d.x), "+f"(d.y), "+f"(d.z), "+f"(d.w)
        : "r"(a[0]), "r"(a[1]), "r"(a[2]), "r"(a[3]), "r"(b0), "r"(b1));
}

#define LDSM4(R0,R1,R2,R3,A) \
    asm volatile("ldmatrix.sync.aligned.m8n8.x4.shared.b16 {%0,%1,%2,%3}, [%4];" \
                 : "=r"(R0),"=r"(R1),"=r"(R2),"=r"(R3) : "r"(A))
#define LDSM4T(R0,R1,R2,R3,A) \
    asm volatile("ldmatrix.sync.aligned.m8n8.x4.trans.shared.b16 {%0,%1,%2,%3}, [%4];" \
                 : "=r"(R0),"=r"(R1),"=r"(R2),"=r"(R3) : "r"(A))

// pack two f32 -> bf16x2 / f16x2 (low half = first arg)
__device__ __forceinline__ uint32_t pack_bf16(float lo, float hi) {
    uint32_t d;
    asm("cvt.rn.bf16x2.f32 %0, %1, %2;" : "=r"(d) : "f"(hi), "f"(lo));
    return d;
}
__device__ __forceinline__ uint32_t pack_f16(float lo, float hi) {
    uint32_t d;
    asm("cvt.rn.f16x2.f32 %0, %1, %2;" : "=r"(d) : "f"(hi), "f"(lo));
    return d;
}
__device__ __forceinline__ float f16_res(float x) {
    return x - __half2float(__float2half_rn(x));
}

// swizzled byte offset, [rows][64] 16-bit tile, 128B pitch
__device__ __forceinline__ uint32_t swz(int r, int c) {
    return (uint32_t)(r * 128 + ((((c >> 3) ^ r) & 7) << 4) + (c & 7) * 2);
}
// swizzled byte offset, [rows][128] 16-bit tile, 256B pitch
__device__ __forceinline__ uint32_t swz256(int r, int c) {
    uint32_t seg = (uint32_t)(c >> 3);
    seg = (seg & 8u) | ((seg ^ (uint32_t)(r & 7)) & 7u);
    return (uint32_t)(r * 256) + seg * 16 + (uint32_t)((c & 7) * 2);
}

// ===========================================================================
// split: fp32 -> fp16 hi + bf16 (residual if full==0, full value if full==1)
// ===========================================================================
__global__ void split_kernel(const float* __restrict__ s,
                             __half* __restrict__ dh,
                             __nv_bfloat16* __restrict__ dl, int n4, int full)
{
    int i = blockIdx.x * blockDim.x + threadIdx.x;
    if (i >= n4) return;
    float4 v = ((const float4*)s)[i];
    ((uint2*)dh)[i] = make_uint2(pack_f16(v.x, v.y), pack_f16(v.z, v.w));
    if (full) {
        ((uint2*)dl)[i] = make_uint2(pack_bf16(v.x, v.y), pack_bf16(v.z, v.w));
    } else {
        ((uint2*)dl)[i] = make_uint2(pack_bf16(f16_res(v.x), f16_res(v.y)),
                                     pack_bf16(f16_res(v.z), f16_res(v.w)));
    }
}

// ===========================================================================
// 2-term mixed GEMM: C[8192 x 512] = A * W + bias
// term1: fp16(A)*fp16(W);  term2: bf16res(A)*bf16(W)
// mode 0: per-mat permuted store into g_qkvh/l (Q: fp16+res; K/V: fp16+full)
// mode 1: fp32 row-major store
// ===========================================================================
#define GA_H 0
#define GA_L 16384
#define GB_H 32768
#define GB_B 49152
#define GSM  65536

__global__ __launch_bounds__(256) void gemm_mix(
    const __half* __restrict__ Ah, const __nv_bfloat16* __restrict__ Al,
    const __half* __restrict__ Wh, const __nv_bfloat16* __restrict__ Wl,
    const float* __restrict__ bias0, const float* __restrict__ bias1,
    const float* __restrict__ bias2,
    __half* __restrict__ Oh, __nv_bfloat16* __restrict__ Ol,
    float* __restrict__ Ofp, int mode)
{
    extern __shared__ char smem[];
    const uint32_t sb = smem_u32(smem);
    const int tid = threadIdx.x, w = tid >> 5, L = tid & 31;
    const int t2 = L & 3;
    const int bm = blockIdx.x, bn = blockIdx.y, mat = blockIdx.z;
    const float* bias = (mat == 0) ? bias0 : (mat == 1) ? bias1 : bias2;
    const __half* Whm = Wh + (size_t)mat * WELEMS;
    const __nv_bfloat16* Wlm = Wl + (size_t)mat * WELEMS;

    const int wm = (w >> 2) * 64, wn = (w & 3) * 32;
    float4 acc[4][4] = {};

    for (int k0 = 0; k0 < 512; k0 += 64) {
        __syncthreads();
        #pragma unroll
        for (int q = 0; q < 4; q++) {
            int i = tid + q * 256;
            int r = i >> 3, c = (i & 7) * 8;
            uint32_t off = swz(r, c);
            *(uint4*)(smem + GA_H + off) =
                *(const uint4*)&Ah[(size_t)(bm * 128 + r) * 512 + k0 + c];
            *(uint4*)(smem + GA_L + off) =
                *(const uint4*)&Al[(size_t)(bm * 128 + r) * 512 + k0 + c];
        }
        #pragma unroll
        for (int q = 0; q < 4; q++) {
            int i = tid + q * 256;
            int r = i >> 4, c = (i & 15) * 8;
            uint32_t off = swz256(r, c);
            *(uint4*)(smem + GB_H + off) =
                *(const uint4*)&Whm[(size_t)(k0 + r) * 512 + bn * 128 + c];
            *(uint4*)(smem + GB_B + off) =
                *(const uint4*)&Wlm[(size_t)(k0 + r) * 512 + bn * 128 + c];
        }
        __syncthreads();

        #pragma unroll
        for (int kt = 0; kt < 4; kt++) {
            uint32_t ah[4][4], al[4][4], bh[2][4], bb[2][4];
            int ar = (L & 7) + 8 * ((L >> 3) & 1);
            int ac = kt * 16 + 8 * ((L >> 4) & 1);
            #pragma unroll
            for (int mi = 0; mi < 4; mi++) {
                LDSM4(ah[mi][0], ah[mi][1], ah[mi][2], ah[mi][3],
                      sb + GA_H + swz(wm + mi * 16 + ar, ac));
                LDSM4(al[mi][0], al[mi][1], al[mi][2], al[mi][3],
                      sb + GA_L + swz(wm + mi * 16 + ar, ac));
            }
            int br = kt * 16 + (L & 7) + 8 * ((L >> 3) & 1);
            int bc = 8 * ((L >> 4) & 1);
            #pragma unroll
            for (int nj = 0; nj < 2; nj++) {
                LDSM4T(bh[nj][0], bh[nj][1], bh[nj][2], bh[nj][3],
                       sb + GB_H + swz256(br, wn + nj * 16 + bc));
                LDSM4T(bb[nj][0], bb[nj][1], bb[nj][2], bb[nj][3],
                       sb + GB_B + swz256(br, wn + nj * 16 + bc));
            }
            #pragma unroll
            for (int mi = 0; mi < 4; mi++)
                #pragma unroll
                for (int nj = 0; nj < 2; nj++) {
                    mma_f16(acc[mi][2 * nj],     ah[mi], bh[nj][0], bh[nj][1]);
                    mma_f16(acc[mi][2 * nj + 1], ah[mi], bh[nj][2], bh[nj][3]);
                }
            #pragma unroll
            for (int mi = 0; mi < 4; mi++)
                #pragma unroll
                for (int nj = 0; nj < 2; nj++) {
                    mma_bf16(acc[mi][2 * nj],     al[mi], bb[nj][0], bb[nj][1]);
                    mma_bf16(acc[mi][2 * nj + 1], al[mi], bb[nj][2], bb[nj][3]);
                }
        }
    }

    const bool isQ = (mode == 0 && mat == 0);
    const float scl = isQ ? 0.125f : 1.f;
    #pragma unroll
    for (int mi = 0; mi < 4; mi++) {
        #pragma unroll
        for (int nq = 0; nq < 4; nq++) {
            int r0 = bm * 128 + wm + mi * 16 + (L >> 2);
            int r1 = r0 + 8;
            int n = bn * 128 + wn + nq * 8 + t2 * 2;
            float bx = bias[n], by = bias[n + 1];
            float4 c = acc[mi][nq];
            float cx = (c.x + bx) * scl, cy = (c.y + by) * scl;
            float cz = (c.z + bx) * scl, cw = (c.w + by) * scl;
            if (mode == 0) {
                int hh = n >> 6, d = n & 63;
                int b0 = r0 >> 12, s0 = r0 & (SEQ - 1);
                int b1 = r1 >> 12, s1 = r1 & (SEQ - 1);
                size_t i0 = (size_t)mat * QKV_ELEMS +
                            (((size_t)(b0 * NH + hh)) * SEQ + s0) * HD + d;
                size_t i1 = (size_t)mat * QKV_ELEMS +
                            (((size_t)(b1 * NH + hh)) * SEQ + s1) * HD + d;
                *(uint32_t*)&Oh[i0] = pack_f16(cx, cy);
                *(uint32_t*)&Oh[i1] = pack_f16(cz, cw);
                if (isQ) {
                    *(uint32_t*)&Ol[i0] = pack_bf16(f16_res(cx), f16_res(cy));
                    *(uint32_t*)&Ol[i1] = pack_bf16(f16_res(cz), f16_res(cw));
                } else {
                    *(uint32_t*)&Ol[i0] = pack_bf16(cx, cy);
                    *(uint32_t*)&Ol[i1] = pack_bf16(cz, cw);
                }
            } else {
                *(float2*)&Ofp[(size_t)r0 * 512 + n] = make_float2(cx, cy);
                *(float2*)&Ofp[(size_t)r1 * 512 + n] = make_float2(cz, cw);
            }
        }
    }
}

// ===========================================================================
// mma.sync attention, 2-term mixed precision.
// S: fp16(Q)*fp16(K) + bf16res(Q)*bf16(K).  PV: fp16(P)*fp16(V) + res*bf16(V)
// CTA = (b, h, 128-row q strip), 8 warps x 16 rows, 64 j-tiles of 64.
// Q frags register-resident; K/V double-buffered, one sync per tile.
// ===========================================================================
#define BR 128
#define BC 64

// per-buffer (32KB): KH(fp16) 0, KB(bf16) 8K, VH(fp16) 16K, VB(bf16) 24K
#define BUF_SZ 32768
#define BKH 0
#define BKB 8192
#define BVH 16384
#define BVB 24576
#define SM_ATTN 65536

__global__ __launch_bounds__(256, 1) void attn_mma(float* __restrict__ rawOut)
{
    extern __shared__ char smem[];
    const uint32_t sb = smem_u32(smem);
    const int tid = threadIdx.x, w = tid >> 5, L = tid & 31;
    const int t2 = L & 3;
    const int it = (int)(gridDim.x - 1 - blockIdx.x);   // heavy blocks first
    const int i0 = it * BR, h = blockIdx.y, b = blockIdx.z;

    const size_t headOff = (size_t)(b * NH + h) * SEQ * HD;
    const __half*        Qh = g_qkvh + headOff + (size_t)i0 * HD;
    const __nv_bfloat16* Ql = g_qkvl + headOff + (size_t)i0 * HD;
    const __half*        Kh = g_qkvh + QKV_ELEMS + headOff;
    const __nv_bfloat16* Kb = g_qkvl + QKV_ELEMS + headOff;
    const __half*        Vh = g_qkvh + 2 * QKV_ELEMS + headOff;
    const __nv_bfloat16* Vb = g_qkvl + 2 * QKV_ELEMS + headOff;

    // ---- stage Q through smem, preload fragments to regs ----
    for (int i = tid; i < 1024; i += 256) {
        int r = i >> 3, c = (i & 7) * 8;
        uint32_t off = swz(r, c);
        *(uint4*)(smem + off)         = *(const uint4*)&Qh[(size_t)r * HD + c];
        *(uint4*)(smem + 16384 + off) = *(const uint4*)&Ql[(size_t)r * HD + c];
    }
    __syncthreads();
    uint32_t qfh[4][4], qfl[4][4];
    {
        int qr = w * 16 + (L & 7) + 8 * ((L >> 3) & 1);
        #pragma unroll
        for (int kt = 0; kt < 4; kt++) {
            int qc = kt * 16 + 8 * ((L >> 4) & 1);
            LDSM4(qfh[kt][0], qfh[kt][1], qfh[kt][2], qfh[kt][3], sb + swz(qr, qc));
            LDSM4(qfl[kt][0], qfl[kt][1], qfl[kt][2], qfl[kt][3], sb + 16384 + swz(qr, qc));
        }
    }
    __syncthreads();

    const int i_row0 = i0 + w * 16 + (L >> 2);
    const int i_row1 = i_row0 + 8;
    const int iwmax = i0 + w * 16 + 15;
    const size_t raw0 = ((size_t)(h * BATCH + b) * SEQ + i_row0) * SEQ;
    const size_t raw1 = raw0 + 8ull * SEQ;
    const int lastCausal = 2 * it + 1;

    float4 O[8];
    #pragma unroll
    for (int nt = 0; nt < 8; nt++) O[nt] = make_float4(0.f, 0.f, 0.f, 0.f);
    float m0 = -INFINITY, m1 = -INFINITY, l0 = 0.f, l1 = 0.f;

    const int pr = tid >> 3, pc = (tid & 7) * 8;
    uint4 kh2[2], kb2[2], vh2[2], vb2[2];
    #pragma unroll
    for (int q = 0; q < 2; q++) {
        int r = pr + q * 32;
        kh2[q] = *(const uint4*)&Kh[(size_t)r * HD + pc];
        kb2[q] = *(const uint4*)&Kb[(size_t)r * HD + pc];
        vh2[q] = *(const uint4*)&Vh[(size_t)r * HD + pc];
        vb2[q] = *(const uint4*)&Vb[(size_t)r * HD + pc];
    }

    for (int jt = 0; jt < 64; jt++) {
        const bool tileCausal = (jt <= lastCausal);
        const uint32_t bo = (uint32_t)(jt & 1) * BUF_SZ;
        #pragma unroll
        for (int q = 0; q < 2; q++) {
            int r = pr + q * 32;
            uint32_t off = bo + swz(r, pc);
            *(uint4*)(smem + BKH + off) = kh2[q];
            *(uint4*)(smem + BKB + off) = kb2[q];
            if (tileCausal) {
                *(uint4*)(smem + BVH + off) = vh2[q];
                *(uint4*)(smem + BVB + off) = vb2[q];
            }
        }
        __syncthreads();
        if (jt < 63) {
            const size_t tOff = (size_t)(jt + 1) * BC * HD;
            const bool nextCausal = (jt + 1 <= lastCausal);
            #pragma unroll
            for (int q = 0; q < 2; q++) {
                int r = pr + q * 32;
                kh2[q] = *(const uint4*)&Kh[tOff + (size_t)r * HD + pc];
                kb2[q] = *(const uint4*)&Kb[tOff + (size_t)r * HD + pc];
                if (nextCausal) {
                    vh2[q] = *(const uint4*)&Vh[tOff + (size_t)r * HD + pc];
                    vb2[q] = *(const uint4*)&Vb[tOff + (size_t)r * HD + pc];
                }
            }
        }

        // ---- S = Q @ K^T (2-term) ----
        float4 acc[8];
        #pragma unroll
        for (int nt = 0; nt < 8; nt++) acc[nt] = make_float4(0.f, 0.f, 0.f, 0.f);

        #pragma unroll
        for (int kt = 0; kt < 4; kt++) {
            int krr = (L & 7) + 8 * ((L >> 4) & 1);
            int kcc = kt * 16 + 8 * ((L >> 3) & 1);
            uint32_t bh[4][4], bb[4][4];
            #pragma unroll
            for (int p = 0; p < 4; p++) {
                LDSM4(bh[p][0], bh[p][1], bh[p][2], bh[p][3],
                      sb + bo + BKH + swz(16 * p + krr, kcc));
                LDSM4(bb[p][0], bb[p][1], bb[p][2], bb[p][3],
                      sb + bo + BKB + swz(16 * p + krr, kcc));
            }
            #pragma unroll
            for (int p = 0; p < 4; p++) {
                mma_f16(acc[2 * p],     qfh[kt], bh[p][0], bh[p][1]);
                mma_f16(acc[2 * p + 1], qfh[kt], bh[p][2], bh[p][3]);
            }
            #pragma unroll
            for (int p = 0; p < 4; p++) {
                mma_bf16(acc[2 * p],     qfl[kt], bb[p][0], bb[p][1]);
                mma_bf16(acc[2 * p + 1], qfl[kt], bb[p][2], bb[p][3]);
            }
        }

        // ---- raw scores (pre-mask) ----
        #pragma unroll
        for (int nt = 0; nt < 8; nt++) {
            int j = jt * 64 + nt * 8 + t2 * 2;
            *(float2*)&rawOut[raw0 + j] = make_float2(acc[nt].x, acc[nt].y);
            *(float2*)&rawOut[raw1 + j] = make_float2(acc[nt].z, acc[nt].w);
        }

        // ---- softmax + PV (warp-uniform) ----
        if (jt * 64 <= iwmax) {
            const bool full = (jt * 64 + 63 <= i0 + w * 16);
            float mt0 = -INFINITY, mt1 = -INFINITY;
            #pragma unroll
            for (int nt = 0; nt < 8; nt++) {
                int j = jt * 64 + nt * 8 + t2 * 2;
                float ax = (full || j     <= i_row0) ? acc[nt].x : -INFINITY;
                float ay = (full || j + 1 <= i_row0) ? acc[nt].y : -INFINITY;
                float az = (full || j     <= i_row1) ? acc[nt].z : -INFINITY;
                float aw = (full || j + 1 <= i_row1) ? acc[nt].w : -INFINITY;
                mt0 = fmaxf(mt0, fmaxf(ax, ay));
                mt1 = fmaxf(mt1, fmaxf(az, aw));
            }
            mt0 = fmaxf(mt0, __shfl_xor_sync(0xffffffffu, mt0, 1));
            mt0 = fmaxf(mt0, __shfl_xor_sync(0xffffffffu, mt0, 2));
            mt1 = fmaxf(mt1, __shfl_xor_sync(0xffffffffu, mt1, 1));
            mt1 = fmaxf(mt1, __shfl_xor_sync(0xffffffffu, mt1, 2));

            float mn0 = fmaxf(m0, mt0), mn1 = fmaxf(m1, mt1);
            float sc0 = __expf(m0 - mn0), sc1 = __expf(m1 - mn1);

            float s0 = 0.f, s1 = 0.f;
            uint32_t ph[16], pl[16];
            #pragma unroll
            for (int nt = 0; nt < 8; nt++) {
                int j = jt * 64 + nt * 8 + t2 * 2;
                float px = (full || j     <= i_row0) ? __expf(acc[nt].x - mn0) : 0.f;
                float py = (full || j + 1 <= i_row0) ? __expf(acc[nt].y - mn0) : 0.f;
                float pz = (full || j     <= i_row1) ? __expf(acc[nt].z - mn1) : 0.f;
                float pw = (full || j + 1 <= i_row1) ? __expf(acc[nt].w - mn1) : 0.f;
                s0 += px + py; s1 += pz + pw;
                ph[2 * nt]     = pack_f16(px, py);
                ph[2 * nt + 1] = pack_f16(pz, pw);
                pl[2 * nt]     = pack_bf16(f16_res(px), f16_res(py));
                pl[2 * nt + 1] = pack_bf16(f16_res(pz), f16_res(pw));
            }
            s0 += __shfl_xor_sync(0xffffffffu, s0, 1);
            s0 += __shfl_xor_sync(0xffffffffu, s0, 2);
            s1 += __shfl_xor_sync(0xffffffffu, s1, 1);
            s1 += __shfl_xor_sync(0xffffffffu, s1, 2);
            l0 = l0 * sc0 + s0;  l1 = l1 * sc1 + s1;
            m0 = mn0;  m1 = mn1;

            #pragma unroll
            for (int nt = 0; nt < 8; nt++) {
                O[nt].x *= sc0; O[nt].y *= sc0;
                O[nt].z *= sc1; O[nt].w *= sc1;
            }

            // O += P @ V (2-term)
            int vrr = (L & 7) + 8 * ((L >> 3) & 1);
            int vcb = 8 * ((L >> 4) & 1);
            #pragma unroll
            for (int ktj = 0; ktj < 4; ktj++) {
                const uint32_t* ahh = &ph[4 * ktj];
                const uint32_t* all = &pl[4 * ktj];
                uint32_t bh[4][4], bb[4][4];
                #pragma unroll
                for (int vp = 0; vp < 4; vp++) {
                    LDSM4T(bh[vp][0], bh[vp][1], bh[vp][2], bh[vp][3],
                           sb + bo + BVH + swz(ktj * 16 + vrr, vp * 16 + vcb));
                    LDSM4T(bb[vp][0], bb[vp][1], bb[vp][2], bb[vp][3],
                           sb + bo + BVB + swz(ktj * 16 + vrr, vp * 16 + vcb));
                }
                #pragma unroll
                for (int vp = 0; vp < 4; vp++) {
                    mma_f16(O[2 * vp],     ahh, bh[vp][0], bh[vp][1]);
                    mma_f16(O[2 * vp + 1], ahh, bh[vp][2], bh[vp][3]);
                }
                #pragma unroll
                for (int vp = 0; vp < 4; vp++) {
                    mma_bf16(O[2 * vp],     all, bb[vp][0], bb[vp][1]);
                    mma_bf16(O[2 * vp + 1], all, bb[vp][2], bb[vp][3]);
                }
            }
        }
    }

    // ---- epilogue: normalize, split-store to g_ah/g_al ----
    const float inv0 = 1.f / l0, inv1 = 1.f / l1;
    __half* aoh0 = g_ah + ((size_t)(b * SEQ + i_row0) * DMODEL + h * HD);
    __nv_bfloat16* aol0 = g_al + ((size_t)(b * SEQ + i_row0) * DMODEL + h * HD);
    __half* aoh1 = g_ah + ((size_t)(b * SEQ + i_row1) * DMODEL + h * HD);
    __nv_bfloat16* aol1 = g_al + ((size_t)(b * SEQ + i_row1) * DMODEL + h * HD);
    #pragma unroll
    for (int nt = 0; nt < 8; nt++) {
        int v = nt * 8 + t2 * 2;
        float x0 = O[nt].x * inv0, y0 = O[nt].y * inv0;
        float x1 = O[nt].z * inv1, y1 = O[nt].w * inv1;
        *(uint32_t*)&aoh0[v] = pack_f16(x0, y0);
        *(uint32_t*)&aol0[v] = pack_bf16(f16_res(x0), f16_res(y0));
        *(uint32_t*)&aoh1[v] = pack_f16(x1, y1);
        *(uint32_t*)&aol1[v] = pack_bf16(f16_res(x1), f16_res(y1));
    }
}

// ===========================================================================
// Launch
// ===========================================================================
extern "C" void kernel_launch(void* const* d_in, const int* in_sizes, int n_in,
                              void* d_out, int out_size)
{
    (void)in_sizes; (void)n_in; (void)out_size;
    const float* x  = (const float*)d_in[0];
    const float* Wq = (const float*)d_in[1];
    const float* bq = (const float*)d_in[2];
    const float* Wk = (const float*)d_in[3];
    const float* bk = (const float*)d_in[4];
    const float* Wv = (const float*)d_in[5];
    const float* bv = (const float*)d_in[6];
    const float* Wo = (const float*)d_in[7];
    const float* bo = (const float*)d_in[8];

    float* out = (float*)d_out;
    float* rawOut = out + (size_t)BATCH * SEQ * DMODEL;

    void *qkvh, *qkvl, *xh, *xl, *wh, *wl, *ah, *al;
    cudaGetSymbolAddress(&qkvh, g_qkvh);
    cudaGetSymbolAddress(&qkvl, g_qkvl);
    cudaGetSymbolAddress(&xh, g_xh);
    cudaGetSymbolAddress(&xl, g_xl);
    cudaGetSymbolAddress(&wh, g_wh);
    cudaGetSymbolAddress(&wl, g_wl);
    cudaGetSymbolAddress(&ah, g_ah);
    cudaGetSymbolAddress(&al, g_al);

    __half* whp = (__half*)wh;
    __nv_bfloat16* wlp = (__nv_bfloat16*)wl;

    // splits: x -> fp16 + bf16 residual; W -> fp16 + bf16 full
    int n4x = QKV_ELEMS / 4;
    split_kernel<<<n4x / 256, 256>>>(x, (__half*)xh, (__nv_bfloat16*)xl, n4x, 0);
    int n4w = WELEMS / 4;
    split_kernel<<<n4w / 256, 256>>>(Wq, whp,              wlp,              n4w, 1);
    split_kernel<<<n4w / 256, 256>>>(Wk, whp + WELEMS,     wlp + WELEMS,     n4w, 1);
    split_kernel<<<n4w / 256, 256>>>(Wv, whp + 2 * WELEMS, wlp + 2 * WELEMS, n4w, 1);
    split_kernel<<<n4w / 256, 256>>>(Wo, whp + 3 * WELEMS, wlp + 3 * WELEMS, n4w, 1);

    cudaFuncSetAttribute(gemm_mix, cudaFuncAttributeMaxDynamicSharedMemorySize, GSM);
    cudaFuncSetAttribute(attn_mma, cudaFuncAttributeMaxDynamicSharedMemorySize, SM_ATTN);

    // QKV projections (fused over grid.z)
    gemm_mix<<<dim3(M_ROWS / 128, 4, 3), 256, GSM>>>(
        (const __half*)xh, (const __nv_bfloat16*)xl, whp, wlp,
        bq, bk, bv,
        (__half*)qkvh, (__nv_bfloat16*)qkvl, nullptr, 0);

    // attention (raw scores + softmax + PV)
    attn_mma<<<dim3(SEQ / BR, NH, BATCH), 256, SM_ATTN>>>(rawOut);

    // output projection
    gemm_mix<<<dim3(M_ROWS / 128, 4, 1), 256, GSM>>>(
        (const __half*)ah, (const __nv_bfloat16*)al,
        whp + 3 * WELEMS, wlp + 3 * WELEMS,
        bo, bo, bo, nullptr, nullptr, out, 1);
}

// round 12
// speedup vs baseline: 3.5241x; 1.0431x over previous
#include <cuda_runtime.h>
#include <cuda_bf16.h>
#include <cuda_fp16.h>
#include <math.h>
#include <stdint.h>

// Problem constants
#define BATCH 2
#define SEQ   4096
#define DMODEL 512
#define NH    8
#define HD    64
#define M_ROWS (BATCH*SEQ)          // 8192
#define QKV_ELEMS (BATCH*NH*SEQ*HD) // 4,194,304
#define WELEMS (DMODEL*DMODEL)      // 262,144

// Scratch (device globals)
// "h" = fp16 leading term; "l":
//   A-side tensors (x, Q, P, attnout): bf16 RESIDUAL (v - fp16(v))
//   B-side tensors (W, K, V): bf16 of the FULL value
__device__ __half        g_qkvh[3 * QKV_ELEMS];
__device__ __nv_bfloat16 g_qkvl[3 * QKV_ELEMS];
__device__ __half        g_xh[QKV_ELEMS];
__device__ __nv_bfloat16 g_xl[QKV_ELEMS];
__device__ __half        g_wh[4 * WELEMS];
__device__ __nv_bfloat16 g_wl[4 * WELEMS];
__device__ __half        g_ah[QKV_ELEMS];
__device__ __nv_bfloat16 g_al[QKV_ELEMS];

// ===========================================================================
// Helpers
// ===========================================================================
__device__ __forceinline__ uint32_t smem_u32(const void* p) {
    uint32_t a;
    asm("{ .reg .u64 t; cvta.to.shared.u64 t, %1; cvt.u32.u64 %0, t; }"
        : "=r"(a) : "l"(p));
    return a;
}

__device__ __forceinline__ void mma_bf16(float4& d, const uint32_t* a,
                                         uint32_t b0, uint32_t b1) {
    asm volatile(
        "mma.sync.aligned.m16n8k16.row.col.f32.bf16.bf16.f32 "
        "{%0,%1,%2,%3}, {%4,%5,%6,%7}, {%8,%9}, {%0,%1,%2,%3};"
        : "+f"(d.x), "+f"(d.y), "+f"(d.z), "+f"(d.w)
        : "r"(a[0]), "r"(a[1]), "r"(a[2]), "r"(a[3]), "r"(b0), "r"(b1));
}
__device__ __forceinline__ void mma_f16(float4& d, const uint32_t* a,
                                        uint32_t b0, uint32_t b1) {
    asm volatile(
        "mma.sync.aligned.m16n8k16.row.col.f32.f16.f16.f32 "
        "{%0,%1,%2,%3}, {%4,%5,%6,%7}, {%8,%9}, {%0,%1,%2,%3};"
        : "+f"(d.x), "+f"(d.y), "+f"(d.z), "+f"(d.w)
        : "r"(a[0]), "r"(a[1]), "r"(a[2]), "r"(a[3]), "r"(b0), "r"(b1));
}

#define LDSM4(R0,R1,R2,R3,A) \
    asm volatile("ldmatrix.sync.aligned.m8n8.x4.shared.b16 {%0,%1,%2,%3}, [%4];" \
                 : "=r"(R0),"=r"(R1),"=r"(R2),"=r"(R3) : "r"(A))
#define LDSM4T(R0,R1,R2,R3,A) \
    asm volatile("ldmatrix.sync.aligned.m8n8.x4.trans.shared.b16 {%0,%1,%2,%3}, [%4];" \
                 : "=r"(R0),"=r"(R1),"=r"(R2),"=r"(R3) : "r"(A))

#define CP_ASYNC16(dst, src) \
    asm volatile("cp.async.cg.shared.global [%0], [%1], 16;" :: "r"(dst), "l"(src))
#define CP_COMMIT() asm volatile("cp.async.commit_group;" ::: "memory")
#define CP_WAIT0()  asm volatile("cp.async.wait_group 0;" ::: "memory")

__device__ __forceinline__ uint32_t pack_bf16(float lo, float hi) {
    uint32_t d;
    asm("cvt.rn.bf16x2.f32 %0, %1, %2;" : "=r"(d) : "f"(hi), "f"(lo));
    return d;
}
__device__ __forceinline__ uint32_t pack_f16(float lo, float hi) {
    uint32_t d;
    asm("cvt.rn.f16x2.f32 %0, %1, %2;" : "=r"(d) : "f"(hi), "f"(lo));
    return d;
}
__device__ __forceinline__ float f16_res(float x) {
    return x - __half2float(__float2half_rn(x));
}

// swizzled byte offset, [rows][64] 16-bit tile, 128B pitch
__device__ __forceinline__ uint32_t swz(int r, int c) {
    return (uint32_t)(r * 128 + ((((c >> 3) ^ r) & 7) << 4) + (c & 7) * 2);
}
// swizzled byte offset, [rows][128] 16-bit tile, 256B pitch
__device__ __forceinline__ uint32_t swz256(int r, int c) {
    uint32_t seg = (uint32_t)(c >> 3);
    seg = (seg & 8u) | ((seg ^ (uint32_t)(r & 7)) & 7u);
    return (uint32_t)(r * 256) + seg * 16 + (uint32_t)((c & 7) * 2);
}

// ===========================================================================
// splits: fp32 -> fp16 hi + bf16 (residual or full)
// ===========================================================================
__global__ void split_kernel(const float* __restrict__ s,
                             __half* __restrict__ dh,
                             __nv_bfloat16* __restrict__ dl, int n4, int full)
{
    int i = blockIdx.x * blockDim.x + threadIdx.x;
    if (i >= n4) return;
    float4 v = ((const float4*)s)[i];
    ((uint2*)dh)[i] = make_uint2(pack_f16(v.x, v.y), pack_f16(v.z, v.w));
    if (full) {
        ((uint2*)dl)[i] = make_uint2(pack_bf16(v.x, v.y), pack_bf16(v.z, v.w));
    } else {
        ((uint2*)dl)[i] = make_uint2(pack_bf16(f16_res(v.x), f16_res(v.y)),
                                     pack_bf16(f16_res(v.z), f16_res(v.w)));
    }
}

// fused weight split: 4 matrices, blockIdx.y selects
__global__ void split_w_kernel(const float* __restrict__ w0,
                               const float* __restrict__ w1,
                               const float* __restrict__ w2,
                               const float* __restrict__ w3,
                               __half* __restrict__ dh,
                               __nv_bfloat16* __restrict__ dl, int n4)
{
    int i = blockIdx.x * blockDim.x + threadIdx.x;
    if (i >= n4) return;
    int m = blockIdx.y;
    const float* s = (m == 0) ? w0 : (m == 1) ? w1 : (m == 2) ? w2 : w3;
    float4 v = ((const float4*)s)[i];
    size_t o = (size_t)m * (WELEMS / 4) + i;
    ((uint2*)dh)[o] = make_uint2(pack_f16(v.x, v.y), pack_f16(v.z, v.w));
    ((uint2*)dl)[o] = make_uint2(pack_bf16(v.x, v.y), pack_bf16(v.z, v.w));
}

// ===========================================================================
// 2-term mixed GEMM: C[8192 x 512] = A * W + bias
// ===========================================================================
#define GA_H 0
#define GA_L 16384
#define GB_H 32768
#define GB_B 49152
#define GSM  65536

__global__ __launch_bounds__(256) void gemm_mix(
    const __half* __restrict__ Ah, const __nv_bfloat16* __restrict__ Al,
    const __half* __restrict__ Wh, const __nv_bfloat16* __restrict__ Wl,
    const float* __restrict__ bias0, const float* __restrict__ bias1,
    const float* __restrict__ bias2,
    __half* __restrict__ Oh, __nv_bfloat16* __restrict__ Ol,
    float* __restrict__ Ofp, int mode)
{
    extern __shared__ char smem[];
    const uint32_t sb = smem_u32(smem);
    const int tid = threadIdx.x, w = tid >> 5, L = tid & 31;
    const int t2 = L & 3;
    const int bm = blockIdx.x, bn = blockIdx.y, mat = blockIdx.z;
    const float* bias = (mat == 0) ? bias0 : (mat == 1) ? bias1 : bias2;
    const __half* Whm = Wh + (size_t)mat * WELEMS;
    const __nv_bfloat16* Wlm = Wl + (size_t)mat * WELEMS;

    const int wm = (w >> 2) * 64, wn = (w & 3) * 32;
    float4 acc[4][4] = {};

    for (int k0 = 0; k0 < 512; k0 += 64) {
        __syncthreads();
        #pragma unroll
        for (int q = 0; q < 4; q++) {
            int i = tid + q * 256;
            int r = i >> 3, c = (i & 7) * 8;
            uint32_t off = swz(r, c);
            *(uint4*)(smem + GA_H + off) =
                *(const uint4*)&Ah[(size_t)(bm * 128 + r) * 512 + k0 + c];
            *(uint4*)(smem + GA_L + off) =
                *(const uint4*)&Al[(size_t)(bm * 128 + r) * 512 + k0 + c];
        }
        #pragma unroll
        for (int q = 0; q < 4; q++) {
            int i = tid + q * 256;
            int r = i >> 4, c = (i & 15) * 8;
            uint32_t off = swz256(r, c);
            *(uint4*)(smem + GB_H + off) =
                *(const uint4*)&Whm[(size_t)(k0 + r) * 512 + bn * 128 + c];
            *(uint4*)(smem + GB_B + off) =
                *(const uint4*)&Wlm[(size_t)(k0 + r) * 512 + bn * 128 + c];
        }
        __syncthreads();

        #pragma unroll
        for (int kt = 0; kt < 4; kt++) {
            uint32_t ah[4][4], al[4][4], bh[2][4], bb[2][4];
            int ar = (L & 7) + 8 * ((L >> 3) & 1);
            int ac = kt * 16 + 8 * ((L >> 4) & 1);
            #pragma unroll
            for (int mi = 0; mi < 4; mi++) {
                LDSM4(ah[mi][0], ah[mi][1], ah[mi][2], ah[mi][3],
                      sb + GA_H + swz(wm + mi * 16 + ar, ac));
                LDSM4(al[mi][0], al[mi][1], al[mi][2], al[mi][3],
                      sb + GA_L + swz(wm + mi * 16 + ar, ac));
            }
            int br = kt * 16 + (L & 7) + 8 * ((L >> 3) & 1);
            int bc = 8 * ((L >> 4) & 1);
            #pragma unroll
            for (int nj = 0; nj < 2; nj++) {
                LDSM4T(bh[nj][0], bh[nj][1], bh[nj][2], bh[nj][3],
                       sb + GB_H + swz256(br, wn + nj * 16 + bc));
                LDSM4T(bb[nj][0], bb[nj][1], bb[nj][2], bb[nj][3],
                       sb + GB_B + swz256(br, wn + nj * 16 + bc));
            }
            #pragma unroll
            for (int mi = 0; mi < 4; mi++)
                #pragma unroll
                for (int nj = 0; nj < 2; nj++) {
                    mma_f16(acc[mi][2 * nj],     ah[mi], bh[nj][0], bh[nj][1]);
                    mma_f16(acc[mi][2 * nj + 1], ah[mi], bh[nj][2], bh[nj][3]);
                }
            #pragma unroll
            for (int mi = 0; mi < 4; mi++)
                #pragma unroll
                for (int nj = 0; nj < 2; nj++) {
                    mma_bf16(acc[mi][2 * nj],     al[mi], bb[nj][0], bb[nj][1]);
                    mma_bf16(acc[mi][2 * nj + 1], al[mi], bb[nj][2], bb[nj][3]);
                }
        }
    }

    const bool isQ = (mode == 0 && mat == 0);
    const float scl = isQ ? 0.125f : 1.f;
    #pragma unroll
    for (int mi = 0; mi < 4; mi++) {
        #pragma unroll
        for (int nq = 0; nq < 4; nq++) {
            int r0 = bm * 128 + wm + mi * 16 + (L >> 2);
            int r1 = r0 + 8;
            int n = bn * 128 + wn + nq * 8 + t2 * 2;
            float bx = bias[n], by = bias[n + 1];
            float4 c = acc[mi][nq];
            float cx = (c.x + bx) * scl, cy = (c.y + by) * scl;
            float cz = (c.z + bx) * scl, cw = (c.w + by) * scl;
            if (mode == 0) {
                int hh = n >> 6, d = n & 63;
                int b0 = r0 >> 12, s0 = r0 & (SEQ - 1);
                int b1 = r1 >> 12, s1 = r1 & (SEQ - 1);
                size_t i0 = (size_t)mat * QKV_ELEMS +
                            (((size_t)(b0 * NH + hh)) * SEQ + s0) * HD + d;
                size_t i1 = (size_t)mat * QKV_ELEMS +
                            (((size_t)(b1 * NH + hh)) * SEQ + s1) * HD + d;
                *(uint32_t*)&Oh[i0] = pack_f16(cx, cy);
                *(uint32_t*)&Oh[i1] = pack_f16(cz, cw);
                if (isQ) {
                    *(uint32_t*)&Ol[i0] = pack_bf16(f16_res(cx), f16_res(cy));
                    *(uint32_t*)&Ol[i1] = pack_bf16(f16_res(cz), f16_res(cw));
                } else {
                    *(uint32_t*)&Ol[i0] = pack_bf16(cx, cy);
                    *(uint32_t*)&Ol[i1] = pack_bf16(cz, cw);
                }
            } else {
                *(float2*)&Ofp[(size_t)r0 * 512 + n] = make_float2(cx, cy);
                *(float2*)&Ofp[(size_t)r1 * 512 + n] = make_float2(cz, cw);
            }
        }
    }
}

// ===========================================================================
// Attention, 2-term mixed: 2 CTAs/SM, cp.async K/V pipeline, Q-lo in smem.
// R11 fix: QL region is 16KB (128 rows x 128B pitch) -> SM_ATTN = 80KB.
// ===========================================================================
#define BR 128
#define BC 64

#define BUF_SZ 32768
#define BKH 0
#define BKB 8192
#define BVH 16384
#define BVB 24576
#define SQL_OFF 65536          // 16KB QL region (128 rows x 128B pitch)
#define SM_ATTN 81920          // 65536 + 16384

__global__ __launch_bounds__(256, 2) void attn_mma(float* __restrict__ rawOut)
{
    extern __shared__ char smem[];
    const uint32_t sb = smem_u32(smem);
    const int tid = threadIdx.x, w = tid >> 5, L = tid & 31;
    const int t2 = L & 3;
    const int it = (int)(gridDim.x - 1 - blockIdx.x);   // heavy blocks first
    const int i0 = it * BR, h = blockIdx.y, b = blockIdx.z;

    const size_t headOff = (size_t)(b * NH + h) * SEQ * HD;
    const __half*        Qh = g_qkvh + headOff + (size_t)i0 * HD;
    const __nv_bfloat16* Ql = g_qkvl + headOff + (size_t)i0 * HD;
    const __half*        Kh = g_qkvh + QKV_ELEMS + headOff;
    const __nv_bfloat16* Kb = g_qkvl + QKV_ELEMS + headOff;
    const __half*        Vh = g_qkvh + 2 * QKV_ELEMS + headOff;
    const __nv_bfloat16* Vb = g_qkvl + 2 * QKV_ELEMS + headOff;

    // ---- stage Q: hi into buffer area (temp), lo into dedicated region ----
    for (int i = tid; i < 1024; i += 256) {
        int r = i >> 3, c = (i & 7) * 8;
        uint32_t off = swz(r, c);
        *(uint4*)(smem + off)           = *(const uint4*)&Qh[(size_t)r * HD + c];
        *(uint4*)(smem + SQL_OFF + off) = *(const uint4*)&Ql[(size_t)r * HD + c];
    }
    __syncthreads();
    uint32_t qfh[4][4];
    const int qr = w * 16 + (L & 7) + 8 * ((L >> 3) & 1);
    const int qcb = 8 * ((L >> 4) & 1);
    #pragma unroll
    for (int kt = 0; kt < 4; kt++) {
        LDSM4(qfh[kt][0], qfh[kt][1], qfh[kt][2], qfh[kt][3],
              sb + swz(qr, kt * 16 + qcb));
    }
    __syncthreads();   // qfh captured; buffer area free

    const int i_row0 = i0 + w * 16 + (L >> 2);
    const int i_row1 = i_row0 + 8;
    const int iwmax = i0 + w * 16 + 15;
    const size_t raw0 = ((size_t)(h * BATCH + b) * SEQ + i_row0) * SEQ;
    const size_t raw1 = raw0 + 8ull * SEQ;
    const int lastCausal = 2 * it + 1;

    float4 O[8];
    #pragma unroll
    for (int nt = 0; nt < 8; nt++) O[nt] = make_float4(0.f, 0.f, 0.f, 0.f);
    float m0 = -INFINITY, m1 = -INFINITY, l0 = 0.f, l1 = 0.f;

    const int pr = tid >> 3, pc = (tid & 7) * 8;

    // cp.async prefetch of one j-tile into buffer bo
    auto prefetch = [&](int jt, uint32_t bo) {
        const size_t tOff = (size_t)jt * BC * HD;
        const bool causal = (jt <= lastCausal);
        #pragma unroll
        for (int q = 0; q < 2; q++) {
            int r = pr + q * 32;
            uint32_t off = bo + swz(r, pc);
            CP_ASYNC16(sb + BKH + off, &Kh[tOff + (size_t)r * HD + pc]);
            CP_ASYNC16(sb + BKB + off, &Kb[tOff + (size_t)r * HD + pc]);
            if (causal) {
                CP_ASYNC16(sb + BVH + off, &Vh[tOff + (size_t)r * HD + pc]);
                CP_ASYNC16(sb + BVB + off, &Vb[tOff + (size_t)r * HD + pc]);
            }
        }
        CP_COMMIT();
    };

    prefetch(0, 0);

    for (int jt = 0; jt < 64; jt++) {
        const uint32_t bo = (uint32_t)(jt & 1) * BUF_SZ;
        CP_WAIT0();
        __syncthreads();
        if (jt < 63) prefetch(jt + 1, (uint32_t)((jt + 1) & 1) * BUF_SZ);

        // ---- S = Q @ K^T (2-term, term-outside) ----
        float4 acc[8];
        #pragma unroll
        for (int nt = 0; nt < 8; nt++) acc[nt] = make_float4(0.f, 0.f, 0.f, 0.f);

        const int krr = (L & 7) + 8 * ((L >> 4) & 1);
        #pragma unroll
        for (int kt = 0; kt < 4; kt++) {
            const int kcc = kt * 16 + 8 * ((L >> 3) & 1);
            // fp16 term
            #pragma unroll
            for (int p = 0; p < 4; p++) {
                uint32_t f0, f1, f2, f3;
                LDSM4(f0, f1, f2, f3, sb + bo + BKH + swz(16 * p + krr, kcc));
                mma_f16(acc[2 * p],     qfh[kt], f0, f1);
                mma_f16(acc[2 * p + 1], qfh[kt], f2, f3);
            }
            // bf16 residual term (Q-lo fragment from smem)
            uint32_t ql[4];
            LDSM4(ql[0], ql[1], ql[2], ql[3],
                  sb + SQL_OFF + swz(qr, kt * 16 + qcb));
            #pragma unroll
            for (int p = 0; p < 4; p++) {
                uint32_t f0, f1, f2, f3;
                LDSM4(f0, f1, f2, f3, sb + bo + BKB + swz(16 * p + krr, kcc));
                mma_bf16(acc[2 * p],     ql, f0, f1);
                mma_bf16(acc[2 * p + 1], ql, f2, f3);
            }
        }

        // ---- raw scores (pre-mask) ----
        #pragma unroll
        for (int nt = 0; nt < 8; nt++) {
            int j = jt * 64 + nt * 8 + t2 * 2;
            *(float2*)&rawOut[raw0 + j] = make_float2(acc[nt].x, acc[nt].y);
            *(float2*)&rawOut[raw1 + j] = make_float2(acc[nt].z, acc[nt].w);
        }

        // ---- softmax + PV (warp-uniform) ----
        if (jt * 64 <= iwmax) {
            const bool full = (jt * 64 + 63 <= i0 + w * 16);
            float mt0 = -INFINITY, mt1 = -INFINITY;
            #pragma unroll
            for (int nt = 0; nt < 8; nt++) {
                int j = jt * 64 + nt * 8 + t2 * 2;
                float ax = (full || j     <= i_row0) ? acc[nt].x : -INFINITY;
                float ay = (full || j + 1 <= i_row0) ? acc[nt].y : -INFINITY;
                float az = (full || j     <= i_row1) ? acc[nt].z : -INFINITY;
                float aw = (full || j + 1 <= i_row1) ? acc[nt].w : -INFINITY;
                mt0 = fmaxf(mt0, fmaxf(ax, ay));
                mt1 = fmaxf(mt1, fmaxf(az, aw));
            }
            mt0 = fmaxf(mt0, __shfl_xor_sync(0xffffffffu, mt0, 1));
            mt0 = fmaxf(mt0, __shfl_xor_sync(0xffffffffu, mt0, 2));
            mt1 = fmaxf(mt1, __shfl_xor_sync(0xffffffffu, mt1, 1));
            mt1 = fmaxf(mt1, __shfl_xor_sync(0xffffffffu, mt1, 2));

            float mn0 = fmaxf(m0, mt0), mn1 = fmaxf(m1, mt1);
            float sc0 = __expf(m0 - mn0), sc1 = __expf(m1 - mn1);

            float s0 = 0.f, s1 = 0.f;
            uint32_t ph[16], pl[16];
            #pragma unroll
            for (int nt = 0; nt < 8; nt++) {
                int j = jt * 64 + nt * 8 + t2 * 2;
                float px = (full || j     <= i_row0) ? __expf(acc[nt].x - mn0) : 0.f;
                float py = (full || j + 1 <= i_row0) ? __expf(acc[nt].y - mn0) : 0.f;
                float pz = (full || j     <= i_row1) ? __expf(acc[nt].z - mn1) : 0.f;
                float pw = (full || j + 1 <= i_row1) ? __expf(acc[nt].w - mn1) : 0.f;
                s0 += px + py; s1 += pz + pw;
                ph[2 * nt]     = pack_f16(px, py);
                ph[2 * nt + 1] = pack_f16(pz, pw);
                pl[2 * nt]     = pack_bf16(f16_res(px), f16_res(py));
                pl[2 * nt + 1] = pack_bf16(f16_res(pz), f16_res(pw));
            }
            s0 += __shfl_xor_sync(0xffffffffu, s0, 1);
            s0 += __shfl_xor_sync(0xffffffffu, s0, 2);
            s1 += __shfl_xor_sync(0xffffffffu, s1, 1);
            s1 += __shfl_xor_sync(0xffffffffu, s1, 2);
            l0 = l0 * sc0 + s0;  l1 = l1 * sc1 + s1;
            m0 = mn0;  m1 = mn1;

            #pragma unroll
            for (int nt = 0; nt < 8; nt++) {
                O[nt].x *= sc0; O[nt].y *= sc0;
                O[nt].z *= sc1; O[nt].w *= sc1;
            }

            // O += P @ V (2-term, term-outside)
            const int vrr = (L & 7) + 8 * ((L >> 3) & 1);
            const int vcb = 8 * ((L >> 4) & 1);
            #pragma unroll
            for (int ktj = 0; ktj < 4; ktj++) {
                const uint32_t* ahh = &ph[4 * ktj];
                const uint32_t* all = &pl[4 * ktj];
                #pragma unroll
                for (int vp = 0; vp < 4; vp++) {
                    uint32_t f0, f1, f2, f3;
                    LDSM4T(f0, f1, f2, f3,
                           sb + bo + BVH + swz(ktj * 16 + vrr, vp * 16 + vcb));
                    mma_f16(O[2 * vp],     ahh, f0, f1);
                    mma_f16(O[2 * vp + 1], ahh, f2, f3);
                }
                #pragma unroll
                for (int vp = 0; vp < 4; vp++) {
                    uint32_t f0, f1, f2, f3;
                    LDSM4T(f0, f1, f2, f3,
                           sb + bo + BVB + swz(ktj * 16 + vrr, vp * 16 + vcb));
                    mma_bf16(O[2 * vp],     all, f0, f1);
                    mma_bf16(O[2 * vp + 1], all, f2, f3);
                }
            }
        }
        __syncthreads();   // all reads of this buffer done before next overwrite
    }

    // ---- epilogue: normalize, split-store ----
    const float inv0 = 1.f / l0, inv1 = 1.f / l1;
    __half* aoh0 = g_ah + ((size_t)(b * SEQ + i_row0) * DMODEL + h * HD);
    __nv_bfloat16* aol0 = g_al + ((size_t)(b * SEQ + i_row0) * DMODEL + h * HD);
    __half* aoh1 = g_ah + ((size_t)(b * SEQ + i_row1) * DMODEL + h * HD);
    __nv_bfloat16* aol1 = g_al + ((size_t)(b * SEQ + i_row1) * DMODEL + h * HD);
    #pragma unroll
    for (int nt = 0; nt < 8; nt++) {
        int v = nt * 8 + t2 * 2;
        float x0 = O[nt].x * inv0, y0 = O[nt].y * inv0;
        float x1 = O[nt].z * inv1, y1 = O[nt].w * inv1;
        *(uint32_t*)&aoh0[v] = pack_f16(x0, y0);
        *(uint32_t*)&aol0[v] = pack_bf16(f16_res(x0), f16_res(y0));
        *(uint32_t*)&aoh1[v] = pack_f16(x1, y1);
        *(uint32_t*)&aol1[v] = pack_bf16(f16_res(x1), f16_res(y1));
    }
}

// ===========================================================================
// Launch
// ===========================================================================
extern "C" void kernel_launch(void* const* d_in, const int* in_sizes, int n_in,
                              void* d_out, int out_size)
{
    (void)in_sizes; (void)n_in; (void)out_size;
    const float* x  = (const float*)d_in[0];
    const float* Wq = (const float*)d_in[1];
    const float* bq = (const float*)d_in[2];
    const float* Wk = (const float*)d_in[3];
    const float* bk = (const float*)d_in[4];
    const float* Wv = (const float*)d_in[5];
    const float* bv = (const float*)d_in[6];
    const float* Wo = (const float*)d_in[7];
    const float* bo = (const float*)d_in[8];

    float* out = (float*)d_out;
    float* rawOut = out + (size_t)BATCH * SEQ * DMODEL;

    void *qkvh, *qkvl, *xh, *xl, *wh, *wl, *ah, *al;
    cudaGetSymbolAddress(&qkvh, g_qkvh);
    cudaGetSymbolAddress(&qkvl, g_qkvl);
    cudaGetSymbolAddress(&xh, g_xh);
    cudaGetSymbolAddress(&xl, g_xl);
    cudaGetSymbolAddress(&wh, g_wh);
    cudaGetSymbolAddress(&wl, g_wl);
    cudaGetSymbolAddress(&ah, g_ah);
    cudaGetSymbolAddress(&al, g_al);

    __half* whp = (__half*)wh;
    __nv_bfloat16* wlp = (__nv_bfloat16*)wl;

    // splits: x -> fp16 + bf16 residual; W (all 4, fused) -> fp16 + bf16 full
    int n4x = QKV_ELEMS / 4;
    split_kernel<<<n4x / 256, 256>>>(x, (__half*)xh, (__nv_bfloat16*)xl, n4x, 0);
    int n4w = WELEMS / 4;
    split_w_kernel<<<dim3(n4w / 256, 4), 256>>>(Wq, Wk, Wv, Wo, whp, wlp, n4w);

    cudaFuncSetAttribute(gemm_mix, cudaFuncAttributeMaxDynamicSharedMemorySize, GSM);
    cudaFuncSetAttribute(attn_mma, cudaFuncAttributeMaxDynamicSharedMemorySize, SM_ATTN);

    // QKV projections (fused over grid.z)
    gemm_mix<<<dim3(M_ROWS / 128, 4, 3), 256, GSM>>>(
        (const __half*)xh, (const __nv_bfloat16*)xl, whp, wlp,
        bq, bk, bv,
        (__half*)qkvh, (__nv_bfloat16*)qkvl, nullptr, 0);

    // attention (raw scores + softmax + PV)
    attn_mma<<<dim3(SEQ / BR, NH, BATCH), 256, SM_ATTN>>>(rawOut);

    // output projection
    gemm_mix<<<dim3(M_ROWS / 128, 4, 1), 256, GSM>>>(
        (const __half*)ah, (const __nv_bfloat16*)al,
        whp + 3 * WELEMS, wlp + 3 * WELEMS,
        bo, bo, bo, nullptr, nullptr, out, 1);
}

// round 14
// speedup vs baseline: 3.5297x; 1.0016x over previous
#include <cuda_runtime.h>
#include <cuda_bf16.h>
#include <cuda_fp16.h>
#include <math.h>
#include <stdint.h>

// Problem constants
#define BATCH 2
#define SEQ   4096
#define DMODEL 512
#define NH    8
#define HD    64
#define M_ROWS (BATCH*SEQ)          // 8192
#define QKV_ELEMS (BATCH*NH*SEQ*HD) // 4,194,304
#define WELEMS (DMODEL*DMODEL)      // 262,144

// Scratch (device globals)
// "h" = fp16 leading term; "l":
//   A-side tensors (x, Q, P, attnout): bf16 RESIDUAL (v - fp16(v))
//   B-side tensors (W, K, V): bf16 of the FULL value
__device__ __half        g_qkvh[3 * QKV_ELEMS];
__device__ __nv_bfloat16 g_qkvl[3 * QKV_ELEMS];
__device__ __half        g_xh[QKV_ELEMS];
__device__ __nv_bfloat16 g_xl[QKV_ELEMS];
__device__ __half        g_wh[4 * WELEMS];
__device__ __nv_bfloat16 g_wl[4 * WELEMS];
__device__ __half        g_ah[QKV_ELEMS];
__device__ __nv_bfloat16 g_al[QKV_ELEMS];

// ===========================================================================
// Helpers
// ===========================================================================
__device__ __forceinline__ uint32_t smem_u32(const void* p) {
    uint32_t a;
    asm("{ .reg .u64 t; cvta.to.shared.u64 t, %1; cvt.u32.u64 %0, t; }"
        : "=r"(a) : "l"(p));
    return a;
}

__device__ __forceinline__ void mma_bf16(float4& d, const uint32_t* a,
                                         uint32_t b0, uint32_t b1) {
    asm volatile(
        "mma.sync.aligned.m16n8k16.row.col.f32.bf16.bf16.f32 "
        "{%0,%1,%2,%3}, {%4,%5,%6,%7}, {%8,%9}, {%0,%1,%2,%3};"
        : "+f"(d.x), "+f"(d.y), "+f"(d.z), "+f"(d.w)
        : "r"(a[0]), "r"(a[1]), "r"(a[2]), "r"(a[3]), "r"(b0), "r"(b1));
}
__device__ __forceinline__ void mma_f16(float4& d, const uint32_t* a,
                                        uint32_t b0, uint32_t b1) {
    asm volatile(
        "mma.sync.aligned.m16n8k16.row.col.f32.f16.f16.f32 "
        "{%0,%1,%2,%3}, {%4,%5,%6,%7}, {%8,%9}, {%0,%1,%2,%3};"
        : "+f"(d.x), "+f"(d.y), "+f"(d.z), "+f"(d.w)
        : "r"(a[0]), "r"(a[1]), "r"(a[2]), "r"(a[3]), "r"(b0), "r"(b1));
}

#define LDSM4(R0,R1,R2,R3,A) \
    asm volatile("ldmatrix.sync.aligned.m8n8.x4.shared.b16 {%0,%1,%2,%3}, [%4];" \
                 : "=r"(R0),"=r"(R1),"=r"(R2),"=r"(R3) : "r"(A))
#define LDSM4T(R0,R1,R2,R3,A) \
    asm volatile("ldmatrix.sync.aligned.m8n8.x4.trans.shared.b16 {%0,%1,%2,%3}, [%4];" \
                 : "=r"(R0),"=r"(R1),"=r"(R2),"=r"(R3) : "r"(A))

#define CP_ASYNC16(dst, src) \
    asm volatile("cp.async.cg.shared.global [%0], [%1], 16;" :: "r"(dst), "l"(src))
#define CP_COMMIT() asm volatile("cp.async.commit_group;" ::: "memory")
#define CP_WAIT0()  asm volatile("cp.async.wait_group 0;" ::: "memory")

__device__ __forceinline__ uint32_t pack_bf16(float lo, float hi) {
    uint32_t d;
    asm("cvt.rn.bf16x2.f32 %0, %1, %2;" : "=r"(d) : "f"(hi), "f"(lo));
    return d;
}
__device__ __forceinline__ uint32_t pack_f16(float lo, float hi) {
    uint32_t d;
    asm("cvt.rn.f16x2.f32 %0, %1, %2;" : "=r"(d) : "f"(hi), "f"(lo));
    return d;
}
__device__ __forceinline__ float f16_res(float x) {
    return x - __half2float(__float2half_rn(x));
}

// swizzled byte offset, [rows][64] 16-bit tile, 128B pitch
__device__ __forceinline__ uint32_t swz(int r, int c) {
    return (uint32_t)(r * 128 + ((((c >> 3) ^ r) & 7) << 4) + (c & 7) * 2);
}
// swizzled byte offset, [rows][128] 16-bit tile, 256B pitch
__device__ __forceinline__ uint32_t swz256(int r, int c) {
    uint32_t seg = (uint32_t)(c >> 3);
    seg = (seg & 8u) | ((seg ^ (uint32_t)(r & 7)) & 7u);
    return (uint32_t)(r * 256) + seg * 16 + (uint32_t)((c & 7) * 2);
}

// ===========================================================================
// splits: fp32 -> fp16 hi + bf16 (residual or full)
// ===========================================================================
__global__ void split_kernel(const float* __restrict__ s,
                             __half* __restrict__ dh,
                             __nv_bfloat16* __restrict__ dl, int n4, int full)
{
    int i = blockIdx.x * blockDim.x + threadIdx.x;
    if (i >= n4) return;
    float4 v = ((const float4*)s)[i];
    ((uint2*)dh)[i] = make_uint2(pack_f16(v.x, v.y), pack_f16(v.z, v.w));
    if (full) {
        ((uint2*)dl)[i] = make_uint2(pack_bf16(v.x, v.y), pack_bf16(v.z, v.w));
    } else {
        ((uint2*)dl)[i] = make_uint2(pack_bf16(f16_res(v.x), f16_res(v.y)),
                                     pack_bf16(f16_res(v.z), f16_res(v.w)));
    }
}

// fused weight split: 4 matrices, blockIdx.y selects
__global__ void split_w_kernel(const float* __restrict__ w0,
                               const float* __restrict__ w1,
                               const float* __restrict__ w2,
                               const float* __restrict__ w3,
                               __half* __restrict__ dh,
                               __nv_bfloat16* __restrict__ dl, int n4)
{
    int i = blockIdx.x * blockDim.x + threadIdx.x;
    if (i >= n4) return;
    int m = blockIdx.y;
    const float* s = (m == 0) ? w0 : (m == 1) ? w1 : (m == 2) ? w2 : w3;
    float4 v = ((const float4*)s)[i];
    size_t o = (size_t)m * (WELEMS / 4) + i;
    ((uint2*)dh)[o] = make_uint2(pack_f16(v.x, v.y), pack_f16(v.z, v.w));
    ((uint2*)dl)[o] = make_uint2(pack_bf16(v.x, v.y), pack_bf16(v.z, v.w));
}

// ===========================================================================
// 2-term mixed GEMM: C[8192 x 512] = A * W + bias
// ===========================================================================
#define GA_H 0
#define GA_L 16384
#define GB_H 32768
#define GB_B 49152
#define GSM  65536

__global__ __launch_bounds__(256) void gemm_mix(
    const __half* __restrict__ Ah, const __nv_bfloat16* __restrict__ Al,
    const __half* __restrict__ Wh, const __nv_bfloat16* __restrict__ Wl,
    const float* __restrict__ bias0, const float* __restrict__ bias1,
    const float* __restrict__ bias2,
    __half* __restrict__ Oh, __nv_bfloat16* __restrict__ Ol,
    float* __restrict__ Ofp, int mode)
{
    extern __shared__ char smem[];
    const uint32_t sb = smem_u32(smem);
    const int tid = threadIdx.x, w = tid >> 5, L = tid & 31;
    const int t2 = L & 3;
    const int bm = blockIdx.x, bn = blockIdx.y, mat = blockIdx.z;
    const float* bias = (mat == 0) ? bias0 : (mat == 1) ? bias1 : bias2;
    const __half* Whm = Wh + (size_t)mat * WELEMS;
    const __nv_bfloat16* Wlm = Wl + (size_t)mat * WELEMS;

    const int wm = (w >> 2) * 64, wn = (w & 3) * 32;
    float4 acc[4][4] = {};

    for (int k0 = 0; k0 < 512; k0 += 64) {
        __syncthreads();
        #pragma unroll
        for (int q = 0; q < 4; q++) {
            int i = tid + q * 256;
            int r = i >> 3, c = (i & 7) * 8;
            uint32_t off = swz(r, c);
            *(uint4*)(smem + GA_H + off) =
                *(const uint4*)&Ah[(size_t)(bm * 128 + r) * 512 + k0 + c];
            *(uint4*)(smem + GA_L + off) =
                *(const uint4*)&Al[(size_t)(bm * 128 + r) * 512 + k0 + c];
        }
        #pragma unroll
        for (int q = 0; q < 4; q++) {
            int i = tid + q * 256;
            int r = i >> 4, c = (i & 15) * 8;
            uint32_t off = swz256(r, c);
            *(uint4*)(smem + GB_H + off) =
                *(const uint4*)&Whm[(size_t)(k0 + r) * 512 + bn * 128 + c];
            *(uint4*)(smem + GB_B + off) =
                *(const uint4*)&Wlm[(size_t)(k0 + r) * 512 + bn * 128 + c];
        }
        __syncthreads();

        #pragma unroll
        for (int kt = 0; kt < 4; kt++) {
            uint32_t ah[4][4], al[4][4], bh[2][4], bb[2][4];
            int ar = (L & 7) + 8 * ((L >> 3) & 1);
            int ac = kt * 16 + 8 * ((L >> 4) & 1);
            #pragma unroll
            for (int mi = 0; mi < 4; mi++) {
                LDSM4(ah[mi][0], ah[mi][1], ah[mi][2], ah[mi][3],
                      sb + GA_H + swz(wm + mi * 16 + ar, ac));
                LDSM4(al[mi][0], al[mi][1], al[mi][2], al[mi][3],
                      sb + GA_L + swz(wm + mi * 16 + ar, ac));
            }
            int br = kt * 16 + (L & 7) + 8 * ((L >> 3) & 1);
            int bc = 8 * ((L >> 4) & 1);
            #pragma unroll
            for (int nj = 0; nj < 2; nj++) {
                LDSM4T(bh[nj][0], bh[nj][1], bh[nj][2], bh[nj][3],
                       sb + GB_H + swz256(br, wn + nj * 16 + bc));
                LDSM4T(bb[nj][0], bb[nj][1], bb[nj][2], bb[nj][3],
                       sb + GB_B + swz256(br, wn + nj * 16 + bc));
            }
            #pragma unroll
            for (int mi = 0; mi < 4; mi++)
                #pragma unroll
                for (int nj = 0; nj < 2; nj++) {
                    mma_f16(acc[mi][2 * nj],     ah[mi], bh[nj][0], bh[nj][1]);
                    mma_f16(acc[mi][2 * nj + 1], ah[mi], bh[nj][2], bh[nj][3]);
                }
            #pragma unroll
            for (int mi = 0; mi < 4; mi++)
                #pragma unroll
                for (int nj = 0; nj < 2; nj++) {
                    mma_bf16(acc[mi][2 * nj],     al[mi], bb[nj][0], bb[nj][1]);
                    mma_bf16(acc[mi][2 * nj + 1], al[mi], bb[nj][2], bb[nj][3]);
                }
        }
    }

    const bool isQ = (mode == 0 && mat == 0);
    const float scl = isQ ? 0.125f : 1.f;
    #pragma unroll
    for (int mi = 0; mi < 4; mi++) {
        #pragma unroll
        for (int nq = 0; nq < 4; nq++) {
            int r0 = bm * 128 + wm + mi * 16 + (L >> 2);
            int r1 = r0 + 8;
            int n = bn * 128 + wn + nq * 8 + t2 * 2;
            float bx = bias[n], by = bias[n + 1];
            float4 c = acc[mi][nq];
            float cx = (c.x + bx) * scl, cy = (c.y + by) * scl;
            float cz = (c.z + bx) * scl, cw = (c.w + by) * scl;
            if (mode == 0) {
                int hh = n >> 6, d = n & 63;
                int b0 = r0 >> 12, s0 = r0 & (SEQ - 1);
                int b1 = r1 >> 12, s1 = r1 & (SEQ - 1);
                size_t i0 = (size_t)mat * QKV_ELEMS +
                            (((size_t)(b0 * NH + hh)) * SEQ + s0) * HD + d;
                size_t i1 = (size_t)mat * QKV_ELEMS +
                            (((size_t)(b1 * NH + hh)) * SEQ + s1) * HD + d;
                *(uint32_t*)&Oh[i0] = pack_f16(cx, cy);
                *(uint32_t*)&Oh[i1] = pack_f16(cz, cw);
                if (isQ) {
                    *(uint32_t*)&Ol[i0] = pack_bf16(f16_res(cx), f16_res(cy));
                    *(uint32_t*)&Ol[i1] = pack_bf16(f16_res(cz), f16_res(cw));
                } else {
                    *(uint32_t*)&Ol[i0] = pack_bf16(cx, cy);
                    *(uint32_t*)&Ol[i1] = pack_bf16(cz, cw);
                }
            } else {
                *(float2*)&Ofp[(size_t)r0 * 512 + n] = make_float2(cx, cy);
                *(float2*)&Ofp[(size_t)r1 * 512 + n] = make_float2(cz, cw);
            }
        }
    }
}

// ===========================================================================
// Attention, 2-term mixed: 2 CTAs/SM, cp.async K/V, Q-lo in smem.
// R13: raw scores staged through warp-private smem -> coalesced STG.128
// (2 full 256B row segments per instruction instead of 8x32B sectors).
// ===========================================================================
#define BR 128
#define BC 64

#define BUF_SZ 32768
#define BKH 0
#define BKB 8192
#define BVH 16384
#define BVB 24576
#define SQL_OFF 65536          // 16KB QL region (128 rows x 128B pitch)
#define SRAW_OFF 81920         // raw staging: 8 warps x 8 rows x 72 f32
#define SRAW_WARP 2304         // 8 * 72 * 4 bytes
#define SRAW_PITCH 288         // 72 f32, in bytes per row
#define SM_ATTN 100352         // 81920 + 8*2304

__global__ __launch_bounds__(256, 2) void attn_mma(float* __restrict__ rawOut)
{
    extern __shared__ char smem[];
    const uint32_t sb = smem_u32(smem);
    const int tid = threadIdx.x, w = tid >> 5, L = tid & 31;
    const int t2 = L & 3;
    const int it = (int)(gridDim.x - 1 - blockIdx.x);   // heavy blocks first
    const int i0 = it * BR, h = blockIdx.y, b = blockIdx.z;

    const size_t headOff = (size_t)(b * NH + h) * SEQ * HD;
    const __half*        Qh = g_qkvh + headOff + (size_t)i0 * HD;
    const __nv_bfloat16* Ql = g_qkvl + headOff + (size_t)i0 * HD;
    const __half*        Kh = g_qkvh + QKV_ELEMS + headOff;
    const __nv_bfloat16* Kb = g_qkvl + QKV_ELEMS + headOff;
    const __half*        Vh = g_qkvh + 2 * QKV_ELEMS + headOff;
    const __nv_bfloat16* Vb = g_qkvl + 2 * QKV_ELEMS + headOff;

    // ---- stage Q: hi into buffer area (temp), lo into dedicated region ----
    for (int i = tid; i < 1024; i += 256) {
        int r = i >> 3, c = (i & 7) * 8;
        uint32_t off = swz(r, c);
        *(uint4*)(smem + off)           = *(const uint4*)&Qh[(size_t)r * HD + c];
        *(uint4*)(smem + SQL_OFF + off) = *(const uint4*)&Ql[(size_t)r * HD + c];
    }
    __syncthreads();
    uint32_t qfh[4][4];
    const int qr = w * 16 + (L & 7) + 8 * ((L >> 3) & 1);
    const int qcb = 8 * ((L >> 4) & 1);
    #pragma unroll
    for (int kt = 0; kt < 4; kt++) {
        LDSM4(qfh[kt][0], qfh[kt][1], qfh[kt][2], qfh[kt][3],
              sb + swz(qr, kt * 16 + qcb));
    }
    __syncthreads();   // qfh captured; buffer area free

    const int i_row0 = i0 + w * 16 + (L >> 2);
    const int i_row1 = i_row0 + 8;
    const int iwmax = i0 + w * 16 + 15;
    const int lastCausal = 2 * it + 1;
    // base of this warp's 16 raw rows
    const size_t rawWarpBase = ((size_t)(h * BATCH + b) * SEQ + i0 + w * 16) * SEQ;
    char* const stg = smem + SRAW_OFF + w * SRAW_WARP;   // warp staging region

    float4 O[8];
    #pragma unroll
    for (int nt = 0; nt < 8; nt++) O[nt] = make_float4(0.f, 0.f, 0.f, 0.f);
    float m0 = -INFINITY, m1 = -INFINITY, l0 = 0.f, l1 = 0.f;

    const int pr = tid >> 3, pc = (tid & 7) * 8;

    // cp.async prefetch of one j-tile into buffer bo
    auto prefetch = [&](int jt, uint32_t bo) {
        const size_t tOff = (size_t)jt * BC * HD;
        const bool causal = (jt <= lastCausal);
        #pragma unroll
        for (int q = 0; q < 2; q++) {
            int r = pr + q * 32;
            uint32_t off = bo + swz(r, pc);
            CP_ASYNC16(sb + BKH + off, &Kh[tOff + (size_t)r * HD + pc]);
            CP_ASYNC16(sb + BKB + off, &Kb[tOff + (size_t)r * HD + pc]);
            if (causal) {
                CP_ASYNC16(sb + BVH + off, &Vh[tOff + (size_t)r * HD + pc]);
                CP_ASYNC16(sb + BVB + off, &Vb[tOff + (size_t)r * HD + pc]);
            }
        }
        CP_COMMIT();
    };

    prefetch(0, 0);

    for (int jt = 0; jt < 64; jt++) {
        const uint32_t bo = (uint32_t)(jt & 1) * BUF_SZ;
        CP_WAIT0();
        __syncthreads();
        if (jt < 63) prefetch(jt + 1, (uint32_t)((jt + 1) & 1) * BUF_SZ);

        // ---- S = Q @ K^T (2-term, term-outside) ----
        float4 acc[8];
        #pragma unroll
        for (int nt = 0; nt < 8; nt++) acc[nt] = make_float4(0.f, 0.f, 0.f, 0.f);

        const int krr = (L & 7) + 8 * ((L >> 4) & 1);
        #pragma unroll
        for (int kt = 0; kt < 4; kt++) {
            const int kcc = kt * 16 + 8 * ((L >> 3) & 1);
            // fp16 term
            #pragma unroll
            for (int p = 0; p < 4; p++) {
                uint32_t f0, f1, f2, f3;
                LDSM4(f0, f1, f2, f3, sb + bo + BKH + swz(16 * p + krr, kcc));
                mma_f16(acc[2 * p],     qfh[kt], f0, f1);
                mma_f16(acc[2 * p + 1], qfh[kt], f2, f3);
            }
            // bf16 residual term (Q-lo fragment from smem)
            uint32_t ql[4];
            LDSM4(ql[0], ql[1], ql[2], ql[3],
                  sb + SQL_OFF + swz(qr, kt * 16 + qcb));
            #pragma unroll
            for (int p = 0; p < 4; p++) {
                uint32_t f0, f1, f2, f3;
                LDSM4(f0, f1, f2, f3, sb + bo + BKB + swz(16 * p + krr, kcc));
                mma_bf16(acc[2 * p],     ql, f0, f1);
                mma_bf16(acc[2 * p + 1], ql, f2, f3);
            }
        }

        // ---- raw scores (pre-mask), coalesced via warp smem staging ----
        // pass 0: rows w*16+0..7 (acc .x/.y); pass 1: rows w*16+8..15 (.z/.w)
        {
            const int srow = (L >> 4) & 1;            // half-warp row select
            const int scol = (L & 15) * 16;           // float4 col in bytes
            const int lrow = L >> 2;                  // staging row 0..7
            #pragma unroll
            for (int pass = 0; pass < 2; pass++) {
                #pragma unroll
                for (int nt = 0; nt < 8; nt++) {
                    float2 v = (pass == 0)
                        ? make_float2(acc[nt].x, acc[nt].y)
                        : make_float2(acc[nt].z, acc[nt].w);
                    *(float2*)(stg + lrow * SRAW_PITCH + (nt * 8 + t2 * 2) * 4) = v;
                }
                __syncwarp();
                #pragma unroll
                for (int i2 = 0; i2 < 4; i2++) {
                    int sr = 2 * i2 + srow;           // staging row 0..7
                    float4 v = *(float4*)(stg + sr * SRAW_PITCH + scol);
                    *(float4*)&rawOut[rawWarpBase + (size_t)(pass * 8 + sr) * SEQ
                                      + jt * 64 + (L & 15) * 4] = v;
                }
                __syncwarp();
            }
        }

        // ---- softmax + PV (warp-uniform) ----
        if (jt * 64 <= iwmax) {
            const bool full = (jt * 64 + 63 <= i0 + w * 16);
            float mt0 = -INFINITY, mt1 = -INFINITY;
            #pragma unroll
            for (int nt = 0; nt < 8; nt++) {
                int j = jt * 64 + nt * 8 + t2 * 2;
                float ax = (full || j     <= i_row0) ? acc[nt].x : -INFINITY;
                float ay = (full || j + 1 <= i_row0) ? acc[nt].y : -INFINITY;
                float az = (full || j     <= i_row1) ? acc[nt].z : -INFINITY;
                float aw = (full || j + 1 <= i_row1) ? acc[nt].w : -INFINITY;
                mt0 = fmaxf(mt0, fmaxf(ax, ay));
                mt1 = fmaxf(mt1, fmaxf(az, aw));
            }
            mt0 = fmaxf(mt0, __shfl_xor_sync(0xffffffffu, mt0, 1));
            mt0 = fmaxf(mt0, __shfl_xor_sync(0xffffffffu, mt0, 2));
            mt1 = fmaxf(mt1, __shfl_xor_sync(0xffffffffu, mt1, 1));
            mt1 = fmaxf(mt1, __shfl_xor_sync(0xffffffffu, mt1, 2));

            float mn0 = fmaxf(m0, mt0), mn1 = fmaxf(m1, mt1);
            float sc0 = __expf(m0 - mn0), sc1 = __expf(m1 - mn1);

            float s0 = 0.f, s1 = 0.f;
            uint32_t ph[16], pl[16];
            #pragma unroll
            for (int nt = 0; nt < 8; nt++) {
                int j = jt * 64 + nt * 8 + t2 * 2;
                float px = (full || j     <= i_row0) ? __expf(acc[nt].x - mn0) : 0.f;
                float py = (full || j + 1 <= i_row0) ? __expf(acc[nt].y - mn0) : 0.f;
                float pz = (full || j     <= i_row1) ? __expf(acc[nt].z - mn1) : 0.f;
                float pw = (full || j + 1 <= i_row1) ? __expf(acc[nt].w - mn1) : 0.f;
                s0 += px + py; s1 += pz + pw;
                ph[2 * nt]     = pack_f16(px, py);
                ph[2 * nt + 1] = pack_f16(pz, pw);
                pl[2 * nt]     = pack_bf16(f16_res(px), f16_res(py));
                pl[2 * nt + 1] = pack_bf16(f16_res(pz), f16_res(pw));
            }
            s0 += __shfl_xor_sync(0xffffffffu, s0, 1);
            s0 += __shfl_xor_sync(0xffffffffu, s0, 2);
            s1 += __shfl_xor_sync(0xffffffffu, s1, 1);
            s1 += __shfl_xor_sync(0xffffffffu, s1, 2);
            l0 = l0 * sc0 + s0;  l1 = l1 * sc1 + s1;
            m0 = mn0;  m1 = mn1;

            #pragma unroll
            for (int nt = 0; nt < 8; nt++) {
                O[nt].x *= sc0; O[nt].y *= sc0;
                O[nt].z *= sc1; O[nt].w *= sc1;
            }

            // O += P @ V (2-term, term-outside)
            const int vrr = (L & 7) + 8 * ((L >> 3) & 1);
            const int vcb = 8 * ((L >> 4) & 1);
            #pragma unroll
            for (int ktj = 0; ktj < 4; ktj++) {
                const uint32_t* ahh = &ph[4 * ktj];
                const uint32_t* all = &pl[4 * ktj];
                #pragma unroll
                for (int vp = 0; vp < 4; vp++) {
                    uint32_t f0, f1, f2, f3;
                    LDSM4T(f0, f1, f2, f3,
                           sb + bo + BVH + swz(ktj * 16 + vrr, vp * 16 + vcb));
                    mma_f16(O[2 * vp],     ahh, f0, f1);
                    mma_f16(O[2 * vp + 1], ahh, f2, f3);
                }
                #pragma unroll
                for (int vp = 0; vp < 4; vp++) {
                    uint32_t f0, f1, f2, f3;
                    LDSM4T(f0, f1, f2, f3,
                           sb + bo + BVB + swz(ktj * 16 + vrr, vp * 16 + vcb));
                    mma_bf16(O[2 * vp],     all, f0, f1);
                    mma_bf16(O[2 * vp + 1], all, f2, f3);
                }
            }
        }
        __syncthreads();   // all reads of this buffer done before next overwrite
    }

    // ---- epilogue: normalize, split-store ----
    const float inv0 = 1.f / l0, inv1 = 1.f / l1;
    __half* aoh0 = g_ah + ((size_t)(b * SEQ + i_row0) * DMODEL + h * HD);
    __nv_bfloat16* aol0 = g_al + ((size_t)(b * SEQ + i_row0) * DMODEL + h * HD);
    __half* aoh1 = g_ah + ((size_t)(b * SEQ + i_row1) * DMODEL + h * HD);
    __nv_bfloat16* aol1 = g_al + ((size_t)(b * SEQ + i_row1) * DMODEL + h * HD);
    #pragma unroll
    for (int nt = 0; nt < 8; nt++) {
        int v = nt * 8 + t2 * 2;
        float x0 = O[nt].x * inv0, y0 = O[nt].y * inv0;
        float x1 = O[nt].z * inv1, y1 = O[nt].w * inv1;
        *(uint32_t*)&aoh0[v] = pack_f16(x0, y0);
        *(uint32_t*)&aol0[v] = pack_bf16(f16_res(x0), f16_res(y0));
        *(uint32_t*)&aoh1[v] = pack_f16(x1, y1);
        *(uint32_t*)&aol1[v] = pack_bf16(f16_res(x1), f16_res(y1));
    }
}

// ===========================================================================
// Launch
// ===========================================================================
extern "C" void kernel_launch(void* const* d_in, const int* in_sizes, int n_in,
                              void* d_out, int out_size)
{
    (void)in_sizes; (void)n_in; (void)out_size;
    const float* x  = (const float*)d_in[0];
    const float* Wq = (const float*)d_in[1];
    const float* bq = (const float*)d_in[2];
    const float* Wk = (const float*)d_in[3];
    const float* bk = (const float*)d_in[4];
    const float* Wv = (const float*)d_in[5];
    const float* bv = (const float*)d_in[6];
    const float* Wo = (const float*)d_in[7];
    const float* bo = (const float*)d_in[8];

    float* out = (float*)d_out;
    float* rawOut = out + (size_t)BATCH * SEQ * DMODEL;

    void *qkvh, *qkvl, *xh, *xl, *wh, *wl, *ah, *al;
    cudaGetSymbolAddress(&qkvh, g_qkvh);
    cudaGetSymbolAddress(&qkvl, g_qkvl);
    cudaGetSymbolAddress(&xh, g_xh);
    cudaGetSymbolAddress(&xl, g_xl);
    cudaGetSymbolAddress(&wh, g_wh);
    cudaGetSymbolAddress(&wl, g_wl);
    cudaGetSymbolAddress(&ah, g_ah);
    cudaGetSymbolAddress(&al, g_al);

    __half* whp = (__half*)wh;
    __nv_bfloat16* wlp = (__nv_bfloat16*)wl;

    // splits: x -> fp16 + bf16 residual; W (all 4, fused) -> fp16 + bf16 full
    int n4x = QKV_ELEMS / 4;
    split_kernel<<<n4x / 256, 256>>>(x, (__half*)xh, (__nv_bfloat16*)xl, n4x, 0);
    int n4w = WELEMS / 4;
    split_w_kernel<<<dim3(n4w / 256, 4), 256>>>(Wq, Wk, Wv, Wo, whp, wlp, n4w);

    cudaFuncSetAttribute(gemm_mix, cudaFuncAttributeMaxDynamicSharedMemorySize, GSM);
    cudaFuncSetAttribute(attn_mma, cudaFuncAttributeMaxDynamicSharedMemorySize, SM_ATTN);

    // QKV projections (fused over grid.z)
    gemm_mix<<<dim3(M_ROWS / 128, 4, 3), 256, GSM>>>(
        (const __half*)xh, (const __nv_bfloat16*)xl, whp, wlp,
        bq, bk, bv,
        (__half*)qkvh, (__nv_bfloat16*)qkvl, nullptr, 0);

    // attention (raw scores + softmax + PV)
    attn_mma<<<dim3(SEQ / BR, NH, BATCH), 256, SM_ATTN>>>(rawOut);

    // output projection
    gemm_mix<<<dim3(M_ROWS / 128, 4, 1), 256, GSM>>>(
        (const __half*)ah, (const __nv_bfloat16*)al,
        whp + 3 * WELEMS, wlp + 3 * WELEMS,
        bo, bo, bo, nullptr, nullptr, out, 1);
}

// round 17
// speedup vs baseline: 4.0324x; 1.1424x over previous
#include <cuda_runtime.h>
#include <cuda_bf16.h>
#include <cuda_fp16.h>
#include <math.h>
#include <stdint.h>

// Problem constants
#define BATCH 2
#define SEQ   4096
#define DMODEL 512
#define NH    8
#define HD    64
#define M_ROWS (BATCH*SEQ)          // 8192
#define QKV_ELEMS (BATCH*NH*SEQ*HD) // 4,194,304
#define WELEMS (DMODEL*DMODEL)      // 262,144

// Scratch (device globals)
// "h" = fp16 leading term; "l":
//   A-side tensors (x, Q, attnout): bf16 RESIDUAL (v - fp16(v))
//   B-side tensors (W, K, V): bf16 of the FULL value
__device__ __half        g_qkvh[3 * QKV_ELEMS];
__device__ __nv_bfloat16 g_qkvl[3 * QKV_ELEMS];
__device__ __half        g_xh[QKV_ELEMS];
__device__ __nv_bfloat16 g_xl[QKV_ELEMS];
__device__ __half        g_wh[4 * WELEMS];
__device__ __nv_bfloat16 g_wl[4 * WELEMS];
__device__ __half        g_ah[QKV_ELEMS];
__device__ __nv_bfloat16 g_al[QKV_ELEMS];

// ===========================================================================
// Helpers
// ===========================================================================
__device__ __forceinline__ uint32_t smem_u32(const void* p) {
    uint32_t a;
    asm("{ .reg .u64 t; cvta.to.shared.u64 t, %1; cvt.u32.u64 %0, t; }"
        : "=r"(a) : "l"(p));
    return a;
}

__device__ __forceinline__ void mma_bf16(float4& d, const uint32_t* a,
                                         uint32_t b0, uint32_t b1) {
    asm volatile(
        "mma.sync.aligned.m16n8k16.row.col.f32.bf16.bf16.f32 "
        "{%0,%1,%2,%3}, {%4,%5,%6,%7}, {%8,%9}, {%0,%1,%2,%3};"
        : "+f"(d.x), "+f"(d.y), "+f"(d.z), "+f"(d.w)
        : "r"(a[0]), "r"(a[1]), "r"(a[2]), "r"(a[3]), "r"(b0), "r"(b1));
}
__device__ __forceinline__ void mma_f16(float4& d, const uint32_t* a,
                                        uint32_t b0, uint32_t b1) {
    asm volatile(
        "mma.sync.aligned.m16n8k16.row.col.f32.f16.f16.f32 "
        "{%0,%1,%2,%3}, {%4,%5,%6,%7}, {%8,%9}, {%0,%1,%2,%3};"
        : "+f"(d.x), "+f"(d.y), "+f"(d.z), "+f"(d.w)
        : "r"(a[0]), "r"(a[1]), "r"(a[2]), "r"(a[3]), "r"(b0), "r"(b1));
}

#define LDSM4(R0,R1,R2,R3,A) \
    asm volatile("ldmatrix.sync.aligned.m8n8.x4.shared.b16 {%0,%1,%2,%3}, [%4];" \
                 : "=r"(R0),"=r"(R1),"=r"(R2),"=r"(R3) : "r"(A))
#define LDSM4T(R0,R1,R2,R3,A) \
    asm volatile("ldmatrix.sync.aligned.m8n8.x4.trans.shared.b16 {%0,%1,%2,%3}, [%4];" \
                 : "=r"(R0),"=r"(R1),"=r"(R2),"=r"(R3) : "r"(A))

#define CP_ASYNC16(dst, src) \
    asm volatile("cp.async.cg.shared.global [%0], [%1], 16;" :: "r"(dst), "l"(src))
#define CP_COMMIT() asm volatile("cp.async.commit_group;" ::: "memory")
#define CP_WAIT0()  asm volatile("cp.async.wait_group 0;" ::: "memory")

__device__ __forceinline__ uint32_t pack_bf16(float lo, float hi) {
    uint32_t d;
    asm("cvt.rn.bf16x2.f32 %0, %1, %2;" : "=r"(d) : "f"(hi), "f"(lo));
    return d;
}
__device__ __forceinline__ uint32_t pack_f16(float lo, float hi) {
    uint32_t d;
    asm("cvt.rn.f16x2.f32 %0, %1, %2;" : "=r"(d) : "f"(hi), "f"(lo));
    return d;
}
__device__ __forceinline__ float f16_res(float x) {
    return x - __half2float(__float2half_rn(x));
}

// swizzled byte offset, [rows][64] 16-bit tile, 128B pitch
__device__ __forceinline__ uint32_t swz(int r, int c) {
    return (uint32_t)(r * 128 + ((((c >> 3) ^ r) & 7) << 4) + (c & 7) * 2);
}
// swizzled byte offset, [rows][128] 16-bit tile, 256B pitch
__device__ __forceinline__ uint32_t swz256(int r, int c) {
    uint32_t seg = (uint32_t)(c >> 3);
    seg = (seg & 8u) | ((seg ^ (uint32_t)(r & 7)) & 7u);
    return (uint32_t)(r * 256) + seg * 16 + (uint32_t)((c & 7) * 2);
}

// ===========================================================================
// splits: fp32 -> fp16 hi + bf16 (residual or full)
// ===========================================================================
__global__ void split_kernel(const float* __restrict__ s,
                             __half* __restrict__ dh,
                             __nv_bfloat16* __restrict__ dl, int n4, int full)
{
    int i = blockIdx.x * blockDim.x + threadIdx.x;
    if (i >= n4) return;
    float4 v = ((const float4*)s)[i];
    ((uint2*)dh)[i] = make_uint2(pack_f16(v.x, v.y), pack_f16(v.z, v.w));
    if (full) {
        ((uint2*)dl)[i] = make_uint2(pack_bf16(v.x, v.y), pack_bf16(v.z, v.w));
    } else {
        ((uint2*)dl)[i] = make_uint2(pack_bf16(f16_res(v.x), f16_res(v.y)),
                                     pack_bf16(f16_res(v.z), f16_res(v.w)));
    }
}

// fused weight split: 4 matrices, blockIdx.y selects
__global__ void split_w_kernel(const float* __restrict__ w0,
                               const float* __restrict__ w1,
                               const float* __restrict__ w2,
                               const float* __restrict__ w3,
                               __half* __restrict__ dh,
                               __nv_bfloat16* __restrict__ dl, int n4)
{
    int i = blockIdx.x * blockDim.x + threadIdx.x;
    if (i >= n4) return;
    int m = blockIdx.y;
    const float* s = (m == 0) ? w0 : (m == 1) ? w1 : (m == 2) ? w2 : w3;
    float4 v = ((const float4*)s)[i];
    size_t o = (size_t)m * (WELEMS / 4) + i;
    ((uint2*)dh)[o] = make_uint2(pack_f16(v.x, v.y), pack_f16(v.z, v.w));
    ((uint2*)dl)[o] = make_uint2(pack_bf16(v.x, v.y), pack_bf16(v.z, v.w));
}

// ===========================================================================
// 2-term mixed GEMM: C[8192 x 512] = A * W + bias
// ===========================================================================
#define GA_H 0
#define GA_L 16384
#define GB_H 32768
#define GB_B 49152
#define GSM  65536

__global__ __launch_bounds__(256) void gemm_mix(
    const __half* __restrict__ Ah, const __nv_bfloat16* __restrict__ Al,
    const __half* __restrict__ Wh, const __nv_bfloat16* __restrict__ Wl,
    const float* __restrict__ bias0, const float* __restrict__ bias1,
    const float* __restrict__ bias2,
    __half* __restrict__ Oh, __nv_bfloat16* __restrict__ Ol,
    float* __restrict__ Ofp, int mode)
{
    extern __shared__ char smem[];
    const uint32_t sb = smem_u32(smem);
    const int tid = threadIdx.x, w = tid >> 5, L = tid & 31;
    const int t2 = L & 3;
    const int bm = blockIdx.x, bn = blockIdx.y, mat = blockIdx.z;
    const float* bias = (mat == 0) ? bias0 : (mat == 1) ? bias1 : bias2;
    const __half* Whm = Wh + (size_t)mat * WELEMS;
    const __nv_bfloat16* Wlm = Wl + (size_t)mat * WELEMS;

    const int wm = (w >> 2) * 64, wn = (w & 3) * 32;
    float4 acc[4][4] = {};

    for (int k0 = 0; k0 < 512; k0 += 64) {
        __syncthreads();
        #pragma unroll
        for (int q = 0; q < 4; q++) {
            int i = tid + q * 256;
            int r = i >> 3, c = (i & 7) * 8;
            uint32_t off = swz(r, c);
            *(uint4*)(smem + GA_H + off) =
                *(const uint4*)&Ah[(size_t)(bm * 128 + r) * 512 + k0 + c];
            *(uint4*)(smem + GA_L + off) =
                *(const uint4*)&Al[(size_t)(bm * 128 + r) * 512 + k0 + c];
        }
        #pragma unroll
        for (int q = 0; q < 4; q++) {
            int i = tid + q * 256;
            int r = i >> 4, c = (i & 15) * 8;
            uint32_t off = swz256(r, c);
            *(uint4*)(smem + GB_H + off) =
                *(const uint4*)&Whm[(size_t)(k0 + r) * 512 + bn * 128 + c];
            *(uint4*)(smem + GB_B + off) =
                *(const uint4*)&Wlm[(size_t)(k0 + r) * 512 + bn * 128 + c];
        }
        __syncthreads();

        #pragma unroll
        for (int kt = 0; kt < 4; kt++) {
            uint32_t ah[4][4], al[4][4], bh[2][4], bb[2][4];
            int ar = (L & 7) + 8 * ((L >> 3) & 1);
            int ac = kt * 16 + 8 * ((L >> 4) & 1);
            #pragma unroll
            for (int mi = 0; mi < 4; mi++) {
                LDSM4(ah[mi][0], ah[mi][1], ah[mi][2], ah[mi][3],
                      sb + GA_H + swz(wm + mi * 16 + ar, ac));
                LDSM4(al[mi][0], al[mi][1], al[mi][2], al[mi][3],
                      sb + GA_L + swz(wm + mi * 16 + ar, ac));
            }
            int br = kt * 16 + (L & 7) + 8 * ((L >> 3) & 1);
            int bc = 8 * ((L >> 4) & 1);
            #pragma unroll
            for (int nj = 0; nj < 2; nj++) {
                LDSM4T(bh[nj][0], bh[nj][1], bh[nj][2], bh[nj][3],
                       sb + GB_H + swz256(br, wn + nj * 16 + bc));
                LDSM4T(bb[nj][0], bb[nj][1], bb[nj][2], bb[nj][3],
                       sb + GB_B + swz256(br, wn + nj * 16 + bc));
            }
            #pragma unroll
            for (int mi = 0; mi < 4; mi++)
                #pragma unroll
                for (int nj = 0; nj < 2; nj++) {
                    mma_f16(acc[mi][2 * nj],     ah[mi], bh[nj][0], bh[nj][1]);
                    mma_f16(acc[mi][2 * nj + 1], ah[mi], bh[nj][2], bh[nj][3]);
                }
            #pragma unroll
            for (int mi = 0; mi < 4; mi++)
                #pragma unroll
                for (int nj = 0; nj < 2; nj++) {
                    mma_bf16(acc[mi][2 * nj],     al[mi], bb[nj][0], bb[nj][1]);
                    mma_bf16(acc[mi][2 * nj + 1], al[mi], bb[nj][2], bb[nj][3]);
                }
        }
    }

    const bool isQ = (mode == 0 && mat == 0);
    const float scl = isQ ? 0.125f : 1.f;
    #pragma unroll
    for (int mi = 0; mi < 4; mi++) {
        #pragma unroll
        for (int nq = 0; nq < 4; nq++) {
            int r0 = bm * 128 + wm + mi * 16 + (L >> 2);
            int r1 = r0 + 8;
            int n = bn * 128 + wn + nq * 8 + t2 * 2;
            float bx = bias[n], by = bias[n + 1];
            float4 c = acc[mi][nq];
            float cx = (c.x + bx) * scl, cy = (c.y + by) * scl;
            float cz = (c.z + bx) * scl, cw = (c.w + by) * scl;
            if (mode == 0) {
                int hh = n >> 6, d = n & 63;
                int b0 = r0 >> 12, s0 = r0 & (SEQ - 1);
                int b1 = r1 >> 12, s1 = r1 & (SEQ - 1);
                size_t i0 = (size_t)mat * QKV_ELEMS +
                            (((size_t)(b0 * NH + hh)) * SEQ + s0) * HD + d;
                size_t i1 = (size_t)mat * QKV_ELEMS +
                            (((size_t)(b1 * NH + hh)) * SEQ + s1) * HD + d;
                *(uint32_t*)&Oh[i0] = pack_f16(cx, cy);
                *(uint32_t*)&Oh[i1] = pack_f16(cz, cw);
                if (isQ) {
                    *(uint32_t*)&Ol[i0] = pack_bf16(f16_res(cx), f16_res(cy));
                    *(uint32_t*)&Ol[i1] = pack_bf16(f16_res(cz), f16_res(cw));
                } else {
                    *(uint32_t*)&Ol[i0] = pack_bf16(cx, cy);
                    *(uint32_t*)&Ol[i1] = pack_bf16(cz, cw);
                }
            } else {
                *(float2*)&Ofp[(size_t)r0 * 512 + n] = make_float2(cx, cy);
                *(float2*)&Ofp[(size_t)r1 * 512 + n] = make_float2(cz, cw);
            }
        }
    }
}

// ===========================================================================
// Attention: 2 CTAs/SM, cp.async K/V, Q-lo in smem.
// R15: PV uses fp16 term ONLY (P-residual term dropped; raw scores keep the
// full 2-term S). V bf16 buffer removed -> smem 64KB, fewer LDSM/MMA/ALU.
// ===========================================================================
#define BR 128
#define BC 64

// per-buffer (24KB): KH(fp16) 0, KB(bf16) 8K, VH(fp16) 16K
#define BUF_SZ 24576
#define BKH 0
#define BKB 8192
#define BVH 16384
#define SQL_OFF 49152          // 16KB QL region (128 rows x 128B pitch)
#define SM_ATTN 65536

__global__ __launch_bounds__(256, 2) void attn_mma(float* __restrict__ rawOut)
{
    extern __shared__ char smem[];
    const uint32_t sb = smem_u32(smem);
    const int tid = threadIdx.x, w = tid >> 5, L = tid & 31;
    const int t2 = L & 3;
    const int it = (int)(gridDim.x - 1 - blockIdx.x);   // heavy blocks first
    const int i0 = it * BR, h = blockIdx.y, b = blockIdx.z;

    const size_t headOff = (size_t)(b * NH + h) * SEQ * HD;
    const __half*        Qh = g_qkvh + headOff + (size_t)i0 * HD;
    const __nv_bfloat16* Ql = g_qkvl + headOff + (size_t)i0 * HD;
    const __half*        Kh = g_qkvh + QKV_ELEMS + headOff;
    const __nv_bfloat16* Kb = g_qkvl + QKV_ELEMS + headOff;
    const __half*        Vh = g_qkvh + 2 * QKV_ELEMS + headOff;

    // ---- stage Q: hi into buffer area (temp), lo into dedicated region ----
    for (int i = tid; i < 1024; i += 256) {
        int r = i >> 3, c = (i & 7) * 8;
        uint32_t off = swz(r, c);
        *(uint4*)(smem + off)           = *(const uint4*)&Qh[(size_t)r * HD + c];
        *(uint4*)(smem + SQL_OFF + off) = *(const uint4*)&Ql[(size_t)r * HD + c];
    }
    __syncthreads();
    uint32_t qfh[4][4];
    const int qr = w * 16 + (L & 7) + 8 * ((L >> 3) & 1);
    const int qcb = 8 * ((L >> 4) & 1);
    #pragma unroll
    for (int kt = 0; kt < 4; kt++) {
        LDSM4(qfh[kt][0], qfh[kt][1], qfh[kt][2], qfh[kt][3],
              sb + swz(qr, kt * 16 + qcb));
    }
    __syncthreads();   // qfh captured; buffer area free

    const int i_row0 = i0 + w * 16 + (L >> 2);
    const int i_row1 = i_row0 + 8;
    const int iwmax = i0 + w * 16 + 15;
    const size_t raw0 = ((size_t)(h * BATCH + b) * SEQ + i_row0) * SEQ;
    const size_t raw1 = raw0 + 8ull * SEQ;
    const int lastCausal = 2 * it + 1;

    float4 O[8];
    #pragma unroll
    for (int nt = 0; nt < 8; nt++) O[nt] = make_float4(0.f, 0.f, 0.f, 0.f);
    float m0 = -INFINITY, m1 = -INFINITY, l0 = 0.f, l1 = 0.f;

    const int pr = tid >> 3, pc = (tid & 7) * 8;

    // cp.async prefetch of one j-tile into buffer bo
    auto prefetch = [&](int jt, uint32_t bo) {
        const size_t tOff = (size_t)jt * BC * HD;
        const bool causal = (jt <= lastCausal);
        #pragma unroll
        for (int q = 0; q < 2; q++) {
            int r = pr + q * 32;
            uint32_t off = bo + swz(r, pc);
            CP_ASYNC16(sb + BKH + off, &Kh[tOff + (size_t)r * HD + pc]);
            CP_ASYNC16(sb + BKB + off, &Kb[tOff + (size_t)r * HD + pc]);
            if (causal) {
                CP_ASYNC16(sb + BVH + off, &Vh[tOff + (size_t)r * HD + pc]);
            }
        }
        CP_COMMIT();
    };

    prefetch(0, 0);

    for (int jt = 0; jt < 64; jt++) {
        const uint32_t bo = (uint32_t)(jt & 1) * BUF_SZ;
        CP_WAIT0();
        __syncthreads();
        if (jt < 63) prefetch(jt + 1, (uint32_t)((jt + 1) & 1) * BUF_SZ);

        // ---- S = Q @ K^T (2-term, term-outside) ----
        float4 acc[8];
        #pragma unroll
        for (int nt = 0; nt < 8; nt++) acc[nt] = make_float4(0.f, 0.f, 0.f, 0.f);

        const int krr = (L & 7) + 8 * ((L >> 4) & 1);
        #pragma unroll
        for (int kt = 0; kt < 4; kt++) {
            const int kcc = kt * 16 + 8 * ((L >> 3) & 1);
            // fp16 term
            #pragma unroll
            for (int p = 0; p < 4; p++) {
                uint32_t f0, f1, f2, f3;
                LDSM4(f0, f1, f2, f3, sb + bo + BKH + swz(16 * p + krr, kcc));
                mma_f16(acc[2 * p],     qfh[kt], f0, f1);
                mma_f16(acc[2 * p + 1], qfh[kt], f2, f3);
            }
            // bf16 residual term (Q-lo fragment from smem)
            uint32_t ql[4];
            LDSM4(ql[0], ql[1], ql[2], ql[3],
                  sb + SQL_OFF + swz(qr, kt * 16 + qcb));
            #pragma unroll
            for (int p = 0; p < 4; p++) {
                uint32_t f0, f1, f2, f3;
                LDSM4(f0, f1, f2, f3, sb + bo + BKB + swz(16 * p + krr, kcc));
                mma_bf16(acc[2 * p],     ql, f0, f1);
                mma_bf16(acc[2 * p + 1], ql, f2, f3);
            }
        }

        // ---- raw scores (pre-mask), direct stores ----
        #pragma unroll
        for (int nt = 0; nt < 8; nt++) {
            int j = jt * 64 + nt * 8 + t2 * 2;
            *(float2*)&rawOut[raw0 + j] = make_float2(acc[nt].x, acc[nt].y);
            *(float2*)&rawOut[raw1 + j] = make_float2(acc[nt].z, acc[nt].w);
        }

        // ---- softmax + PV (warp-uniform) ----
        if (jt * 64 <= iwmax) {
            const bool full = (jt * 64 + 63 <= i0 + w * 16);
            float mt0 = -INFINITY, mt1 = -INFINITY;
            #pragma unroll
            for (int nt = 0; nt < 8; nt++) {
                int j = jt * 64 + nt * 8 + t2 * 2;
                float ax = (full || j     <= i_row0) ? acc[nt].x : -INFINITY;
                float ay = (full || j + 1 <= i_row0) ? acc[nt].y : -INFINITY;
                float az = (full || j     <= i_row1) ? acc[nt].z : -INFINITY;
                float aw = (full || j + 1 <= i_row1) ? acc[nt].w : -INFINITY;
                mt0 = fmaxf(mt0, fmaxf(ax, ay));
                mt1 = fmaxf(mt1, fmaxf(az, aw));
            }
            mt0 = fmaxf(mt0, __shfl_xor_sync(0xffffffffu, mt0, 1));
            mt0 = fmaxf(mt0, __shfl_xor_sync(0xffffffffu, mt0, 2));
            mt1 = fmaxf(mt1, __shfl_xor_sync(0xffffffffu, mt1, 1));
            mt1 = fmaxf(mt1, __shfl_xor_sync(0xffffffffu, mt1, 2));

            float mn0 = fmaxf(m0, mt0), mn1 = fmaxf(m1, mt1);
            float sc0 = __expf(m0 - mn0), sc1 = __expf(m1 - mn1);

            float s0 = 0.f, s1 = 0.f;
            uint32_t ph[16];
            #pragma unroll
            for (int nt = 0; nt < 8; nt++) {
                int j = jt * 64 + nt * 8 + t2 * 2;
                float px = (full || j     <= i_row0) ? __expf(acc[nt].x - mn0) : 0.f;
                float py = (full || j + 1 <= i_row0) ? __expf(acc[nt].y - mn0) : 0.f;
                float pz = (full || j     <= i_row1) ? __expf(acc[nt].z - mn1) : 0.f;
                float pw = (full || j + 1 <= i_row1) ? __expf(acc[nt].w - mn1) : 0.f;
                s0 += px + py; s1 += pz + pw;
                ph[2 * nt]     = pack_f16(px, py);
                ph[2 * nt + 1] = pack_f16(pz, pw);
            }
            s0 += __shfl_xor_sync(0xffffffffu, s0, 1);
            s0 += __shfl_xor_sync(0xffffffffu, s0, 2);
            s1 += __shfl_xor_sync(0xffffffffu, s1, 1);
            s1 += __shfl_xor_sync(0xffffffffu, s1, 2);
            l0 = l0 * sc0 + s0;  l1 = l1 * sc1 + s1;
            m0 = mn0;  m1 = mn1;

            #pragma unroll
            for (int nt = 0; nt < 8; nt++) {
                O[nt].x *= sc0; O[nt].y *= sc0;
                O[nt].z *= sc1; O[nt].w *= sc1;
            }

            // O += P @ V (fp16 term only)
            const int vrr = (L & 7) + 8 * ((L >> 3) & 1);
            const int vcb = 8 * ((L >> 4) & 1);
            #pragma unroll
            for (int ktj = 0; ktj < 4; ktj++) {
                const uint32_t* ahh = &ph[4 * ktj];
                #pragma unroll
                for (int vp = 0; vp < 4; vp++) {
                    uint32_t f0, f1, f2, f3;
                    LDSM4T(f0, f1, f2, f3,
                           sb + bo + BVH + swz(ktj * 16 + vrr, vp * 16 + vcb));
                    mma_f16(O[2 * vp],     ahh, f0, f1);
                    mma_f16(O[2 * vp + 1], ahh, f2, f3);
                }
            }
        }
        __syncthreads();   // all reads of this buffer done before next overwrite
    }

    // ---- epilogue: normalize, split-store ----
    const float inv0 = 1.f / l0, inv1 = 1.f / l1;
    __half* aoh0 = g_ah + ((size_t)(b * SEQ + i_row0) * DMODEL + h * HD);
    __nv_bfloat16* aol0 = g_al + ((size_t)(b * SEQ + i_row0) * DMODEL + h * HD);
    __half* aoh1 = g_ah + ((size_t)(b * SEQ + i_row1) * DMODEL + h * HD);
    __nv_bfloat16* aol1 = g_al + ((size_t)(b * SEQ + i_row1) * DMODEL + h * HD);
    #pragma unroll
    for (int nt = 0; nt < 8; nt++) {
        int v = nt * 8 + t2 * 2;
        float x0 = O[nt].x * inv0, y0 = O[nt].y * inv0;
        float x1 = O[nt].z * inv1, y1 = O[nt].w * inv1;
        *(uint32_t*)&aoh0[v] = pack_f16(x0, y0);
        *(uint32_t*)&aol0[v] = pack_bf16(f16_res(x0), f16_res(y0));
        *(uint32_t*)&aoh1[v] = pack_f16(x1, y1);
        *(uint32_t*)&aol1[v] = pack_bf16(f16_res(x1), f16_res(y1));
    }
}

// ===========================================================================
// Launch
// ===========================================================================
extern "C" void kernel_launch(void* const* d_in, const int* in_sizes, int n_in,
                              void* d_out, int out_size)
{
    (void)in_sizes; (void)n_in; (void)out_size;
    const float* x  = (const float*)d_in[0];
    const float* Wq = (const float*)d_in[1];
    const float* bq = (const float*)d_in[2];
    const float* Wk = (const float*)d_in[3];
    const float* bk = (const float*)d_in[4];
    const float* Wv = (const float*)d_in[5];
    const float* bv = (const float*)d_in[6];
    const float* Wo = (const float*)d_in[7];
    const float* bo = (const float*)d_in[8];

    float* out = (float*)d_out;
    float* rawOut = out + (size_t)BATCH * SEQ * DMODEL;

    void *qkvh, *qkvl, *xh, *xl, *wh, *wl, *ah, *al;
    cudaGetSymbolAddress(&qkvh, g_qkvh);
    cudaGetSymbolAddress(&qkvl, g_qkvl);
    cudaGetSymbolAddress(&xh, g_xh);
    cudaGetSymbolAddress(&xl, g_xl);
    cudaGetSymbolAddress(&wh, g_wh);
    cudaGetSymbolAddress(&wl, g_wl);
    cudaGetSymbolAddress(&ah, g_ah);
    cudaGetSymbolAddress(&al, g_al);

    __half* whp = (__half*)wh;
    __nv_bfloat16* wlp = (__nv_bfloat16*)wl;

    // splits: x -> fp16 + bf16 residual; W (all 4, fused) -> fp16 + bf16 full
    int n4x = QKV_ELEMS / 4;
    split_kernel<<<n4x / 256, 256>>>(x, (__half*)xh, (__nv_bfloat16*)xl, n4x, 0);
    int n4w = WELEMS / 4;
    split_w_kernel<<<dim3(n4w / 256, 4), 256>>>(Wq, Wk, Wv, Wo, whp, wlp, n4w);

    cudaFuncSetAttribute(gemm_mix, cudaFuncAttributeMaxDynamicSharedMemorySize, GSM);
    cudaFuncSetAttribute(attn_mma, cudaFuncAttributeMaxDynamicSharedMemorySize, SM_ATTN);

    // QKV projections (fused over grid.z)
    gemm_mix<<<dim3(M_ROWS / 128, 4, 3), 256, GSM>>>(
        (const __half*)xh, (const __nv_bfloat16*)xl, whp, wlp,
        bq, bk, bv,
        (__half*)qkvh, (__nv_bfloat16*)qkvl, nullptr, 0);

    // attention (raw scores + softmax + PV)
    attn_mma<<<dim3(SEQ / BR, NH, BATCH), 256, SM_ATTN>>>(rawOut);

    // output projection
    gemm_mix<<<dim3(M_ROWS / 128, 4, 1), 256, GSM>>>(
        (const __half*)ah, (const __nv_bfloat16*)al,
        whp + 3 * WELEMS, wlp + 3 * WELEMS,
        bo, bo, bo, nullptr, nullptr, out, 1);
}